// round 6
// baseline (speedup 1.0000x reference)
#include <cuda_runtime.h>
#include <cuda_fp16.h>
#include <math.h>

#define Bn   2
#define Cn   128
#define Hs   56
#define Nn   3136
#define NHn  4
#define HFn  341
#define TOK  (Bn*Nn)

__device__ __align__(256) float g_y   [TOK*Cn];
__device__ __align__(256) float g_tmp1[TOK*512];
__device__ __align__(256) float g_qs  [TOK*Cn];
__device__ __align__(256) float g_qn  [TOK*Cn];
__device__ __align__(256) float g_kl  [TOK*Cn];
__device__ __align__(256) float g_vl  [TOK*Cn];
__device__ __align__(256) float g_xp  [TOK*Cn];
__device__ __align__(256) float g_kvp [TOK*256];
__device__ __align__(256) float g_kp  [TOK*Cn];
__device__ __align__(256) float g_vp  [TOK*Cn];
__device__ __align__(256) float g_U   [TOK*Cn];
__device__ __align__(256) float g_Zp  [8*Nn];
__device__ __align__(256) float g_att [TOK*Cn];
__device__ __align__(256) float g_x2  [TOK*Cn];
__device__ __align__(256) float g_y2  [TOK*Cn];
__device__ __align__(256) float g_f1  [TOK*682];
__device__ __align__(256) float g_gb  [TOK*HFn];

__device__ __forceinline__ float gelu_exact(float x) {
    return 0.5f * x * (1.0f + erff(x * 0.70710678118654752f));
}

__device__ __forceinline__ unsigned h2pack(float a, float b) {
    __half2 h = __floats2half2_rn(a, b);
    return *(unsigned*)&h;
}

__device__ __forceinline__ void mma16816(float* c, const unsigned* a, unsigned b0, unsigned b1) {
    asm volatile("mma.sync.aligned.m16n8k16.row.col.f32.f16.f16.f32 "
        "{%0,%1,%2,%3}, {%4,%5,%6,%7}, {%8,%9}, {%0,%1,%2,%3};"
        : "+f"(c[0]), "+f"(c[1]), "+f"(c[2]), "+f"(c[3])
        : "r"(a[0]), "r"(a[1]), "r"(a[2]), "r"(a[3]), "r"(b0), "r"(b1));
}

// ---------- LayerNorm: warp per token, channel-major input (stride Nn) ----------
__global__ void ln_kernel(const float* __restrict__ in, const float* __restrict__ w,
                          const float* __restrict__ bvec, float* __restrict__ out)
{
    int warp = blockIdx.x * 8 + (threadIdx.x >> 5);
    int lane = threadIdx.x & 31;
    int bb = warp / Nn, n = warp - bb * Nn;
    const float* p = in + (size_t)bb * (Cn*Nn) + n;
    float v[4], s = 0.f, s2 = 0.f;
#pragma unroll
    for (int k = 0; k < 4; k++) {
        int c = lane + 32*k;
        v[k] = p[(size_t)c * Nn];
        s += v[k]; s2 += v[k]*v[k];
    }
#pragma unroll
    for (int d = 1; d < 32; d <<= 1) {
        s  += __shfl_xor_sync(0xffffffffu, s,  d);
        s2 += __shfl_xor_sync(0xffffffffu, s2, d);
    }
    float mu = s * (1.0f/128.0f);
    float rstd = rsqrtf(s2*(1.0f/128.0f) - mu*mu + 1e-5f);
    float* o = out + (size_t)warp * 128;
#pragma unroll
    for (int k = 0; k < 4; k++) {
        int c = lane + 32*k;
        o[c] = (v[k]-mu)*rstd*w[c] + bvec[c];
    }
}

// ---------- HMMA GEMM: out[M,Nout] = A[M,Kd] @ W[Nout,Kd]^T + bias ----------
// BM=128 (8 warps x 16 rows), BN=64, K chunks of 32, fp16 hi/lo split both operands.
__global__ void __launch_bounds__(256) hgemm_kernel(
    const float* __restrict__ A, const float* __restrict__ W,
    const float* __restrict__ bias, float* __restrict__ out,
    int ldo, int Nout, int Kd, int mode, const float* __restrict__ res)
{
    __shared__ __half Ah[128][34];
    __shared__ __half Al[128][34];
    __shared__ __half Wh[64][34];
    __shared__ __half Wl[64][34];

    const int m0 = blockIdx.y * 128;
    const int n0 = blockIdx.x * 64;
    const int tid = threadIdx.x;
    const int warp = tid >> 5;
    const int lane = tid & 31;
    const int r  = lane >> 2;
    const int c2 = (lane & 3) * 2;

    float acc[8][4];
#pragma unroll
    for (int t = 0; t < 8; t++)
#pragma unroll
        for (int i = 0; i < 4; i++) acc[t][i] = 0.f;

    const int KC = (Kd + 31) / 32;
    for (int kc = 0; kc < KC; kc++) {
        const int k0 = kc * 32;
        // stage A chunk (128x32) hi/lo
        for (int i = tid; i < 4096; i += 256) {
            int m = i >> 5, k = i & 31;
            int kg = k0 + k;
            float v = (kg < Kd) ? A[(size_t)(m0 + m)*Kd + kg] : 0.f;
            __half hv = __float2half_rn(v);
            Ah[m][k] = hv;
            Al[m][k] = __float2half_rn(v - __half2float(hv));
        }
        // stage W chunk (64x32) hi/lo
        for (int i = tid; i < 2048; i += 256) {
            int n = i >> 5, k = i & 31;
            int kg = k0 + k;
            float v = ((n0 + n) < Nout && kg < Kd) ? W[(size_t)(n0 + n)*Kd + kg] : 0.f;
            __half hv = __float2half_rn(v);
            Wh[n][k] = hv;
            Wl[n][k] = __float2half_rn(v - __half2float(hv));
        }
        __syncthreads();

#pragma unroll
        for (int ks = 0; ks < 2; ks++) {
            int d0 = ks*16 + c2;
            int row = warp*16 + r;
            unsigned ah[4], al[4];
            ah[0] = *(const unsigned*)&Ah[row][d0];
            ah[1] = *(const unsigned*)&Ah[row+8][d0];
            ah[2] = *(const unsigned*)&Ah[row][d0+8];
            ah[3] = *(const unsigned*)&Ah[row+8][d0+8];
            al[0] = *(const unsigned*)&Al[row][d0];
            al[1] = *(const unsigned*)&Al[row+8][d0];
            al[2] = *(const unsigned*)&Al[row][d0+8];
            al[3] = *(const unsigned*)&Al[row+8][d0+8];
#pragma unroll
            for (int nt = 0; nt < 8; nt++) {
                int n = nt*8 + (lane >> 2);
                unsigned bh0 = *(const unsigned*)&Wh[n][d0];
                unsigned bh1 = *(const unsigned*)&Wh[n][d0+8];
                unsigned bl0 = *(const unsigned*)&Wl[n][d0];
                unsigned bl1 = *(const unsigned*)&Wl[n][d0+8];
                mma16816(acc[nt], ah, bh0, bh1);
                mma16816(acc[nt], al, bh0, bh1);
                mma16816(acc[nt], ah, bl0, bl1);
            }
        }
        __syncthreads();
    }

    // epilogue
    int m1 = m0 + warp*16 + r;
    int m2 = m1 + 8;
#pragma unroll
    for (int nt = 0; nt < 8; nt++) {
        int n = n0 + nt*8 + c2;
#pragma unroll
        for (int j = 0; j < 2; j++) {
            int nn = n + j;
            if (nn >= Nout) continue;
            float v1 = acc[nt][j]   + bias[nn];
            float v2 = acc[nt][2+j] + bias[nn];
            if (mode == 0) {
                out[(size_t)m1*ldo + nn] = v1;
                out[(size_t)m2*ldo + nn] = v2;
            } else if (mode == 1) {
                size_t i1 = (size_t)m1*ldo + nn, i2 = (size_t)m2*ldo + nn;
                out[i1] = v1 + res[i1];
                out[i2] = v2 + res[i2];
            } else {
                int b1 = m1 / Nn, t1i = m1 - b1*Nn;
                int b2 = m2 / Nn, t2i = m2 - b2*Nn;
                size_t i1 = ((size_t)b1*Cn + nn)*Nn + t1i;
                size_t i2 = ((size_t)b2*Cn + nn)*Nn + t2i;
                out[i1] = v1 + res[i1];
                out[i2] = v2 + res[i2];
            }
        }
    }
}

// ---------- pointwise after GEMM1 ----------
__global__ void pointwise1(const float* __restrict__ tmp1, const float* __restrict__ temp,
                           const float* __restrict__ qe, const float* __restrict__ plnw,
                           const float* __restrict__ plnb,
                           float* __restrict__ qs, float* __restrict__ qn,
                           float* __restrict__ kl, float* __restrict__ vl,
                           float* __restrict__ xp)
{
    int t = blockIdx.x * 8 + (threadIdx.x >> 5);
    int lane = threadIdx.x & 31;
    int bb = t / Nn, n = t - bb * Nn;
    int h = lane >> 3;
    int g = bb * NHn + h;
    const float4* row = (const float4*)(tmp1 + (size_t)t * 512);
    size_t ho = ((size_t)g * Nn + n) * 8 + (lane & 7);

    float4 q4 = row[lane];
    float ss = q4.x*q4.x + q4.y*q4.y + q4.z*q4.z + q4.w*q4.w;
    ss += __shfl_xor_sync(0xffffffffu, ss, 1);
    ss += __shfl_xor_sync(0xffffffffu, ss, 2);
    ss += __shfl_xor_sync(0xffffffffu, ss, 4);
    float inv = 1.0f / fmaxf(sqrtf(ss), 1e-12f);
    float4 qn4 = make_float4(q4.x*inv, q4.y*inv, q4.z*inv, q4.w*inv);
    float tv = temp[h];
    float sp = log1pf(__expf(tv));
    float4 qe4 = ((const float4*)qe)[h*8 + (lane & 7)];
    ((float4*)qn)[ho] = qn4;
    ((float4*)qs)[ho] = make_float4((qn4.x+qe4.x)*sp, (qn4.y+qe4.y)*sp,
                                    (qn4.z+qe4.z)*sp, (qn4.w+qe4.w)*sp);

    float4 k4 = row[32 + lane];
    float ks = k4.x*k4.x + k4.y*k4.y + k4.z*k4.z + k4.w*k4.w;
    ks += __shfl_xor_sync(0xffffffffu, ks, 1);
    ks += __shfl_xor_sync(0xffffffffu, ks, 2);
    ks += __shfl_xor_sync(0xffffffffu, ks, 4);
    float ki = 1.0f / fmaxf(sqrtf(ks), 1e-12f);
    ((float4*)kl)[ho] = make_float4(k4.x*ki, k4.y*ki, k4.z*ki, k4.w*ki);
    ((float4*)vl)[ho] = row[64 + lane];

    float4 s4 = row[96 + lane];
    float g0 = gelu_exact(s4.x), g1 = gelu_exact(s4.y);
    float g2 = gelu_exact(s4.z), g3 = gelu_exact(s4.w);
    float sm = g0+g1+g2+g3;
    float sq = g0*g0+g1*g1+g2*g2+g3*g3;
#pragma unroll
    for (int d = 1; d < 32; d <<= 1) {
        sm += __shfl_xor_sync(0xffffffffu, sm, d);
        sq += __shfl_xor_sync(0xffffffffu, sq, d);
    }
    float mu = sm*(1.0f/128.0f);
    float rstd = rsqrtf(sq*(1.0f/128.0f) - mu*mu + 1e-5f);
    int c = lane * 4;
    float4 o;
    o.x = (g0-mu)*rstd*plnw[c]   + plnb[c];
    o.y = (g1-mu)*rstd*plnw[c+1] + plnb[c+1];
    o.z = (g2-mu)*rstd*plnw[c+2] + plnb[c+2];
    o.w = (g3-mu)*rstd*plnw[c+3] + plnb[c+3];
    ((float4*)xp)[(size_t)t*32 + lane] = o;
}

// ---------- split kvp -> normalized kp / raw vp (head-major) ----------
__global__ void pointwise2(const float* __restrict__ kvp, float* __restrict__ kp,
                           float* __restrict__ vp)
{
    int t = blockIdx.x * 8 + (threadIdx.x >> 5);
    int lane = threadIdx.x & 31;
    int bb = t / Nn, n = t - bb * Nn;
    int h = lane >> 3;
    int g = bb * NHn + h;
    const float4* row = (const float4*)(kvp + (size_t)t * 256);
    size_t ho = ((size_t)g * Nn + n) * 8 + (lane & 7);

    float4 k4 = row[lane];
    float ks = k4.x*k4.x + k4.y*k4.y + k4.z*k4.z + k4.w*k4.w;
    ks += __shfl_xor_sync(0xffffffffu, ks, 1);
    ks += __shfl_xor_sync(0xffffffffu, ks, 2);
    ks += __shfl_xor_sync(0xffffffffu, ks, 4);
    float ki = 1.0f / fmaxf(sqrtf(ks), 1e-12f);
    ((float4*)kp)[ho] = make_float4(k4.x*ki, k4.y*ki, k4.z*ki, k4.w*ki);
    ((float4*)vp)[ho] = row[32 + lane];
}

// ---------- HMMA streaming pooled attention ----------
__global__ void __launch_bounds__(128) attn_pool_mma(
    const float* __restrict__ qs, const float* __restrict__ kp,
    const float* __restrict__ vp, float* __restrict__ U, float* __restrict__ Zp)
{
    __shared__ __half Khi[128][36];
    __shared__ __half Klo[128][36];
    __shared__ __half Vt[32][132];

    const int g  = blockIdx.y;
    const int q0 = blockIdx.x * 64;
    const int tid = threadIdx.x;
    const int warp = tid >> 5;
    const int lane = tid & 31;
    const int r  = lane >> 2;
    const int c2 = (lane & 3) * 2;

    unsigned qhi[2][4], qlo[2][4];
    {
        const float* q0p = qs + ((size_t)g*Nn + q0 + warp*16 + r)*32;
        const float* q8p = q0p + 8*32;
#pragma unroll
        for (int ks = 0; ks < 2; ks++) {
            int d0 = ks*16 + c2;
            float x[4][2];
            x[0][0] = q0p[d0];   x[0][1] = q0p[d0+1];
            x[1][0] = q8p[d0];   x[1][1] = q8p[d0+1];
            x[2][0] = q0p[d0+8]; x[2][1] = q0p[d0+9];
            x[3][0] = q8p[d0+8]; x[3][1] = q8p[d0+9];
#pragma unroll
            for (int i = 0; i < 4; i++) {
                float a = x[i][0], b = x[i][1];
                float ah = __half2float(__float2half_rn(a));
                float bh = __half2float(__float2half_rn(b));
                qhi[ks][i] = h2pack(ah, bh);
                qlo[ks][i] = h2pack(a - ah, b - bh);
            }
        }
    }

    float uf[4][4];
#pragma unroll
    for (int t = 0; t < 4; t++)
#pragma unroll
        for (int i = 0; i < 4; i++) uf[t][i] = 0.f;
    float z0 = 0.f, z1 = 0.f;

    const int NCH = 25;
    for (int ch = 0; ch < NCH; ch++) {
        const int m0 = ch * 128;
        {
            int kvr = m0 + tid;
            bool ok = kvr < Nn;
            const float4* kr = (const float4*)(kp + ((size_t)g*Nn + (ok ? kvr : 0))*32);
            const float4* vr = (const float4*)(vp + ((size_t)g*Nn + (ok ? kvr : 0))*32);
#pragma unroll
            for (int j = 0; j < 8; j++) {
                float4 f = ok ? kr[j] : make_float4(0.f,0.f,0.f,0.f);
                float e[4] = {f.x, f.y, f.z, f.w};
#pragma unroll
                for (int u = 0; u < 4; u++) {
                    float hv = __half2float(__float2half_rn(e[u]));
                    Khi[tid][j*4+u] = __float2half_rn(e[u]);
                    Klo[tid][j*4+u] = __float2half_rn(e[u] - hv);
                }
                float4 v = ok ? vr[j] : make_float4(0.f,0.f,0.f,0.f);
                Vt[j*4+0][tid] = __float2half_rn(v.x);
                Vt[j*4+1][tid] = __float2half_rn(v.y);
                Vt[j*4+2][tid] = __float2half_rn(v.z);
                Vt[j*4+3][tid] = __float2half_rn(v.w);
            }
        }
        __syncthreads();

        float sf[16][4];
#pragma unroll
        for (int t = 0; t < 16; t++)
#pragma unroll
            for (int i = 0; i < 4; i++) sf[t][i] = 0.f;

#pragma unroll
        for (int ks = 0; ks < 2; ks++) {
            int d0 = ks*16 + c2;
#pragma unroll
            for (int t = 0; t < 16; t++) {
                int kv = t*8 + (lane >> 2);
                unsigned bh0 = *(const unsigned*)&Khi[kv][d0];
                unsigned bh1 = *(const unsigned*)&Khi[kv][d0+8];
                unsigned bl0 = *(const unsigned*)&Klo[kv][d0];
                unsigned bl1 = *(const unsigned*)&Klo[kv][d0+8];
                mma16816(sf[t], qhi[ks], bh0, bh1);
                mma16816(sf[t], qhi[ks], bl0, bl1);
                mma16816(sf[t], qlo[ks], bh0, bh1);
            }
        }

        const int tlim = (m0 + 128 <= Nn) ? 16 : 8;
        unsigned ep[32];
#pragma unroll
        for (int t = 0; t < 16; t++) {
            if (t < tlim) {
                float e0 = __expf(sf[t][0]);
                float e1 = __expf(sf[t][1]);
                float e2 = __expf(sf[t][2]);
                float e3 = __expf(sf[t][3]);
                z0 += e0 + e1;
                z1 += e2 + e3;
                ep[2*t]   = h2pack(e0, e1);
                ep[2*t+1] = h2pack(e2, e3);
            } else {
                ep[2*t] = 0u; ep[2*t+1] = 0u;
            }
        }

        const int kkmax = (tlim == 16) ? 8 : 4;
        for (int kk = 0; kk < kkmax; kk++) {
            int kv0 = kk*16 + c2;
#pragma unroll
            for (int nt = 0; nt < 4; nt++) {
                int d = nt*8 + (lane >> 2);
                unsigned b0 = *(const unsigned*)&Vt[d][kv0];
                unsigned b1 = *(const unsigned*)&Vt[d][kv0+8];
                mma16816(uf[nt], &ep[4*kk], b0, b1);
            }
        }
        __syncthreads();
    }

    {
        int qrow = q0 + warp*16 + r;
        float* u0 = U + ((size_t)g*Nn + qrow)*32;
        float* u8 = u0 + 8*32;
#pragma unroll
        for (int nt = 0; nt < 4; nt++) {
            int d = nt*8 + c2;
            u0[d]   = uf[nt][0];
            u0[d+1] = uf[nt][1];
            u8[d]   = uf[nt][2];
            u8[d+1] = uf[nt][3];
        }
        z0 += __shfl_xor_sync(0xffffffffu, z0, 1);
        z0 += __shfl_xor_sync(0xffffffffu, z0, 2);
        z1 += __shfl_xor_sync(0xffffffffu, z1, 1);
        z1 += __shfl_xor_sync(0xffffffffu, z1, 2);
        if ((lane & 3) == 0) {
            Zp[(size_t)g*Nn + qrow]     = z0;
            Zp[(size_t)g*Nn + qrow + 8] = z1;
        }
    }
}

// ---------- finalize ----------
__global__ void attn_finalize(
    const float* __restrict__ qs, const float* __restrict__ qn,
    const float* __restrict__ kl, const float* __restrict__ vl,
    const float* __restrict__ U, const float* __restrict__ Zp,
    const float* __restrict__ lt, const float* __restrict__ lb,
    float* __restrict__ xo)
{
    int warp = blockIdx.x * 8 + (threadIdx.x >> 5);
    int lane = threadIdx.x & 31;
    int g = warp / Nn, n = warp - g*Nn;
    int b = g >> 2, h = g & 3;
    int hh = n / Hs, ww = n - hh*Hs;
    size_t qi = ((size_t)g*Nn + n)*32 + lane;
    float q = qs[qi];
    float qv = qn[qi];
    float z = 0.f, res = 0.f, res2 = 0.f;
#pragma unroll
    for (int k = 0; k < 9; k++) {
        int h2 = hh + k/3 - 1, w2 = ww + (k%3) - 1;
        bool ok = (h2 >= 0 && h2 < Hs && w2 >= 0 && w2 < Hs);
        int nb = h2*Hs + w2;
        float kv = 0.f, vv = 0.f;
        if (ok) {
            size_t bi = ((size_t)g*Nn + nb)*32 + lane;
            kv = kl[bi]; vv = vl[bi];
        }
        float lg = q * kv;
        float wl = qv * lt[(h*32 + lane)*9 + k];
#pragma unroll
        for (int d = 16; d >= 1; d >>= 1) {
            lg += __shfl_xor_sync(0xffffffffu, lg, d);
            wl += __shfl_xor_sync(0xffffffffu, wl, d);
        }
        float e = __expf(lg);
        z += e;
        res  += e * vv;
        res2 += (wl + lb[h*9 + k]) * vv;
    }
    float Z = Zp[(size_t)g*Nn + n] + z;
    float o = (U[qi] + res) / Z + res2;
    xo[((size_t)(b*Nn + n))*128 + h*32 + lane] = o;
}

// ---------- depthwise 3x3 + gelu * v ----------
__global__ void dwconv_kernel(const float* __restrict__ f1, const float* __restrict__ dww,
                              const float* __restrict__ dwb, float* __restrict__ gout)
{
    int t = blockIdx.x;
    int c = threadIdx.x;
    if (c >= HFn) return;
    int b = t / Nn, n = t - b*Nn;
    int hh = n / Hs, ww = n - hh*Hs;
    float acc = dwb[c];
#pragma unroll
    for (int k = 0; k < 9; k++) {
        int h2 = hh + k/3 - 1, w2 = ww + (k%3) - 1;
        if (h2 < 0 || h2 >= Hs || w2 < 0 || w2 >= Hs) continue;
        acc += f1[((size_t)(b*Nn + h2*Hs + w2))*682 + c] * dww[c*9 + k];
    }
    float v = f1[(size_t)t*682 + 341 + c];
    gout[(size_t)t*HFn + c] = gelu_exact(acc) * v;
}

extern "C" void kernel_launch(void* const* d_in, const int* in_sizes, int n_in,
                              void* d_out, int out_size)
{
    const float* x      = (const float*)d_in[0];
    const float* n1w    = (const float*)d_in[1];
    const float* n1b    = (const float*)d_in[2];
    const float* q_w    = (const float*)d_in[3];
    const float* q_b    = (const float*)d_in[4];
    const float* kv_w   = (const float*)d_in[5];
    const float* kv_b   = (const float*)d_in[6];
    const float* temp   = (const float*)d_in[7];
    const float* qe     = (const float*)d_in[8];
    const float* lt     = (const float*)d_in[9];
    const float* lb     = (const float*)d_in[10];
    const float* sr_w   = (const float*)d_in[11];
    const float* sr_b   = (const float*)d_in[12];
    const float* plnw   = (const float*)d_in[13];
    const float* plnb   = (const float*)d_in[14];
    const float* proj_w = (const float*)d_in[15];
    const float* proj_b = (const float*)d_in[16];
    const float* n2w    = (const float*)d_in[17];
    const float* n2b    = (const float*)d_in[18];
    const float* fc1_w  = (const float*)d_in[19];
    const float* fc1_b  = (const float*)d_in[20];
    const float* dw_w   = (const float*)d_in[21];
    const float* dw_b   = (const float*)d_in[22];
    const float* fc2_w  = (const float*)d_in[23];
    const float* fc2_b  = (const float*)d_in[24];
    float* out = (float*)d_out;

    float *yb, *t1, *qsb, *qnb, *klb, *vlb, *xpb, *kvpb, *kpb, *vpb;
    float *Ub, *Zpb, *attb, *x2b, *y2b, *f1b, *gbb;
    cudaGetSymbolAddress((void**)&yb,   g_y);
    cudaGetSymbolAddress((void**)&t1,   g_tmp1);
    cudaGetSymbolAddress((void**)&qsb,  g_qs);
    cudaGetSymbolAddress((void**)&qnb,  g_qn);
    cudaGetSymbolAddress((void**)&klb,  g_kl);
    cudaGetSymbolAddress((void**)&vlb,  g_vl);
    cudaGetSymbolAddress((void**)&xpb,  g_xp);
    cudaGetSymbolAddress((void**)&kvpb, g_kvp);
    cudaGetSymbolAddress((void**)&kpb,  g_kp);
    cudaGetSymbolAddress((void**)&vpb,  g_vp);
    cudaGetSymbolAddress((void**)&Ub,   g_U);
    cudaGetSymbolAddress((void**)&Zpb,  g_Zp);
    cudaGetSymbolAddress((void**)&attb, g_att);
    cudaGetSymbolAddress((void**)&x2b,  g_x2);
    cudaGetSymbolAddress((void**)&y2b,  g_y2);
    cudaGetSymbolAddress((void**)&f1b,  g_f1);
    cudaGetSymbolAddress((void**)&gbb,  g_gb);

    ln_kernel<<<TOK/8, 256>>>(x, n1w, n1b, yb);
    hgemm_kernel<<<dim3(2,49), 256>>>(yb, q_w,  q_b,  t1,       512, 128, 128, 0, nullptr);
    hgemm_kernel<<<dim3(4,49), 256>>>(yb, kv_w, kv_b, t1 + 128, 512, 256, 128, 0, nullptr);
    hgemm_kernel<<<dim3(2,49), 256>>>(yb, sr_w, sr_b, t1 + 384, 512, 128, 128, 0, nullptr);
    pointwise1<<<TOK/8, 256>>>(t1, temp, qe, plnw, plnb, qsb, qnb, klb, vlb, xpb);
    hgemm_kernel<<<dim3(4,49), 256>>>(xpb, kv_w, kv_b, kvpb, 256, 256, 128, 0, nullptr);
    pointwise2<<<TOK/8, 256>>>(kvpb, kpb, vpb);
    attn_pool_mma<<<dim3(49,8), 128>>>(qsb, kpb, vpb, Ub, Zpb);
    attn_finalize<<<Nn, 256>>>(qsb, qnb, klb, vlb, Ub, Zpb, lt, lb, attb);
    hgemm_kernel<<<dim3(2,49), 256>>>(attb, proj_w, proj_b, x2b, 128, 128, 128, 1, x);
    ln_kernel<<<TOK/8, 256>>>(x2b, n2w, n2b, y2b);
    hgemm_kernel<<<dim3(11,49), 256>>>(y2b, fc1_w, fc1_b, f1b, 682, 682, 128, 0, nullptr);
    dwconv_kernel<<<TOK, 384>>>(f1b, dw_w, dw_b, gbb);
    hgemm_kernel<<<dim3(2,49), 256>>>(gbb, fc2_w, fc2_b, out, 128, 128, 341, 2, x2b);
}

// round 7
// speedup vs baseline: 1.0759x; 1.0759x over previous
#include <cuda_runtime.h>
#include <cuda_fp16.h>
#include <math.h>

#define Bn   2
#define Cn   128
#define Hs   56
#define Nn   3136
#define NHn  4
#define HFn  341
#define TOK  (Bn*Nn)
#define LDF  352

// fp32 scratch
__device__ __align__(256) float g_tmp1[TOK*512];
__device__ __align__(256) float g_qs [8*Nn*32];
__device__ __align__(256) float g_qn [8*Nn*32];
__device__ __align__(256) float g_kl [8*Nn*32];
__device__ __align__(256) float g_vl [8*Nn*32];
__device__ __align__(256) float g_kvp[TOK*256];
__device__ __align__(256) float g_U  [8*Nn*32];
__device__ __align__(256) float g_Zp [8*Nn];
__device__ __align__(256) float g_x2 [TOK*Cn];
__device__ __align__(256) float g_f1 [TOK*682];
// half scratch (hi/lo split pairs)
__device__ __align__(256) __half g_yh [TOK*Cn], g_yl [TOK*Cn];
__device__ __align__(256) __half g_xph[TOK*Cn], g_xpl[TOK*Cn];
__device__ __align__(256) __half g_atth[TOK*Cn], g_attl[TOK*Cn];
__device__ __align__(256) __half g_y2h[TOK*Cn], g_y2l[TOK*Cn];
__device__ __align__(256) __half g_kph[TOK*Cn], g_kpl[TOK*Cn];
__device__ __align__(256) __half g_vph[TOK*Cn];
__device__ __align__(256) __half g_gbh[TOK*LDF], g_gbl[TOK*LDF];
// converted weights (one pool, offsets below)
#define OQ   0
#define OKV  16384
#define OSR  49152
#define OPJ  65536
#define OF1  81920
#define OF2  169216
__device__ __align__(256) __half g_wh[214272], g_wl[214272];

__device__ __forceinline__ float gelu_exact(float x) {
    return 0.5f * x * (1.0f + erff(x * 0.70710678118654752f));
}
__device__ __forceinline__ unsigned h2pack(float a, float b) {
    __half2 h = __floats2half2_rn(a, b);
    return *(unsigned*)&h;
}
__device__ __forceinline__ void hsplit(float v, __half& hi, __half& lo) {
    hi = __float2half_rn(v);
    lo = __float2half_rn(v - __half2float(hi));
}
__device__ __forceinline__ void mma16816(float* c, const unsigned* a, unsigned b0, unsigned b1) {
    asm volatile("mma.sync.aligned.m16n8k16.row.col.f32.f16.f16.f32 "
        "{%0,%1,%2,%3}, {%4,%5,%6,%7}, {%8,%9}, {%0,%1,%2,%3};"
        : "+f"(c[0]), "+f"(c[1]), "+f"(c[2]), "+f"(c[3])
        : "r"(a[0]), "r"(a[1]), "r"(a[2]), "r"(a[3]), "r"(b0), "r"(b1));
}

// ---------- weight fp32 -> fp16 hi/lo (zero-padded stride) ----------
__global__ void cvt_pad(const float* __restrict__ in, __half* __restrict__ hi,
                        __half* __restrict__ lo, int rows, int Kd, int ldp)
{
    int i = blockIdx.x * 256 + threadIdx.x;
    if (i >= rows * ldp) return;
    int r = i / ldp, c = i - r * ldp;
    float v = (c < Kd) ? in[(size_t)r * Kd + c] : 0.f;
    __half h, l; hsplit(v, h, l);
    hi[i] = h; lo[i] = l;
}

// ---------- LayerNorm (channel-major in) -> fp16 hi/lo token-major ----------
__global__ void ln_kernel(const float* __restrict__ in, const float* __restrict__ w,
                          const float* __restrict__ bvec,
                          __half* __restrict__ oh, __half* __restrict__ ol)
{
    int warp = blockIdx.x * 8 + (threadIdx.x >> 5);
    int lane = threadIdx.x & 31;
    int bb = warp / Nn, n = warp - bb * Nn;
    const float* p = in + (size_t)bb * (Cn*Nn) + n;
    float v[4], s = 0.f, s2 = 0.f;
#pragma unroll
    for (int pp = 0; pp < 2; pp++) {
        int c0 = 2*lane + 64*pp;
        v[2*pp]   = p[(size_t)c0 * Nn];
        v[2*pp+1] = p[(size_t)(c0+1) * Nn];
        s += v[2*pp] + v[2*pp+1];
        s2 += v[2*pp]*v[2*pp] + v[2*pp+1]*v[2*pp+1];
    }
#pragma unroll
    for (int d = 1; d < 32; d <<= 1) {
        s  += __shfl_xor_sync(0xffffffffu, s,  d);
        s2 += __shfl_xor_sync(0xffffffffu, s2, d);
    }
    float mu = s * (1.0f/128.0f);
    float rstd = rsqrtf(s2*(1.0f/128.0f) - mu*mu + 1e-5f);
    unsigned* ohp = (unsigned*)oh;
    unsigned* olp = (unsigned*)ol;
#pragma unroll
    for (int pp = 0; pp < 2; pp++) {
        int c0 = 2*lane + 64*pp;
        float a = (v[2*pp]  -mu)*rstd*w[c0]   + bvec[c0];
        float b = (v[2*pp+1]-mu)*rstd*w[c0+1] + bvec[c0+1];
        __half ah, al_, bh, bl; hsplit(a, ah, al_); hsplit(b, bh, bl);
        __half2 hh = __halves2half2(ah, bh), ll = __halves2half2(al_, bl);
        ohp[warp*64 + lane + 32*pp] = *(unsigned*)&hh;
        olp[warp*64 + lane + 32*pp] = *(unsigned*)&ll;
    }
}

// ---------- HMMA GEMM, gmem-direct fragments, no smem ----------
// BM=64 (4 warps x 16 rows), BN=64. ld = padded K stride (mult of 32, zero-padded).
__global__ void __launch_bounds__(128) hgemm2(
    const __half* __restrict__ Ah, const __half* __restrict__ Al,
    const __half* __restrict__ Wh, const __half* __restrict__ Wl, int ld,
    const float* __restrict__ bias, float* __restrict__ out,
    int ldo, int Nout, int mode, const float* __restrict__ res)
{
    const int m0 = blockIdx.y * 64;
    const int n0 = blockIdx.x * 64;
    const int warp = threadIdx.x >> 5;
    const int lane = threadIdx.x & 31;
    const int r  = lane >> 2;
    const int c2 = (lane & 3) * 2;

    float acc[8][4];
#pragma unroll
    for (int t = 0; t < 8; t++)
#pragma unroll
        for (int i = 0; i < 4; i++) acc[t][i] = 0.f;

    const int row1 = m0 + warp*16 + r;
    const __half* a1h = Ah + (size_t)row1 * ld;
    const __half* a2h = a1h + (size_t)8 * ld;
    const __half* a1l = Al + (size_t)row1 * ld;
    const __half* a2l = a1l + (size_t)8 * ld;

    const int nr = n0 + (lane >> 2);
    const __half* wrow[8];
    const __half* wrol[8];
#pragma unroll
    for (int nt = 0; nt < 8; nt++) {
        int n = nr + nt*8;
        int nc = (n < Nout) ? n : (Nout - 1);
        wrow[nt] = Wh + (size_t)nc * ld;
        wrol[nt] = Wl + (size_t)nc * ld;
    }

    const int KC = ld / 32;
    for (int kc = 0; kc < KC; kc++) {
#pragma unroll
        for (int ks = 0; ks < 2; ks++) {
            int d0 = kc*32 + ks*16 + c2;
            unsigned ah[4], al[4];
            ah[0] = *(const unsigned*)&a1h[d0];
            ah[1] = *(const unsigned*)&a2h[d0];
            ah[2] = *(const unsigned*)&a1h[d0+8];
            ah[3] = *(const unsigned*)&a2h[d0+8];
            al[0] = *(const unsigned*)&a1l[d0];
            al[1] = *(const unsigned*)&a2l[d0];
            al[2] = *(const unsigned*)&a1l[d0+8];
            al[3] = *(const unsigned*)&a2l[d0+8];
#pragma unroll
            for (int nt = 0; nt < 8; nt++) {
                unsigned bh0 = *(const unsigned*)&wrow[nt][d0];
                unsigned bh1 = *(const unsigned*)&wrow[nt][d0+8];
                unsigned bl0 = *(const unsigned*)&wrol[nt][d0];
                unsigned bl1 = *(const unsigned*)&wrol[nt][d0+8];
                mma16816(acc[nt], ah, bh0, bh1);
                mma16816(acc[nt], al, bh0, bh1);
                mma16816(acc[nt], ah, bl0, bl1);
            }
        }
    }

    int m1 = row1, m2 = row1 + 8;
#pragma unroll
    for (int nt = 0; nt < 8; nt++) {
        int n = n0 + nt*8 + c2;
#pragma unroll
        for (int j = 0; j < 2; j++) {
            int nn = n + j;
            if (nn >= Nout) continue;
            float v1 = acc[nt][j]   + bias[nn];
            float v2 = acc[nt][2+j] + bias[nn];
            if (mode == 0) {
                out[(size_t)m1*ldo + nn] = v1;
                out[(size_t)m2*ldo + nn] = v2;
            } else if (mode == 1) {
                size_t i1 = (size_t)m1*ldo + nn, i2 = (size_t)m2*ldo + nn;
                out[i1] = v1 + res[i1];
                out[i2] = v2 + res[i2];
            } else {
                int b1 = m1 / Nn, t1i = m1 - b1*Nn;
                int b2 = m2 / Nn, t2i = m2 - b2*Nn;
                size_t i1 = ((size_t)b1*Cn + nn)*Nn + t1i;
                size_t i2 = ((size_t)b2*Cn + nn)*Nn + t2i;
                out[i1] = v1 + res[i1];
                out[i2] = v2 + res[i2];
            }
        }
    }
}

// ---------- pointwise after GEMM1 ----------
__global__ void pointwise1(const float* __restrict__ tmp1, const float* __restrict__ temp,
                           const float* __restrict__ qe, const float* __restrict__ plnw,
                           const float* __restrict__ plnb,
                           float* __restrict__ qs, float* __restrict__ qn,
                           float* __restrict__ kl, float* __restrict__ vl,
                           __half* __restrict__ xph, __half* __restrict__ xpl)
{
    int t = blockIdx.x * 8 + (threadIdx.x >> 5);
    int lane = threadIdx.x & 31;
    int bb = t / Nn, n = t - bb * Nn;
    int h = lane >> 3;
    int g = bb * NHn + h;
    const float4* row = (const float4*)(tmp1 + (size_t)t * 512);
    size_t ho = ((size_t)g * Nn + n) * 8 + (lane & 7);

    float4 q4 = row[lane];
    float ss = q4.x*q4.x + q4.y*q4.y + q4.z*q4.z + q4.w*q4.w;
    ss += __shfl_xor_sync(0xffffffffu, ss, 1);
    ss += __shfl_xor_sync(0xffffffffu, ss, 2);
    ss += __shfl_xor_sync(0xffffffffu, ss, 4);
    float inv = 1.0f / fmaxf(sqrtf(ss), 1e-12f);
    float4 qn4 = make_float4(q4.x*inv, q4.y*inv, q4.z*inv, q4.w*inv);
    float tv = temp[h];
    float sp = log1pf(__expf(tv));
    float4 qe4 = ((const float4*)qe)[h*8 + (lane & 7)];
    ((float4*)qn)[ho] = qn4;
    ((float4*)qs)[ho] = make_float4((qn4.x+qe4.x)*sp, (qn4.y+qe4.y)*sp,
                                    (qn4.z+qe4.z)*sp, (qn4.w+qe4.w)*sp);

    float4 k4 = row[32 + lane];
    float ks = k4.x*k4.x + k4.y*k4.y + k4.z*k4.z + k4.w*k4.w;
    ks += __shfl_xor_sync(0xffffffffu, ks, 1);
    ks += __shfl_xor_sync(0xffffffffu, ks, 2);
    ks += __shfl_xor_sync(0xffffffffu, ks, 4);
    float ki = 1.0f / fmaxf(sqrtf(ks), 1e-12f);
    ((float4*)kl)[ho] = make_float4(k4.x*ki, k4.y*ki, k4.z*ki, k4.w*ki);
    ((float4*)vl)[ho] = row[64 + lane];

    float4 s4 = row[96 + lane];
    float g0 = gelu_exact(s4.x), g1 = gelu_exact(s4.y);
    float g2 = gelu_exact(s4.z), g3 = gelu_exact(s4.w);
    float sm = g0+g1+g2+g3;
    float sq = g0*g0+g1*g1+g2*g2+g3*g3;
#pragma unroll
    for (int d = 1; d < 32; d <<= 1) {
        sm += __shfl_xor_sync(0xffffffffu, sm, d);
        sq += __shfl_xor_sync(0xffffffffu, sq, d);
    }
    float mu = sm*(1.0f/128.0f);
    float rstd = rsqrtf(sq*(1.0f/128.0f) - mu*mu + 1e-5f);
    int c = lane * 4;
    float o0 = (g0-mu)*rstd*plnw[c]   + plnb[c];
    float o1 = (g1-mu)*rstd*plnw[c+1] + plnb[c+1];
    float o2 = (g2-mu)*rstd*plnw[c+2] + plnb[c+2];
    float o3 = (g3-mu)*rstd*plnw[c+3] + plnb[c+3];
    __half h0,l0,h1,l1,h2,l2,h3,l3;
    hsplit(o0,h0,l0); hsplit(o1,h1,l1); hsplit(o2,h2,l2); hsplit(o3,h3,l3);
    unsigned* xh = (unsigned*)xph;
    unsigned* xl = (unsigned*)xpl;
    __half2 a01 = __halves2half2(h0,h1), a23 = __halves2half2(h2,h3);
    __half2 b01 = __halves2half2(l0,l1), b23 = __halves2half2(l2,l3);
    xh[(size_t)t*64 + lane*2]     = *(unsigned*)&a01;
    xh[(size_t)t*64 + lane*2 + 1] = *(unsigned*)&a23;
    xl[(size_t)t*64 + lane*2]     = *(unsigned*)&b01;
    xl[(size_t)t*64 + lane*2 + 1] = *(unsigned*)&b23;
}

// ---------- split kvp -> fp16 hi/lo normalized kp + fp16 vp (head-major) ----------
__global__ void pointwise2(const float* __restrict__ kvp, __half* __restrict__ kph,
                           __half* __restrict__ kpl, __half* __restrict__ vph)
{
    int t = blockIdx.x * 8 + (threadIdx.x >> 5);
    int lane = threadIdx.x & 31;
    int bb = t / Nn, n = t - bb * Nn;
    int h = lane >> 3;
    int g = bb * NHn + h;
    const float4* row = (const float4*)(kvp + (size_t)t * 256);
    unsigned base = ((unsigned)g*Nn + n)*16 + (lane & 7)*2;

    float4 k4 = row[lane];
    float ks = k4.x*k4.x + k4.y*k4.y + k4.z*k4.z + k4.w*k4.w;
    ks += __shfl_xor_sync(0xffffffffu, ks, 1);
    ks += __shfl_xor_sync(0xffffffffu, ks, 2);
    ks += __shfl_xor_sync(0xffffffffu, ks, 4);
    float ki = 1.0f / fmaxf(sqrtf(ks), 1e-12f);
    float e0 = k4.x*ki, e1 = k4.y*ki, e2 = k4.z*ki, e3 = k4.w*ki;
    __half h0,l0,h1,l1,h2,l2,h3,l3;
    hsplit(e0,h0,l0); hsplit(e1,h1,l1); hsplit(e2,h2,l2); hsplit(e3,h3,l3);
    __half2 a01 = __halves2half2(h0,h1), a23 = __halves2half2(h2,h3);
    __half2 b01 = __halves2half2(l0,l1), b23 = __halves2half2(l2,l3);
    ((unsigned*)kph)[base]   = *(unsigned*)&a01;
    ((unsigned*)kph)[base+1] = *(unsigned*)&a23;
    ((unsigned*)kpl)[base]   = *(unsigned*)&b01;
    ((unsigned*)kpl)[base+1] = *(unsigned*)&b23;

    float4 v4 = row[32 + lane];
    ((unsigned*)vph)[base]   = h2pack(v4.x, v4.y);
    ((unsigned*)vph)[base+1] = h2pack(v4.z, v4.w);
}

// ---------- HMMA streaming pooled attention (preconverted inputs) ----------
__global__ void __launch_bounds__(128) attn_pool_mma(
    const float* __restrict__ qs, const __half* __restrict__ kph,
    const __half* __restrict__ kpl, const __half* __restrict__ vph,
    float* __restrict__ U, float* __restrict__ Zp)
{
    __shared__ __half Khi[128][40];
    __shared__ __half Klo[128][40];
    __shared__ __half Vt[32][132];

    const int g  = blockIdx.y;
    const int q0 = blockIdx.x * 64;
    const int tid = threadIdx.x;
    const int warp = tid >> 5;
    const int lane = tid & 31;
    const int r  = lane >> 2;
    const int c2 = (lane & 3) * 2;

    unsigned qhi[2][4], qlo[2][4];
    {
        const float* q0p = qs + ((size_t)g*Nn + q0 + warp*16 + r)*32;
        const float* q8p = q0p + 8*32;
#pragma unroll
        for (int ks = 0; ks < 2; ks++) {
            int d0 = ks*16 + c2;
            float x[4][2];
            x[0][0] = q0p[d0];   x[0][1] = q0p[d0+1];
            x[1][0] = q8p[d0];   x[1][1] = q8p[d0+1];
            x[2][0] = q0p[d0+8]; x[2][1] = q0p[d0+9];
            x[3][0] = q8p[d0+8]; x[3][1] = q8p[d0+9];
#pragma unroll
            for (int i = 0; i < 4; i++) {
                float a = x[i][0], b = x[i][1];
                float ah = __half2float(__float2half_rn(a));
                float bh = __half2float(__float2half_rn(b));
                qhi[ks][i] = h2pack(ah, bh);
                qlo[ks][i] = h2pack(a - ah, b - bh);
            }
        }
    }

    float uf[4][4];
#pragma unroll
    for (int t = 0; t < 4; t++)
#pragma unroll
        for (int i = 0; i < 4; i++) uf[t][i] = 0.f;
    float z0 = 0.f, z1 = 0.f;

    const int NCH = 25;
    for (int ch = 0; ch < NCH; ch++) {
        const int m0 = ch * 128;
        {
            int kvr = m0 + tid;
            bool ok = kvr < Nn;
            size_t rb = ((size_t)g*Nn + (ok ? kvr : 0))*32;
            const uint4* krh = (const uint4*)(kph + rb);
            const uint4* krl = (const uint4*)(kpl + rb);
            uint4 z4 = make_uint4(0,0,0,0);
#pragma unroll
            for (int j = 0; j < 4; j++) {
                *(uint4*)&Khi[tid][j*8] = ok ? krh[j] : z4;
                *(uint4*)&Klo[tid][j*8] = ok ? krl[j] : z4;
            }
            const unsigned* vr = (const unsigned*)(vph + rb);
#pragma unroll
            for (int j = 0; j < 16; j++) {
                unsigned p = ok ? vr[j] : 0u;
                __half2 hh = *(__half2*)&p;
                Vt[2*j][tid]   = hh.x;
                Vt[2*j+1][tid] = hh.y;
            }
        }
        __syncthreads();

        float sf[16][4];
#pragma unroll
        for (int t = 0; t < 16; t++)
#pragma unroll
            for (int i = 0; i < 4; i++) sf[t][i] = 0.f;

#pragma unroll
        for (int ks = 0; ks < 2; ks++) {
            int d0 = ks*16 + c2;
#pragma unroll
            for (int t = 0; t < 16; t++) {
                int kv = t*8 + (lane >> 2);
                unsigned bh0 = *(const unsigned*)&Khi[kv][d0];
                unsigned bh1 = *(const unsigned*)&Khi[kv][d0+8];
                unsigned bl0 = *(const unsigned*)&Klo[kv][d0];
                unsigned bl1 = *(const unsigned*)&Klo[kv][d0+8];
                mma16816(sf[t], qhi[ks], bh0, bh1);
                mma16816(sf[t], qhi[ks], bl0, bl1);
                mma16816(sf[t], qlo[ks], bh0, bh1);
            }
        }

        const int tlim = (m0 + 128 <= Nn) ? 16 : 8;
        unsigned ep[32];
#pragma unroll
        for (int t = 0; t < 16; t++) {
            if (t < tlim) {
                float e0 = __expf(sf[t][0]);
                float e1 = __expf(sf[t][1]);
                float e2 = __expf(sf[t][2]);
                float e3 = __expf(sf[t][3]);
                z0 += e0 + e1;
                z1 += e2 + e3;
                ep[2*t]   = h2pack(e0, e1);
                ep[2*t+1] = h2pack(e2, e3);
            } else {
                ep[2*t] = 0u; ep[2*t+1] = 0u;
            }
        }

        const int kkmax = (tlim == 16) ? 8 : 4;
        for (int kk = 0; kk < kkmax; kk++) {
            int kv0 = kk*16 + c2;
#pragma unroll
            for (int nt = 0; nt < 4; nt++) {
                int d = nt*8 + (lane >> 2);
                unsigned b0 = *(const unsigned*)&Vt[d][kv0];
                unsigned b1 = *(const unsigned*)&Vt[d][kv0+8];
                mma16816(uf[nt], &ep[4*kk], b0, b1);
            }
        }
        __syncthreads();
    }

    {
        int qrow = q0 + warp*16 + r;
        float* u0 = U + ((size_t)g*Nn + qrow)*32;
        float* u8 = u0 + 8*32;
#pragma unroll
        for (int nt = 0; nt < 4; nt++) {
            int d = nt*8 + c2;
            u0[d]   = uf[nt][0];
            u0[d+1] = uf[nt][1];
            u8[d]   = uf[nt][2];
            u8[d+1] = uf[nt][3];
        }
        z0 += __shfl_xor_sync(0xffffffffu, z0, 1);
        z0 += __shfl_xor_sync(0xffffffffu, z0, 2);
        z1 += __shfl_xor_sync(0xffffffffu, z1, 1);
        z1 += __shfl_xor_sync(0xffffffffu, z1, 2);
        if ((lane & 3) == 0) {
            Zp[(size_t)g*Nn + qrow]     = z0;
            Zp[(size_t)g*Nn + qrow + 8] = z1;
        }
    }
}

// ---------- finalize -> fp16 hi/lo att ----------
__global__ void attn_finalize(
    const float* __restrict__ qs, const float* __restrict__ qn,
    const float* __restrict__ kl, const float* __restrict__ vl,
    const float* __restrict__ U, const float* __restrict__ Zp,
    const float* __restrict__ lt, const float* __restrict__ lb,
    __half* __restrict__ atth, __half* __restrict__ attl)
{
    int warp = blockIdx.x * 8 + (threadIdx.x >> 5);
    int lane = threadIdx.x & 31;
    int g = warp / Nn, n = warp - g*Nn;
    int b = g >> 2, h = g & 3;
    int hh = n / Hs, ww = n - hh*Hs;
    size_t qi = ((size_t)g*Nn + n)*32 + lane;
    float q = qs[qi];
    float qv = qn[qi];
    float z = 0.f, res = 0.f, res2 = 0.f;
#pragma unroll
    for (int k = 0; k < 9; k++) {
        int h2 = hh + k/3 - 1, w2 = ww + (k%3) - 1;
        bool ok = (h2 >= 0 && h2 < Hs && w2 >= 0 && w2 < Hs);
        int nb = h2*Hs + w2;
        float kv = 0.f, vv = 0.f;
        if (ok) {
            size_t bi = ((size_t)g*Nn + nb)*32 + lane;
            kv = kl[bi]; vv = vl[bi];
        }
        float lg = q * kv;
        float wl = qv * lt[(h*32 + lane)*9 + k];
#pragma unroll
        for (int d = 16; d >= 1; d >>= 1) {
            lg += __shfl_xor_sync(0xffffffffu, lg, d);
            wl += __shfl_xor_sync(0xffffffffu, wl, d);
        }
        float e = __expf(lg);
        z += e;
        res  += e * vv;
        res2 += (wl + lb[h*9 + k]) * vv;
    }
    float Z = Zp[(size_t)g*Nn + n] + z;
    float o = (U[qi] + res) / Z + res2;
    size_t oi = ((size_t)(b*Nn + n))*128 + h*32 + lane;
    __half oh, ol; hsplit(o, oh, ol);
    atth[oi] = oh; attl[oi] = ol;
}

// ---------- depthwise 3x3 + gelu * v -> fp16 hi/lo (padded stride) ----------
__global__ void dwconv_kernel(const float* __restrict__ f1, const float* __restrict__ dww,
                              const float* __restrict__ dwb,
                              __half* __restrict__ gbh, __half* __restrict__ gbl)
{
    int t = blockIdx.x;
    int c = threadIdx.x;
    if (c >= LDF) return;
    size_t oi = (size_t)t*LDF + c;
    if (c >= HFn) { gbh[oi] = __float2half(0.f); gbl[oi] = __float2half(0.f); return; }
    int b = t / Nn, n = t - b*Nn;
    int hh = n / Hs, ww = n - hh*Hs;
    float acc = dwb[c];
#pragma unroll
    for (int k = 0; k < 9; k++) {
        int h2 = hh + k/3 - 1, w2 = ww + (k%3) - 1;
        if (h2 < 0 || h2 >= Hs || w2 < 0 || w2 >= Hs) continue;
        acc += f1[((size_t)(b*Nn + h2*Hs + w2))*682 + c] * dww[c*9 + k];
    }
    float v = f1[(size_t)t*682 + 341 + c];
    float o = gelu_exact(acc) * v;
    __half oh, ol; hsplit(o, oh, ol);
    gbh[oi] = oh; gbl[oi] = ol;
}

extern "C" void kernel_launch(void* const* d_in, const int* in_sizes, int n_in,
                              void* d_out, int out_size)
{
    const float* x      = (const float*)d_in[0];
    const float* n1w    = (const float*)d_in[1];
    const float* n1b    = (const float*)d_in[2];
    const float* q_w    = (const float*)d_in[3];
    const float* q_b    = (const float*)d_in[4];
    const float* kv_w   = (const float*)d_in[5];
    const float* kv_b   = (const float*)d_in[6];
    const float* temp   = (const float*)d_in[7];
    const float* qe     = (const float*)d_in[8];
    const float* lt     = (const float*)d_in[9];
    const float* lb     = (const float*)d_in[10];
    const float* sr_w   = (const float*)d_in[11];
    const float* sr_b   = (const float*)d_in[12];
    const float* plnw   = (const float*)d_in[13];
    const float* plnb   = (const float*)d_in[14];
    const float* proj_w = (const float*)d_in[15];
    const float* proj_b = (const float*)d_in[16];
    const float* n2w    = (const float*)d_in[17];
    const float* n2b    = (const float*)d_in[18];
    const float* fc1_w  = (const float*)d_in[19];
    const float* fc1_b  = (const float*)d_in[20];
    const float* dw_w   = (const float*)d_in[21];
    const float* dw_b   = (const float*)d_in[22];
    const float* fc2_w  = (const float*)d_in[23];
    const float* fc2_b  = (const float*)d_in[24];
    float* out = (float*)d_out;

    float *t1, *qsb, *qnb, *klb, *vlb, *kvpb, *Ub, *Zpb, *x2b, *f1b;
    __half *yh, *yl, *xph, *xpl, *atth, *attl, *y2h, *y2l, *kph, *kpl, *vphh, *gbh, *gbl, *wh, *wl;
    cudaGetSymbolAddress((void**)&t1,   g_tmp1);
    cudaGetSymbolAddress((void**)&qsb,  g_qs);
    cudaGetSymbolAddress((void**)&qnb,  g_qn);
    cudaGetSymbolAddress((void**)&klb,  g_kl);
    cudaGetSymbolAddress((void**)&vlb,  g_vl);
    cudaGetSymbolAddress((void**)&kvpb, g_kvp);
    cudaGetSymbolAddress((void**)&Ub,   g_U);
    cudaGetSymbolAddress((void**)&Zpb,  g_Zp);
    cudaGetSymbolAddress((void**)&x2b,  g_x2);
    cudaGetSymbolAddress((void**)&f1b,  g_f1);
    cudaGetSymbolAddress((void**)&yh,   g_yh);
    cudaGetSymbolAddress((void**)&yl,   g_yl);
    cudaGetSymbolAddress((void**)&xph,  g_xph);
    cudaGetSymbolAddress((void**)&xpl,  g_xpl);
    cudaGetSymbolAddress((void**)&atth, g_atth);
    cudaGetSymbolAddress((void**)&attl, g_attl);
    cudaGetSymbolAddress((void**)&y2h,  g_y2h);
    cudaGetSymbolAddress((void**)&y2l,  g_y2l);
    cudaGetSymbolAddress((void**)&kph,  g_kph);
    cudaGetSymbolAddress((void**)&kpl,  g_kpl);
    cudaGetSymbolAddress((void**)&vphh, g_vph);
    cudaGetSymbolAddress((void**)&gbh,  g_gbh);
    cudaGetSymbolAddress((void**)&gbl,  g_gbl);
    cudaGetSymbolAddress((void**)&wh,   g_wh);
    cudaGetSymbolAddress((void**)&wl,   g_wl);

    // weight conversions
    cvt_pad<<<64, 256>>>(q_w,    wh+OQ,  wl+OQ,  128, 128, 128);
    cvt_pad<<<128, 256>>>(kv_w,  wh+OKV, wl+OKV, 256, 128, 128);
    cvt_pad<<<64, 256>>>(sr_w,   wh+OSR, wl+OSR, 128, 128, 128);
    cvt_pad<<<64, 256>>>(proj_w, wh+OPJ, wl+OPJ, 128, 128, 128);
    cvt_pad<<<341, 256>>>(fc1_w, wh+OF1, wl+OF1, 682, 128, 128);
    cvt_pad<<<176, 256>>>(fc2_w, wh+OF2, wl+OF2, 128, 341, LDF);

    ln_kernel<<<TOK/8, 256>>>(x, n1w, n1b, yh, yl);
    hgemm2<<<dim3(2,98), 128>>>(yh, yl, wh+OQ,  wl+OQ,  128, q_b,  t1,       512, 128, 0, nullptr);
    hgemm2<<<dim3(4,98), 128>>>(yh, yl, wh+OKV, wl+OKV, 128, kv_b, t1 + 128, 512, 256, 0, nullptr);
    hgemm2<<<dim3(2,98), 128>>>(yh, yl, wh+OSR, wl+OSR, 128, sr_b, t1 + 384, 512, 128, 0, nullptr);
    pointwise1<<<TOK/8, 256>>>(t1, temp, qe, plnw, plnb, qsb, qnb, klb, vlb, xph, xpl);
    hgemm2<<<dim3(4,98), 128>>>(xph, xpl, wh+OKV, wl+OKV, 128, kv_b, kvpb, 256, 256, 0, nullptr);
    pointwise2<<<TOK/8, 256>>>(kvpb, kph, kpl, vphh);
    attn_pool_mma<<<dim3(49,8), 128>>>(qsb, kph, kpl, vphh, Ub, Zpb);
    attn_finalize<<<Nn, 256>>>(qsb, qnb, klb, vlb, Ub, Zpb, lt, lb, atth, attl);
    hgemm2<<<dim3(2,98), 128>>>(atth, attl, wh+OPJ, wl+OPJ, 128, proj_b, x2b, 128, 128, 1, x);
    ln_kernel<<<TOK/8, 256>>>(x2b, n2w, n2b, y2h, y2l);
    hgemm2<<<dim3(11,98), 128>>>(y2h, y2l, wh+OF1, wl+OF1, 128, fc1_b, f1b, 682, 682, 0, nullptr);
    dwconv_kernel<<<TOK, LDF>>>(f1b, dw_w, dw_b, gbh, gbl);
    hgemm2<<<dim3(2,98), 128>>>(gbh, gbl, wh+OF2, wl+OF2, LDF, fc2_b, out, 128, 128, 2, x2b);
}

// round 8
// speedup vs baseline: 1.1338x; 1.0538x over previous
#include <cuda_runtime.h>
#include <cuda_fp16.h>
#include <math.h>

#define Bn   2
#define Cn   128
#define Hs   56
#define Nn   3136
#define NHn  4
#define HFn  341
#define TOK  (Bn*Nn)
#define LDF  352

// fp32 scratch
__device__ __align__(256) float g_tmp1[TOK*512];
__device__ __align__(256) float g_qs [8*Nn*32];
__device__ __align__(256) float g_qn [8*Nn*32];
__device__ __align__(256) float g_kl [8*Nn*32];
__device__ __align__(256) float g_vl [8*Nn*32];
__device__ __align__(256) float g_kvp[TOK*256];
__device__ __align__(256) float g_x2 [TOK*Cn];
__device__ __align__(256) float g_f1 [TOK*682];
__device__ __align__(256) float g_b512[512];
// half scratch (hi/lo split pairs)
__device__ __align__(256) __half g_yh [TOK*Cn], g_yl [TOK*Cn];
__device__ __align__(256) __half g_xph[TOK*Cn], g_xpl[TOK*Cn];
__device__ __align__(256) __half g_atth[TOK*Cn], g_attl[TOK*Cn];
__device__ __align__(256) __half g_y2h[TOK*Cn], g_y2l[TOK*Cn];
__device__ __align__(256) __half g_kph[TOK*Cn], g_kpl[TOK*Cn];
__device__ __align__(256) __half g_vph[TOK*Cn];
__device__ __align__(256) __half g_gbh[TOK*LDF], g_gbl[TOK*LDF];
// converted weights pool
#define OQ   0
#define OKV  16384
#define OSR  49152
#define OPJ  65536
#define OF1  81920
#define OF2  169216
#define WTOT 214272
__device__ __align__(256) __half g_wh[WTOT], g_wl[WTOT];

__device__ __forceinline__ float gelu_exact(float x) {
    return 0.5f * x * (1.0f + erff(x * 0.70710678118654752f));
}
__device__ __forceinline__ unsigned h2pack(float a, float b) {
    __half2 h = __floats2half2_rn(a, b);
    return *(unsigned*)&h;
}
__device__ __forceinline__ void hsplit(float v, __half& hi, __half& lo) {
    hi = __float2half_rn(v);
    lo = __float2half_rn(v - __half2float(hi));
}
__device__ __forceinline__ void mma16816(float* c, const unsigned* a, unsigned b0, unsigned b1) {
    asm volatile("mma.sync.aligned.m16n8k16.row.col.f32.f16.f16.f32 "
        "{%0,%1,%2,%3}, {%4,%5,%6,%7}, {%8,%9}, {%0,%1,%2,%3};"
        : "+f"(c[0]), "+f"(c[1]), "+f"(c[2]), "+f"(c[3])
        : "r"(a[0]), "r"(a[1]), "r"(a[2]), "r"(a[3]), "r"(b0), "r"(b1));
}

// ---------- single-launch weight conversion + fused bias ----------
__global__ void cvt_all(const float* __restrict__ q_w, const float* __restrict__ kv_w,
                        const float* __restrict__ sr_w, const float* __restrict__ proj_w,
                        const float* __restrict__ fc1_w, const float* __restrict__ fc2_w,
                        const float* __restrict__ q_b, const float* __restrict__ kv_b,
                        const float* __restrict__ sr_b,
                        __half* __restrict__ wh, __half* __restrict__ wl,
                        float* __restrict__ b512)
{
    int i = blockIdx.x * 256 + threadIdx.x;
    if (i < WTOT) {
        float v;
        if      (i < OKV) v = q_w[i];
        else if (i < OSR) v = kv_w[i - OKV];
        else if (i < OPJ) v = sr_w[i - OSR];
        else if (i < OF1) v = proj_w[i - OPJ];
        else if (i < OF2) v = fc1_w[i - OF1];
        else {
            int j = i - OF2, r = j / LDF, c = j - r * LDF;
            v = (c < HFn) ? fc2_w[r * HFn + c] : 0.f;
        }
        __half h, l; hsplit(v, h, l);
        wh[i] = h; wl[i] = l;
    } else if (i < WTOT + 512) {
        int j = i - WTOT;
        b512[j] = (j < 128) ? q_b[j] : (j < 384) ? kv_b[j - 128] : sr_b[j - 384];
    }
}

// ---------- LayerNorm (channel-major in) -> fp16 hi/lo token-major ----------
__global__ void ln_kernel(const float* __restrict__ in, const float* __restrict__ w,
                          const float* __restrict__ bvec,
                          __half* __restrict__ oh, __half* __restrict__ ol)
{
    int warp = blockIdx.x * 8 + (threadIdx.x >> 5);
    int lane = threadIdx.x & 31;
    int bb = warp / Nn, n = warp - bb * Nn;
    const float* p = in + (size_t)bb * (Cn*Nn) + n;
    float v[4], s = 0.f, s2 = 0.f;
#pragma unroll
    for (int pp = 0; pp < 2; pp++) {
        int c0 = 2*lane + 64*pp;
        v[2*pp]   = p[(size_t)c0 * Nn];
        v[2*pp+1] = p[(size_t)(c0+1) * Nn];
        s += v[2*pp] + v[2*pp+1];
        s2 += v[2*pp]*v[2*pp] + v[2*pp+1]*v[2*pp+1];
    }
#pragma unroll
    for (int d = 1; d < 32; d <<= 1) {
        s  += __shfl_xor_sync(0xffffffffu, s,  d);
        s2 += __shfl_xor_sync(0xffffffffu, s2, d);
    }
    float mu = s * (1.0f/128.0f);
    float rstd = rsqrtf(s2*(1.0f/128.0f) - mu*mu + 1e-5f);
    unsigned* ohp = (unsigned*)oh;
    unsigned* olp = (unsigned*)ol;
#pragma unroll
    for (int pp = 0; pp < 2; pp++) {
        int c0 = 2*lane + 64*pp;
        float a = (v[2*pp]  -mu)*rstd*w[c0]   + bvec[c0];
        float b = (v[2*pp+1]-mu)*rstd*w[c0+1] + bvec[c0+1];
        __half ah, al_, bh, bl; hsplit(a, ah, al_); hsplit(b, bh, bl);
        __half2 hh = __halves2half2(ah, bh), ll = __halves2half2(al_, bl);
        ohp[warp*64 + lane + 32*pp] = *(unsigned*)&hh;
        olp[warp*64 + lane + 32*pp] = *(unsigned*)&ll;
    }
}

// ---------- HMMA GEMM, gmem-direct fragments ----------
__global__ void __launch_bounds__(128) hgemm2(
    const __half* __restrict__ Ah, const __half* __restrict__ Al,
    const __half* __restrict__ Wh, const __half* __restrict__ Wl, int ld,
    const float* __restrict__ bias, float* __restrict__ out,
    int ldo, int Nout, int mode, const float* __restrict__ res)
{
    const int m0 = blockIdx.y * 64;
    const int n0 = blockIdx.x * 64;
    const int warp = threadIdx.x >> 5;
    const int lane = threadIdx.x & 31;
    const int r  = lane >> 2;
    const int c2 = (lane & 3) * 2;

    float acc[8][4];
#pragma unroll
    for (int t = 0; t < 8; t++)
#pragma unroll
        for (int i = 0; i < 4; i++) acc[t][i] = 0.f;

    const int row1 = m0 + warp*16 + r;
    const __half* a1h = Ah + (size_t)row1 * ld;
    const __half* a2h = a1h + (size_t)8 * ld;
    const __half* a1l = Al + (size_t)row1 * ld;
    const __half* a2l = a1l + (size_t)8 * ld;

    const int nr = n0 + (lane >> 2);
    const __half* wrow[8];
    const __half* wrol[8];
#pragma unroll
    for (int nt = 0; nt < 8; nt++) {
        int n = nr + nt*8;
        int nc = (n < Nout) ? n : (Nout - 1);
        wrow[nt] = Wh + (size_t)nc * ld;
        wrol[nt] = Wl + (size_t)nc * ld;
    }

    const int KC = ld / 32;
    for (int kc = 0; kc < KC; kc++) {
#pragma unroll
        for (int ks = 0; ks < 2; ks++) {
            int d0 = kc*32 + ks*16 + c2;
            unsigned ah[4], al[4];
            ah[0] = *(const unsigned*)&a1h[d0];
            ah[1] = *(const unsigned*)&a2h[d0];
            ah[2] = *(const unsigned*)&a1h[d0+8];
            ah[3] = *(const unsigned*)&a2h[d0+8];
            al[0] = *(const unsigned*)&a1l[d0];
            al[1] = *(const unsigned*)&a2l[d0];
            al[2] = *(const unsigned*)&a1l[d0+8];
            al[3] = *(const unsigned*)&a2l[d0+8];
#pragma unroll
            for (int nt = 0; nt < 8; nt++) {
                unsigned bh0 = *(const unsigned*)&wrow[nt][d0];
                unsigned bh1 = *(const unsigned*)&wrow[nt][d0+8];
                unsigned bl0 = *(const unsigned*)&wrol[nt][d0];
                unsigned bl1 = *(const unsigned*)&wrol[nt][d0+8];
                mma16816(acc[nt], ah, bh0, bh1);
                mma16816(acc[nt], al, bh0, bh1);
                mma16816(acc[nt], ah, bl0, bl1);
            }
        }
    }

    int m1 = row1, m2 = row1 + 8;
#pragma unroll
    for (int nt = 0; nt < 8; nt++) {
        int n = n0 + nt*8 + c2;
#pragma unroll
        for (int j = 0; j < 2; j++) {
            int nn = n + j;
            if (nn >= Nout) continue;
            float v1 = acc[nt][j]   + bias[nn];
            float v2 = acc[nt][2+j] + bias[nn];
            if (mode == 0) {
                out[(size_t)m1*ldo + nn] = v1;
                out[(size_t)m2*ldo + nn] = v2;
            } else if (mode == 1) {
                size_t i1 = (size_t)m1*ldo + nn, i2 = (size_t)m2*ldo + nn;
                out[i1] = v1 + res[i1];
                out[i2] = v2 + res[i2];
            } else {
                int b1 = m1 / Nn, t1i = m1 - b1*Nn;
                int b2 = m2 / Nn, t2i = m2 - b2*Nn;
                size_t i1 = ((size_t)b1*Cn + nn)*Nn + t1i;
                size_t i2 = ((size_t)b2*Cn + nn)*Nn + t2i;
                out[i1] = v1 + res[i1];
                out[i2] = v2 + res[i2];
            }
        }
    }
}

// ---------- pointwise after fused QKVSR GEMM ----------
__global__ void pointwise1(const float* __restrict__ tmp1, const float* __restrict__ temp,
                           const float* __restrict__ qe, const float* __restrict__ plnw,
                           const float* __restrict__ plnb,
                           float* __restrict__ qs, float* __restrict__ qn,
                           float* __restrict__ kl, float* __restrict__ vl,
                           __half* __restrict__ xph, __half* __restrict__ xpl)
{
    int t = blockIdx.x * 8 + (threadIdx.x >> 5);
    int lane = threadIdx.x & 31;
    int bb = t / Nn, n = t - bb * Nn;
    int h = lane >> 3;
    int g = bb * NHn + h;
    const float4* row = (const float4*)(tmp1 + (size_t)t * 512);
    size_t ho = ((size_t)g * Nn + n) * 8 + (lane & 7);

    float4 q4 = row[lane];
    float ss = q4.x*q4.x + q4.y*q4.y + q4.z*q4.z + q4.w*q4.w;
    ss += __shfl_xor_sync(0xffffffffu, ss, 1);
    ss += __shfl_xor_sync(0xffffffffu, ss, 2);
    ss += __shfl_xor_sync(0xffffffffu, ss, 4);
    float inv = 1.0f / fmaxf(sqrtf(ss), 1e-12f);
    float4 qn4 = make_float4(q4.x*inv, q4.y*inv, q4.z*inv, q4.w*inv);
    float tv = temp[h];
    float sp = log1pf(__expf(tv));
    float4 qe4 = ((const float4*)qe)[h*8 + (lane & 7)];
    ((float4*)qn)[ho] = qn4;
    ((float4*)qs)[ho] = make_float4((qn4.x+qe4.x)*sp, (qn4.y+qe4.y)*sp,
                                    (qn4.z+qe4.z)*sp, (qn4.w+qe4.w)*sp);

    float4 k4 = row[32 + lane];
    float ks = k4.x*k4.x + k4.y*k4.y + k4.z*k4.z + k4.w*k4.w;
    ks += __shfl_xor_sync(0xffffffffu, ks, 1);
    ks += __shfl_xor_sync(0xffffffffu, ks, 2);
    ks += __shfl_xor_sync(0xffffffffu, ks, 4);
    float ki = 1.0f / fmaxf(sqrtf(ks), 1e-12f);
    ((float4*)kl)[ho] = make_float4(k4.x*ki, k4.y*ki, k4.z*ki, k4.w*ki);
    ((float4*)vl)[ho] = row[64 + lane];

    float4 s4 = row[96 + lane];
    float g0 = gelu_exact(s4.x), g1 = gelu_exact(s4.y);
    float g2 = gelu_exact(s4.z), g3 = gelu_exact(s4.w);
    float sm = g0+g1+g2+g3;
    float sq = g0*g0+g1*g1+g2*g2+g3*g3;
#pragma unroll
    for (int d = 1; d < 32; d <<= 1) {
        sm += __shfl_xor_sync(0xffffffffu, sm, d);
        sq += __shfl_xor_sync(0xffffffffu, sq, d);
    }
    float mu = sm*(1.0f/128.0f);
    float rstd = rsqrtf(sq*(1.0f/128.0f) - mu*mu + 1e-5f);
    int c = lane * 4;
    float o0 = (g0-mu)*rstd*plnw[c]   + plnb[c];
    float o1 = (g1-mu)*rstd*plnw[c+1] + plnb[c+1];
    float o2 = (g2-mu)*rstd*plnw[c+2] + plnb[c+2];
    float o3 = (g3-mu)*rstd*plnw[c+3] + plnb[c+3];
    __half h0,l0,h1,l1,h2,l2,h3,l3;
    hsplit(o0,h0,l0); hsplit(o1,h1,l1); hsplit(o2,h2,l2); hsplit(o3,h3,l3);
    unsigned* xh = (unsigned*)xph;
    unsigned* xl = (unsigned*)xpl;
    __half2 a01 = __halves2half2(h0,h1), a23 = __halves2half2(h2,h3);
    __half2 b01 = __halves2half2(l0,l1), b23 = __halves2half2(l2,l3);
    xh[(size_t)t*64 + lane*2]     = *(unsigned*)&a01;
    xh[(size_t)t*64 + lane*2 + 1] = *(unsigned*)&a23;
    xl[(size_t)t*64 + lane*2]     = *(unsigned*)&b01;
    xl[(size_t)t*64 + lane*2 + 1] = *(unsigned*)&b23;
}

// ---------- split kvp -> fp16 hi/lo normalized kp + fp16 vp ----------
__global__ void pointwise2(const float* __restrict__ kvp, __half* __restrict__ kph,
                           __half* __restrict__ kpl, __half* __restrict__ vph)
{
    int t = blockIdx.x * 8 + (threadIdx.x >> 5);
    int lane = threadIdx.x & 31;
    int bb = t / Nn, n = t - bb * Nn;
    int h = lane >> 3;
    int g = bb * NHn + h;
    const float4* row = (const float4*)(kvp + (size_t)t * 256);
    unsigned base = ((unsigned)g*Nn + n)*16 + (lane & 7)*2;

    float4 k4 = row[lane];
    float ks = k4.x*k4.x + k4.y*k4.y + k4.z*k4.z + k4.w*k4.w;
    ks += __shfl_xor_sync(0xffffffffu, ks, 1);
    ks += __shfl_xor_sync(0xffffffffu, ks, 2);
    ks += __shfl_xor_sync(0xffffffffu, ks, 4);
    float ki = 1.0f / fmaxf(sqrtf(ks), 1e-12f);
    float e0 = k4.x*ki, e1 = k4.y*ki, e2 = k4.z*ki, e3 = k4.w*ki;
    __half h0,l0,h1,l1,h2,l2,h3,l3;
    hsplit(e0,h0,l0); hsplit(e1,h1,l1); hsplit(e2,h2,l2); hsplit(e3,h3,l3);
    __half2 a01 = __halves2half2(h0,h1), a23 = __halves2half2(h2,h3);
    __half2 b01 = __halves2half2(l0,l1), b23 = __halves2half2(l2,l3);
    ((unsigned*)kph)[base]   = *(unsigned*)&a01;
    ((unsigned*)kph)[base+1] = *(unsigned*)&a23;
    ((unsigned*)kpl)[base]   = *(unsigned*)&b01;
    ((unsigned*)kpl)[base+1] = *(unsigned*)&b23;

    float4 v4 = row[32 + lane];
    ((unsigned*)vph)[base]   = h2pack(v4.x, v4.y);
    ((unsigned*)vph)[base+1] = h2pack(v4.z, v4.w);
}

// ---------- HMMA pooled attention + fused local/finalize ----------
__global__ void __launch_bounds__(128) attn_pool_mma(
    const float* __restrict__ qs, const __half* __restrict__ kph,
    const __half* __restrict__ kpl, const __half* __restrict__ vph,
    const float* __restrict__ qn, const float* __restrict__ kl,
    const float* __restrict__ vl, const float* __restrict__ lt,
    const float* __restrict__ lb,
    __half* __restrict__ atth, __half* __restrict__ attl)
{
    __shared__ __half Khi[128][40];
    __shared__ __half Klo[128][40];
    __shared__ __half Vt[32][132];

    const int g  = blockIdx.y;
    const int q0 = blockIdx.x * 64;
    const int tid = threadIdx.x;
    const int warp = tid >> 5;
    const int lane = tid & 31;
    const int r  = lane >> 2;
    const int c2 = (lane & 3) * 2;

    unsigned qhi[2][4], qlo[2][4];
    {
        const float* q0p = qs + ((size_t)g*Nn + q0 + warp*16 + r)*32;
        const float* q8p = q0p + 8*32;
#pragma unroll
        for (int ks = 0; ks < 2; ks++) {
            int d0 = ks*16 + c2;
            float x[4][2];
            x[0][0] = q0p[d0];   x[0][1] = q0p[d0+1];
            x[1][0] = q8p[d0];   x[1][1] = q8p[d0+1];
            x[2][0] = q0p[d0+8]; x[2][1] = q0p[d0+9];
            x[3][0] = q8p[d0+8]; x[3][1] = q8p[d0+9];
#pragma unroll
            for (int i = 0; i < 4; i++) {
                float a = x[i][0], b = x[i][1];
                float ah = __half2float(__float2half_rn(a));
                float bh = __half2float(__float2half_rn(b));
                qhi[ks][i] = h2pack(ah, bh);
                qlo[ks][i] = h2pack(a - ah, b - bh);
            }
        }
    }

    float uf[4][4];
#pragma unroll
    for (int t = 0; t < 4; t++)
#pragma unroll
        for (int i = 0; i < 4; i++) uf[t][i] = 0.f;
    float z0 = 0.f, z1 = 0.f;

    const int NCH = 25;
    for (int ch = 0; ch < NCH; ch++) {
        const int m0 = ch * 128;
        {
            int kvr = m0 + tid;
            bool ok = kvr < Nn;
            size_t rb = ((size_t)g*Nn + (ok ? kvr : 0))*32;
            const uint4* krh = (const uint4*)(kph + rb);
            const uint4* krl = (const uint4*)(kpl + rb);
            uint4 z4 = make_uint4(0,0,0,0);
#pragma unroll
            for (int j = 0; j < 4; j++) {
                *(uint4*)&Khi[tid][j*8] = ok ? krh[j] : z4;
                *(uint4*)&Klo[tid][j*8] = ok ? krl[j] : z4;
            }
            const unsigned* vr = (const unsigned*)(vph + rb);
#pragma unroll
            for (int j = 0; j < 16; j++) {
                unsigned p = ok ? vr[j] : 0u;
                __half2 hh = *(__half2*)&p;
                Vt[2*j][tid]   = hh.x;
                Vt[2*j+1][tid] = hh.y;
            }
        }
        __syncthreads();

        float sf[16][4];
#pragma unroll
        for (int t = 0; t < 16; t++)
#pragma unroll
            for (int i = 0; i < 4; i++) sf[t][i] = 0.f;

#pragma unroll
        for (int ks = 0; ks < 2; ks++) {
            int d0 = ks*16 + c2;
#pragma unroll
            for (int t = 0; t < 16; t++) {
                int kv = t*8 + (lane >> 2);
                unsigned bh0 = *(const unsigned*)&Khi[kv][d0];
                unsigned bh1 = *(const unsigned*)&Khi[kv][d0+8];
                unsigned bl0 = *(const unsigned*)&Klo[kv][d0];
                unsigned bl1 = *(const unsigned*)&Klo[kv][d0+8];
                mma16816(sf[t], qhi[ks], bh0, bh1);
                mma16816(sf[t], qhi[ks], bl0, bl1);
                mma16816(sf[t], qlo[ks], bh0, bh1);
            }
        }

        const int tlim = (m0 + 128 <= Nn) ? 16 : 8;
        unsigned ep[32];
#pragma unroll
        for (int t = 0; t < 16; t++) {
            if (t < tlim) {
                float e0 = __expf(sf[t][0]);
                float e1 = __expf(sf[t][1]);
                float e2 = __expf(sf[t][2]);
                float e3 = __expf(sf[t][3]);
                z0 += e0 + e1;
                z1 += e2 + e3;
                ep[2*t]   = h2pack(e0, e1);
                ep[2*t+1] = h2pack(e2, e3);
            } else {
                ep[2*t] = 0u; ep[2*t+1] = 0u;
            }
        }

        const int kkmax = (tlim == 16) ? 8 : 4;
        for (int kk = 0; kk < kkmax; kk++) {
            int kv0 = kk*16 + c2;
#pragma unroll
            for (int nt = 0; nt < 4; nt++) {
                int d = nt*8 + (lane >> 2);
                unsigned b0 = *(const unsigned*)&Vt[d][kv0];
                unsigned b1 = *(const unsigned*)&Vt[d][kv0+8];
                mma16816(uf[nt], &ep[4*kk], b0, b1);
            }
        }
        __syncthreads();
    }

    // ---- fused finalize: pool Z reduce + local 3x3 + learnable tokens ----
    z0 += __shfl_xor_sync(0xffffffffu, z0, 1);
    z0 += __shfl_xor_sync(0xffffffffu, z0, 2);
    z1 += __shfl_xor_sync(0xffffffffu, z1, 1);
    z1 += __shfl_xor_sync(0xffffffffu, z1, 2);

    const int b = g >> 2, h = g & 3;
#pragma unroll
    for (int half = 0; half < 2; half++) {
        int n = q0 + warp*16 + r + half*8;
        float Zpool = half ? z1 : z0;
        int hh = n / Hs, ww = n - hh*Hs;
        const float* qp  = qs + ((size_t)g*Nn + n)*32;
        const float* qnp = qn + ((size_t)g*Nn + n)*32;
        float qsv[8], qnv[8];
#pragma unroll
        for (int nt = 0; nt < 4; nt++)
#pragma unroll
            for (int j = 0; j < 2; j++) {
                int c = nt*8 + c2 + j;
                qsv[nt*2+j] = qp[c];
                qnv[nt*2+j] = qnp[c];
            }
        float resv[8], res2v[8];
#pragma unroll
        for (int i = 0; i < 8; i++) { resv[i] = 0.f; res2v[i] = 0.f; }
        float zl = 0.f;
#pragma unroll
        for (int k = 0; k < 9; k++) {
            int h2 = hh + k/3 - 1, w2 = ww + (k%3) - 1;
            bool ok = (h2 >= 0 && h2 < Hs && w2 >= 0 && w2 < Hs);
            size_t bi = ((size_t)g*Nn + (ok ? (h2*Hs + w2) : 0))*32;
            float klv[8], vlv[8];
            float lg = 0.f, wl = 0.f;
#pragma unroll
            for (int nt = 0; nt < 4; nt++)
#pragma unroll
                for (int j = 0; j < 2; j++) {
                    int c = nt*8 + c2 + j;
                    int idx = nt*2 + j;
                    klv[idx] = ok ? kl[bi + c] : 0.f;
                    vlv[idx] = ok ? vl[bi + c] : 0.f;
                    lg += qsv[idx] * klv[idx];
                    wl += qnv[idx] * lt[(h*32 + c)*9 + k];
                }
            lg += __shfl_xor_sync(0xffffffffu, lg, 1);
            lg += __shfl_xor_sync(0xffffffffu, lg, 2);
            wl += __shfl_xor_sync(0xffffffffu, wl, 1);
            wl += __shfl_xor_sync(0xffffffffu, wl, 2);
            float e = __expf(lg);
            zl += e;
            float w2l = wl + lb[h*9 + k];
#pragma unroll
            for (int i = 0; i < 8; i++) {
                resv[i]  += e   * vlv[i];
                res2v[i] += w2l * vlv[i];
            }
        }
        float Zf = Zpool + zl;
        float rZ = 1.0f / Zf;
#pragma unroll
        for (int nt = 0; nt < 4; nt++)
#pragma unroll
            for (int j = 0; j < 2; j++) {
                int c = nt*8 + c2 + j;
                int idx = nt*2 + j;
                float o = (uf[nt][half*2 + j] + resv[idx]) * rZ + res2v[idx];
                size_t oi = ((size_t)(b*Nn + n))*128 + h*32 + c;
                __half oh, ol; hsplit(o, oh, ol);
                atth[oi] = oh; attl[oi] = ol;
            }
    }
}

// ---------- depthwise 3x3 + gelu * v -> fp16 hi/lo (padded stride) ----------
__global__ void dwconv_kernel(const float* __restrict__ f1, const float* __restrict__ dww,
                              const float* __restrict__ dwb,
                              __half* __restrict__ gbh, __half* __restrict__ gbl)
{
    int t = blockIdx.x;
    int c = threadIdx.x;
    if (c >= LDF) return;
    size_t oi = (size_t)t*LDF + c;
    if (c >= HFn) { gbh[oi] = __float2half(0.f); gbl[oi] = __float2half(0.f); return; }
    int b = t / Nn, n = t - b*Nn;
    int hh = n / Hs, ww = n - hh*Hs;
    float acc = dwb[c];
#pragma unroll
    for (int k = 0; k < 9; k++) {
        int h2 = hh + k/3 - 1, w2 = ww + (k%3) - 1;
        if (h2 < 0 || h2 >= Hs || w2 < 0 || w2 >= Hs) continue;
        acc += f1[((size_t)(b*Nn + h2*Hs + w2))*682 + c] * dww[c*9 + k];
    }
    float v = f1[(size_t)t*682 + 341 + c];
    float o = gelu_exact(acc) * v;
    __half oh, ol; hsplit(o, oh, ol);
    gbh[oi] = oh; gbl[oi] = ol;
}

extern "C" void kernel_launch(void* const* d_in, const int* in_sizes, int n_in,
                              void* d_out, int out_size)
{
    const float* x      = (const float*)d_in[0];
    const float* n1w    = (const float*)d_in[1];
    const float* n1b    = (const float*)d_in[2];
    const float* q_w    = (const float*)d_in[3];
    const float* q_b    = (const float*)d_in[4];
    const float* kv_w   = (const float*)d_in[5];
    const float* kv_b   = (const float*)d_in[6];
    const float* temp   = (const float*)d_in[7];
    const float* qe     = (const float*)d_in[8];
    const float* lt     = (const float*)d_in[9];
    const float* lb     = (const float*)d_in[10];
    const float* sr_w   = (const float*)d_in[11];
    const float* sr_b   = (const float*)d_in[12];
    const float* plnw   = (const float*)d_in[13];
    const float* plnb   = (const float*)d_in[14];
    const float* proj_w = (const float*)d_in[15];
    const float* proj_b = (const float*)d_in[16];
    const float* n2w    = (const float*)d_in[17];
    const float* n2b    = (const float*)d_in[18];
    const float* fc1_w  = (const float*)d_in[19];
    const float* fc1_b  = (const float*)d_in[20];
    const float* dw_w   = (const float*)d_in[21];
    const float* dw_b   = (const float*)d_in[22];
    const float* fc2_w  = (const float*)d_in[23];
    const float* fc2_b  = (const float*)d_in[24];
    float* out = (float*)d_out;

    float *t1, *qsb, *qnb, *klb, *vlb, *kvpb, *x2b, *f1b, *b512;
    __half *yh, *yl, *xph, *xpl, *atth, *attl, *y2h, *y2l, *kph, *kpl, *vphh, *gbh, *gbl, *wh, *wl;
    cudaGetSymbolAddress((void**)&t1,   g_tmp1);
    cudaGetSymbolAddress((void**)&qsb,  g_qs);
    cudaGetSymbolAddress((void**)&qnb,  g_qn);
    cudaGetSymbolAddress((void**)&klb,  g_kl);
    cudaGetSymbolAddress((void**)&vlb,  g_vl);
    cudaGetSymbolAddress((void**)&kvpb, g_kvp);
    cudaGetSymbolAddress((void**)&x2b,  g_x2);
    cudaGetSymbolAddress((void**)&f1b,  g_f1);
    cudaGetSymbolAddress((void**)&b512, g_b512);
    cudaGetSymbolAddress((void**)&yh,   g_yh);
    cudaGetSymbolAddress((void**)&yl,   g_yl);
    cudaGetSymbolAddress((void**)&xph,  g_xph);
    cudaGetSymbolAddress((void**)&xpl,  g_xpl);
    cudaGetSymbolAddress((void**)&atth, g_atth);
    cudaGetSymbolAddress((void**)&attl, g_attl);
    cudaGetSymbolAddress((void**)&y2h,  g_y2h);
    cudaGetSymbolAddress((void**)&y2l,  g_y2l);
    cudaGetSymbolAddress((void**)&kph,  g_kph);
    cudaGetSymbolAddress((void**)&kpl,  g_kpl);
    cudaGetSymbolAddress((void**)&vphh, g_vph);
    cudaGetSymbolAddress((void**)&gbh,  g_gbh);
    cudaGetSymbolAddress((void**)&gbl,  g_gbl);
    cudaGetSymbolAddress((void**)&wh,   g_wh);
    cudaGetSymbolAddress((void**)&wl,   g_wl);

    cvt_all<<<840, 256>>>(q_w, kv_w, sr_w, proj_w, fc1_w, fc2_w, q_b, kv_b, sr_b, wh, wl, b512);

    ln_kernel<<<TOK/8, 256>>>(x, n1w, n1b, yh, yl);
    hgemm2<<<dim3(8,98), 128>>>(yh, yl, wh+OQ, wl+OQ, 128, b512, t1, 512, 512, 0, nullptr);
    pointwise1<<<TOK/8, 256>>>(t1, temp, qe, plnw, plnb, qsb, qnb, klb, vlb, xph, xpl);
    hgemm2<<<dim3(4,98), 128>>>(xph, xpl, wh+OKV, wl+OKV, 128, kv_b, kvpb, 256, 256, 0, nullptr);
    pointwise2<<<TOK/8, 256>>>(kvpb, kph, kpl, vphh);
    attn_pool_mma<<<dim3(49,8), 128>>>(qsb, kph, kpl, vphh, qnb, klb, vlb, lt, lb, atth, attl);
    hgemm2<<<dim3(2,98), 128>>>(atth, attl, wh+OPJ, wl+OPJ, 128, proj_b, x2b, 128, 128, 1, x);
    ln_kernel<<<TOK/8, 256>>>(x2b, n2w, n2b, y2h, y2l);
    hgemm2<<<dim3(11,98), 128>>>(y2h, y2l, wh+OF1, wl+OF1, 128, fc1_b, f1b, 682, 682, 0, nullptr);
    dwconv_kernel<<<TOK, LDF>>>(f1b, dw_w, dw_b, gbh, gbl);
    hgemm2<<<dim3(2,98), 128>>>(gbh, gbl, wh+OF2, wl+OF2, LDF, fc2_b, out, 128, 128, 2, x2b);
}

// round 9
// speedup vs baseline: 1.2641x; 1.1149x over previous
#include <cuda_runtime.h>
#include <cuda_fp16.h>
#include <math.h>

#define Bn   2
#define Cn   128
#define Hs   56
#define Nn   3136
#define NHn  4
#define HFn  341
#define TOK  (Bn*Nn)
#define LDF  352

// fp32 scratch
__device__ __align__(256) float g_tmp1[TOK*512];
__device__ __align__(256) float g_qs [8*Nn*32];
__device__ __align__(256) float g_qn [8*Nn*32];
__device__ __align__(256) float g_kl [8*Nn*32];
__device__ __align__(256) float g_vl [8*Nn*32];
__device__ __align__(256) float g_x2 [TOK*Cn];
__device__ __align__(256) float g_f1 [TOK*682];
__device__ __align__(256) float g_b512[512];
// half scratch
__device__ __align__(256) __half g_yh [TOK*Cn], g_yl [TOK*Cn];
__device__ __align__(256) __half g_xph[TOK*Cn], g_xpl[TOK*Cn];
__device__ __align__(256) __half g_atth[TOK*Cn], g_attl[TOK*Cn];
__device__ __align__(256) __half g_y2h[TOK*Cn], g_y2l[TOK*Cn];
__device__ __align__(256) __half g_kph[TOK*Cn];
__device__ __align__(256) __half g_vph[TOK*Cn];
__device__ __align__(256) __half g_gbh[TOK*LDF], g_gbl[TOK*LDF];
// converted weights pool
#define OQ   0
#define OKV  16384
#define OSR  49152
#define OPJ  65536
#define OF1  81920
#define OF2  169216
#define WTOT 214272
__device__ __align__(256) __half g_wh[WTOT], g_wl[WTOT];

__device__ __forceinline__ float gelu_exact(float x) {
    return 0.5f * x * (1.0f + erff(x * 0.70710678118654752f));
}
__device__ __forceinline__ unsigned h2pack(float a, float b) {
    __half2 h = __floats2half2_rn(a, b);
    return *(unsigned*)&h;
}
__device__ __forceinline__ void hsplit(float v, __half& hi, __half& lo) {
    hi = __float2half_rn(v);
    lo = __float2half_rn(v - __half2float(hi));
}
__device__ __forceinline__ void mma16816(float* c, const unsigned* a, unsigned b0, unsigned b1) {
    asm volatile("mma.sync.aligned.m16n8k16.row.col.f32.f16.f16.f32 "
        "{%0,%1,%2,%3}, {%4,%5,%6,%7}, {%8,%9}, {%0,%1,%2,%3};"
        : "+f"(c[0]), "+f"(c[1]), "+f"(c[2]), "+f"(c[3])
        : "r"(a[0]), "r"(a[1]), "r"(a[2]), "r"(a[3]), "r"(b0), "r"(b1));
}

// ---------- single-launch weight conversion + fused bias ----------
__global__ void cvt_all(const float* __restrict__ q_w, const float* __restrict__ kv_w,
                        const float* __restrict__ sr_w, const float* __restrict__ proj_w,
                        const float* __restrict__ fc1_w, const float* __restrict__ fc2_w,
                        const float* __restrict__ q_b, const float* __restrict__ kv_b,
                        const float* __restrict__ sr_b,
                        __half* __restrict__ wh, __half* __restrict__ wl,
                        float* __restrict__ b512)
{
    int i = blockIdx.x * 256 + threadIdx.x;
    if (i < WTOT) {
        float v;
        if      (i < OKV) v = q_w[i];
        else if (i < OSR) v = kv_w[i - OKV];
        else if (i < OPJ) v = sr_w[i - OSR];
        else if (i < OF1) v = proj_w[i - OPJ];
        else if (i < OF2) v = fc1_w[i - OF1];
        else {
            int j = i - OF2, r = j / LDF, c = j - r * LDF;
            v = (c < HFn) ? fc2_w[r * HFn + c] : 0.f;
        }
        __half h, l; hsplit(v, h, l);
        wh[i] = h; wl[i] = l;
    } else if (i < WTOT + 512) {
        int j = i - WTOT;
        b512[j] = (j < 128) ? q_b[j] : (j < 384) ? kv_b[j - 128] : sr_b[j - 384];
    }
}

// ---------- LayerNorm (channel-major in) -> fp16 hi/lo token-major ----------
__global__ void ln_kernel(const float* __restrict__ in, const float* __restrict__ w,
                          const float* __restrict__ bvec,
                          __half* __restrict__ oh, __half* __restrict__ ol)
{
    int warp = blockIdx.x * 8 + (threadIdx.x >> 5);
    int lane = threadIdx.x & 31;
    int bb = warp / Nn, n = warp - bb * Nn;
    const float* p = in + (size_t)bb * (Cn*Nn) + n;
    float v[4], s = 0.f, s2 = 0.f;
#pragma unroll
    for (int pp = 0; pp < 2; pp++) {
        int c0 = 2*lane + 64*pp;
        v[2*pp]   = p[(size_t)c0 * Nn];
        v[2*pp+1] = p[(size_t)(c0+1) * Nn];
        s += v[2*pp] + v[2*pp+1];
        s2 += v[2*pp]*v[2*pp] + v[2*pp+1]*v[2*pp+1];
    }
#pragma unroll
    for (int d = 1; d < 32; d <<= 1) {
        s  += __shfl_xor_sync(0xffffffffu, s,  d);
        s2 += __shfl_xor_sync(0xffffffffu, s2, d);
    }
    float mu = s * (1.0f/128.0f);
    float rstd = rsqrtf(s2*(1.0f/128.0f) - mu*mu + 1e-5f);
    unsigned* ohp = (unsigned*)oh;
    unsigned* olp = (unsigned*)ol;
#pragma unroll
    for (int pp = 0; pp < 2; pp++) {
        int c0 = 2*lane + 64*pp;
        float a = (v[2*pp]  -mu)*rstd*w[c0]   + bvec[c0];
        float b = (v[2*pp+1]-mu)*rstd*w[c0+1] + bvec[c0+1];
        __half ah, al_, bh, bl; hsplit(a, ah, al_); hsplit(b, bh, bl);
        __half2 hh = __halves2half2(ah, bh), ll = __halves2half2(al_, bl);
        ohp[warp*64 + lane + 32*pp] = *(unsigned*)&hh;
        olp[warp*64 + lane + 32*pp] = *(unsigned*)&ll;
    }
}

// ---------- HMMA GEMM, gmem-direct fragments ----------
__global__ void __launch_bounds__(128) hgemm2(
    const __half* __restrict__ Ah, const __half* __restrict__ Al,
    const __half* __restrict__ Wh, const __half* __restrict__ Wl, int ld,
    const float* __restrict__ bias, float* __restrict__ out,
    int ldo, int Nout, int mode, const float* __restrict__ res)
{
    const int m0 = blockIdx.y * 64;
    const int n0 = blockIdx.x * 64;
    const int warp = threadIdx.x >> 5;
    const int lane = threadIdx.x & 31;
    const int r  = lane >> 2;
    const int c2 = (lane & 3) * 2;

    float acc[8][4];
#pragma unroll
    for (int t = 0; t < 8; t++)
#pragma unroll
        for (int i = 0; i < 4; i++) acc[t][i] = 0.f;

    const int row1 = m0 + warp*16 + r;
    const __half* a1h = Ah + (size_t)row1 * ld;
    const __half* a2h = a1h + (size_t)8 * ld;
    const __half* a1l = Al + (size_t)row1 * ld;
    const __half* a2l = a1l + (size_t)8 * ld;

    const int nr = n0 + (lane >> 2);
    const __half* wrow[8];
    const __half* wrol[8];
#pragma unroll
    for (int nt = 0; nt < 8; nt++) {
        int n = nr + nt*8;
        int nc = (n < Nout) ? n : (Nout - 1);
        wrow[nt] = Wh + (size_t)nc * ld;
        wrol[nt] = Wl + (size_t)nc * ld;
    }

    const int KC = ld / 32;
    for (int kc = 0; kc < KC; kc++) {
#pragma unroll
        for (int ks = 0; ks < 2; ks++) {
            int d0 = kc*32 + ks*16 + c2;
            unsigned ah[4], al[4];
            ah[0] = *(const unsigned*)&a1h[d0];
            ah[1] = *(const unsigned*)&a2h[d0];
            ah[2] = *(const unsigned*)&a1h[d0+8];
            ah[3] = *(const unsigned*)&a2h[d0+8];
            al[0] = *(const unsigned*)&a1l[d0];
            al[1] = *(const unsigned*)&a2l[d0];
            al[2] = *(const unsigned*)&a1l[d0+8];
            al[3] = *(const unsigned*)&a2l[d0+8];
#pragma unroll
            for (int nt = 0; nt < 8; nt++) {
                unsigned bh0 = *(const unsigned*)&wrow[nt][d0];
                unsigned bh1 = *(const unsigned*)&wrow[nt][d0+8];
                unsigned bl0 = *(const unsigned*)&wrol[nt][d0];
                unsigned bl1 = *(const unsigned*)&wrol[nt][d0+8];
                mma16816(acc[nt], ah, bh0, bh1);
                mma16816(acc[nt], al, bh0, bh1);
                mma16816(acc[nt], ah, bl0, bl1);
            }
        }
    }

    int m1 = row1, m2 = row1 + 8;
#pragma unroll
    for (int nt = 0; nt < 8; nt++) {
        int n = n0 + nt*8 + c2;
#pragma unroll
        for (int j = 0; j < 2; j++) {
            int nn = n + j;
            if (nn >= Nout) continue;
            float v1 = acc[nt][j]   + bias[nn];
            float v2 = acc[nt][2+j] + bias[nn];
            if (mode == 0) {
                out[(size_t)m1*ldo + nn] = v1;
                out[(size_t)m2*ldo + nn] = v2;
            } else if (mode == 1) {
                size_t i1 = (size_t)m1*ldo + nn, i2 = (size_t)m2*ldo + nn;
                out[i1] = v1 + res[i1];
                out[i2] = v2 + res[i2];
            } else {
                int b1 = m1 / Nn, t1i = m1 - b1*Nn;
                int b2 = m2 / Nn, t2i = m2 - b2*Nn;
                size_t i1 = ((size_t)b1*Cn + nn)*Nn + t1i;
                size_t i2 = ((size_t)b2*Cn + nn)*Nn + t2i;
                out[i1] = v1 + res[i1];
                out[i2] = v2 + res[i2];
            }
        }
    }
}

// ---------- HMMA kv GEMM with fused l2norm/split epilogue -> kph/vph fp16 ----------
__global__ void __launch_bounds__(128) hgemm_kv(
    const __half* __restrict__ Ah, const __half* __restrict__ Al,
    const __half* __restrict__ Wh, const __half* __restrict__ Wl,
    const float* __restrict__ bias,
    __half* __restrict__ kph, __half* __restrict__ vph)
{
    const int m0 = blockIdx.y * 64;
    const int n0 = blockIdx.x * 64;
    const int warp = threadIdx.x >> 5;
    const int lane = threadIdx.x & 31;
    const int r  = lane >> 2;
    const int c2 = (lane & 3) * 2;
    const int ld = 128;

    float acc[8][4];
#pragma unroll
    for (int t = 0; t < 8; t++)
#pragma unroll
        for (int i = 0; i < 4; i++) acc[t][i] = 0.f;

    const int row1 = m0 + warp*16 + r;
    const __half* a1h = Ah + (size_t)row1 * ld;
    const __half* a2h = a1h + (size_t)8 * ld;
    const __half* a1l = Al + (size_t)row1 * ld;
    const __half* a2l = a1l + (size_t)8 * ld;

    const int nr = n0 + (lane >> 2);
    const __half* wrow[8];
    const __half* wrol[8];
#pragma unroll
    for (int nt = 0; nt < 8; nt++) {
        wrow[nt] = Wh + (size_t)(nr + nt*8) * ld;
        wrol[nt] = Wl + (size_t)(nr + nt*8) * ld;
    }

#pragma unroll
    for (int kc = 0; kc < 4; kc++) {
#pragma unroll
        for (int ks = 0; ks < 2; ks++) {
            int d0 = kc*32 + ks*16 + c2;
            unsigned ah[4], al[4];
            ah[0] = *(const unsigned*)&a1h[d0];
            ah[1] = *(const unsigned*)&a2h[d0];
            ah[2] = *(const unsigned*)&a1h[d0+8];
            ah[3] = *(const unsigned*)&a2h[d0+8];
            al[0] = *(const unsigned*)&a1l[d0];
            al[1] = *(const unsigned*)&a2l[d0];
            al[2] = *(const unsigned*)&a1l[d0+8];
            al[3] = *(const unsigned*)&a2l[d0+8];
#pragma unroll
            for (int nt = 0; nt < 8; nt++) {
                unsigned bh0 = *(const unsigned*)&wrow[nt][d0];
                unsigned bh1 = *(const unsigned*)&wrow[nt][d0+8];
                unsigned bl0 = *(const unsigned*)&wrol[nt][d0];
                unsigned bl1 = *(const unsigned*)&wrol[nt][d0+8];
                mma16816(acc[nt], ah, bh0, bh1);
                mma16816(acc[nt], al, bh0, bh1);
                mma16816(acc[nt], ah, bl0, bl1);
            }
        }
    }

    // fused epilogue: cols [0,128) -> per-head l2norm -> kph; cols [128,256) -> vph
#pragma unroll
    for (int half = 0; half < 2; half++) {
        int m = row1 + half*8;
        int bb = m / Nn, n = m - bb*Nn;
        float vals[16];
#pragma unroll
        for (int nt = 0; nt < 8; nt++)
#pragma unroll
            for (int j = 0; j < 2; j++)
                vals[nt*2+j] = acc[nt][half*2+j] + bias[n0 + nt*8 + c2 + j];
        if (n0 < 128) {
            float se = 0.f, so = 0.f;
#pragma unroll
            for (int i = 0; i < 8; i++) { se += vals[i]*vals[i]; so += vals[8+i]*vals[8+i]; }
            se += __shfl_xor_sync(0xffffffffu, se, 1);
            se += __shfl_xor_sync(0xffffffffu, se, 2);
            so += __shfl_xor_sync(0xffffffffu, so, 1);
            so += __shfl_xor_sync(0xffffffffu, so, 2);
            float ke = 1.0f / fmaxf(sqrtf(se), 1e-12f);
            float ko = 1.0f / fmaxf(sqrtf(so), 1e-12f);
#pragma unroll
            for (int nt = 0; nt < 8; nt++) {
                int col = n0 + nt*8 + c2;
                int head = col >> 5;
                float sc = (nt < 4) ? ke : ko;
                __half2 hv = __floats2half2_rn(vals[nt*2]*sc, vals[nt*2+1]*sc);
                *(__half2*)&kph[((size_t)(bb*NHn + head)*Nn + n)*32 + (col & 31)] = hv;
            }
        } else {
#pragma unroll
            for (int nt = 0; nt < 8; nt++) {
                int col = n0 - 128 + nt*8 + c2;
                int head = col >> 5;
                __half2 hv = __floats2half2_rn(vals[nt*2], vals[nt*2+1]);
                *(__half2*)&vph[((size_t)(bb*NHn + head)*Nn + n)*32 + (col & 31)] = hv;
            }
        }
    }
}

// ---------- pointwise after fused QKVSR GEMM ----------
__global__ void pointwise1(const float* __restrict__ tmp1, const float* __restrict__ temp,
                           const float* __restrict__ qe, const float* __restrict__ plnw,
                           const float* __restrict__ plnb,
                           float* __restrict__ qs, float* __restrict__ qn,
                           float* __restrict__ kl, float* __restrict__ vl,
                           __half* __restrict__ xph, __half* __restrict__ xpl)
{
    int t = blockIdx.x * 8 + (threadIdx.x >> 5);
    int lane = threadIdx.x & 31;
    int bb = t / Nn, n = t - bb * Nn;
    int h = lane >> 3;
    int g = bb * NHn + h;
    const float4* row = (const float4*)(tmp1 + (size_t)t * 512);
    size_t ho = ((size_t)g * Nn + n) * 8 + (lane & 7);

    float4 q4 = row[lane];
    float ss = q4.x*q4.x + q4.y*q4.y + q4.z*q4.z + q4.w*q4.w;
    ss += __shfl_xor_sync(0xffffffffu, ss, 1);
    ss += __shfl_xor_sync(0xffffffffu, ss, 2);
    ss += __shfl_xor_sync(0xffffffffu, ss, 4);
    float inv = 1.0f / fmaxf(sqrtf(ss), 1e-12f);
    float4 qn4 = make_float4(q4.x*inv, q4.y*inv, q4.z*inv, q4.w*inv);
    float tv = temp[h];
    float sp = log1pf(__expf(tv));
    float4 qe4 = ((const float4*)qe)[h*8 + (lane & 7)];
    ((float4*)qn)[ho] = qn4;
    ((float4*)qs)[ho] = make_float4((qn4.x+qe4.x)*sp, (qn4.y+qe4.y)*sp,
                                    (qn4.z+qe4.z)*sp, (qn4.w+qe4.w)*sp);

    float4 k4 = row[32 + lane];
    float ks = k4.x*k4.x + k4.y*k4.y + k4.z*k4.z + k4.w*k4.w;
    ks += __shfl_xor_sync(0xffffffffu, ks, 1);
    ks += __shfl_xor_sync(0xffffffffu, ks, 2);
    ks += __shfl_xor_sync(0xffffffffu, ks, 4);
    float ki = 1.0f / fmaxf(sqrtf(ks), 1e-12f);
    ((float4*)kl)[ho] = make_float4(k4.x*ki, k4.y*ki, k4.z*ki, k4.w*ki);
    ((float4*)vl)[ho] = row[64 + lane];

    float4 s4 = row[96 + lane];
    float g0 = gelu_exact(s4.x), g1 = gelu_exact(s4.y);
    float g2 = gelu_exact(s4.z), g3 = gelu_exact(s4.w);
    float sm = g0+g1+g2+g3;
    float sq = g0*g0+g1*g1+g2*g2+g3*g3;
#pragma unroll
    for (int d = 1; d < 32; d <<= 1) {
        sm += __shfl_xor_sync(0xffffffffu, sm, d);
        sq += __shfl_xor_sync(0xffffffffu, sq, d);
    }
    float mu = sm*(1.0f/128.0f);
    float rstd = rsqrtf(sq*(1.0f/128.0f) - mu*mu + 1e-5f);
    int c = lane * 4;
    float o0 = (g0-mu)*rstd*plnw[c]   + plnb[c];
    float o1 = (g1-mu)*rstd*plnw[c+1] + plnb[c+1];
    float o2 = (g2-mu)*rstd*plnw[c+2] + plnb[c+2];
    float o3 = (g3-mu)*rstd*plnw[c+3] + plnb[c+3];
    __half h0,l0,h1,l1,h2,l2,h3,l3;
    hsplit(o0,h0,l0); hsplit(o1,h1,l1); hsplit(o2,h2,l2); hsplit(o3,h3,l3);
    unsigned* xh = (unsigned*)xph;
    unsigned* xl = (unsigned*)xpl;
    __half2 a01 = __halves2half2(h0,h1), a23 = __halves2half2(h2,h3);
    __half2 b01 = __halves2half2(l0,l1), b23 = __halves2half2(l2,l3);
    xh[(size_t)t*64 + lane*2]     = *(unsigned*)&a01;
    xh[(size_t)t*64 + lane*2 + 1] = *(unsigned*)&a23;
    xl[(size_t)t*64 + lane*2]     = *(unsigned*)&b01;
    xl[(size_t)t*64 + lane*2 + 1] = *(unsigned*)&b23;
}

// ---------- HMMA pooled attention (K fp16, Q hi/lo) + fused finalize ----------
__global__ void __launch_bounds__(128) attn_pool_mma(
    const float* __restrict__ qs, const __half* __restrict__ kph,
    const __half* __restrict__ vph,
    const float* __restrict__ qn, const float* __restrict__ kl,
    const float* __restrict__ vl, const float* __restrict__ lt,
    const float* __restrict__ lb,
    __half* __restrict__ atth, __half* __restrict__ attl)
{
    __shared__ __half Khi[128][40];
    __shared__ __half Vt[32][132];

    const int g  = blockIdx.y;
    const int q0 = blockIdx.x * 64;
    const int tid = threadIdx.x;
    const int warp = tid >> 5;
    const int lane = tid & 31;
    const int r  = lane >> 2;
    const int c2 = (lane & 3) * 2;

    unsigned qhi[2][4], qlo[2][4];
    {
        const float* q0p = qs + ((size_t)g*Nn + q0 + warp*16 + r)*32;
        const float* q8p = q0p + 8*32;
#pragma unroll
        for (int ks = 0; ks < 2; ks++) {
            int d0 = ks*16 + c2;
            float x[4][2];
            x[0][0] = q0p[d0];   x[0][1] = q0p[d0+1];
            x[1][0] = q8p[d0];   x[1][1] = q8p[d0+1];
            x[2][0] = q0p[d0+8]; x[2][1] = q0p[d0+9];
            x[3][0] = q8p[d0+8]; x[3][1] = q8p[d0+9];
#pragma unroll
            for (int i = 0; i < 4; i++) {
                float a = x[i][0], b = x[i][1];
                float ah = __half2float(__float2half_rn(a));
                float bh = __half2float(__float2half_rn(b));
                qhi[ks][i] = h2pack(ah, bh);
                qlo[ks][i] = h2pack(a - ah, b - bh);
            }
        }
    }

    float uf[4][4];
#pragma unroll
    for (int t = 0; t < 4; t++)
#pragma unroll
        for (int i = 0; i < 4; i++) uf[t][i] = 0.f;
    float z0 = 0.f, z1 = 0.f;

    const int NCH = 25;
    for (int ch = 0; ch < NCH; ch++) {
        const int m0 = ch * 128;
        {
            int kvr = m0 + tid;
            bool ok = kvr < Nn;
            size_t rb = ((size_t)g*Nn + (ok ? kvr : 0))*32;
            const uint4* krh = (const uint4*)(kph + rb);
            uint4 z4 = make_uint4(0,0,0,0);
#pragma unroll
            for (int j = 0; j < 4; j++)
                *(uint4*)&Khi[tid][j*8] = ok ? krh[j] : z4;
            const unsigned* vr = (const unsigned*)(vph + rb);
#pragma unroll
            for (int j = 0; j < 16; j++) {
                unsigned p = ok ? vr[j] : 0u;
                __half2 hh = *(__half2*)&p;
                Vt[2*j][tid]   = hh.x;
                Vt[2*j+1][tid] = hh.y;
            }
        }
        __syncthreads();

        const int kkmax = (m0 + 128 <= Nn) ? 8 : 4;
        for (int kk = 0; kk < kkmax; kk++) {
            unsigned ea[4];
#pragma unroll
            for (int tt = 0; tt < 2; tt++) {
                int t = 2*kk + tt;
                int kv = t*8 + (lane >> 2);
                float sf[4] = {0.f, 0.f, 0.f, 0.f};
#pragma unroll
                for (int ks = 0; ks < 2; ks++) {
                    int d0 = ks*16 + c2;
                    unsigned bh0 = *(const unsigned*)&Khi[kv][d0];
                    unsigned bh1 = *(const unsigned*)&Khi[kv][d0+8];
                    mma16816(sf, qhi[ks], bh0, bh1);
                    mma16816(sf, qlo[ks], bh0, bh1);
                }
                float e0 = __expf(sf[0]);
                float e1 = __expf(sf[1]);
                float e2 = __expf(sf[2]);
                float e3 = __expf(sf[3]);
                z0 += e0 + e1;
                z1 += e2 + e3;
                ea[2*tt]   = h2pack(e0, e1);
                ea[2*tt+1] = h2pack(e2, e3);
            }
            int kv0 = kk*16 + c2;
#pragma unroll
            for (int nt = 0; nt < 4; nt++) {
                int d = nt*8 + (lane >> 2);
                unsigned b0 = *(const unsigned*)&Vt[d][kv0];
                unsigned b1 = *(const unsigned*)&Vt[d][kv0+8];
                mma16816(uf[nt], ea, b0, b1);
            }
        }
        __syncthreads();
    }

    // ---- fused finalize ----
    z0 += __shfl_xor_sync(0xffffffffu, z0, 1);
    z0 += __shfl_xor_sync(0xffffffffu, z0, 2);
    z1 += __shfl_xor_sync(0xffffffffu, z1, 1);
    z1 += __shfl_xor_sync(0xffffffffu, z1, 2);

    const int b = g >> 2, h = g & 3;
#pragma unroll
    for (int half = 0; half < 2; half++) {
        int n = q0 + warp*16 + r + half*8;
        float Zpool = half ? z1 : z0;
        int hh = n / Hs, ww = n - hh*Hs;
        const float* qp  = qs + ((size_t)g*Nn + n)*32;
        const float* qnp = qn + ((size_t)g*Nn + n)*32;
        float qsv[8], qnv[8];
#pragma unroll
        for (int nt = 0; nt < 4; nt++)
#pragma unroll
            for (int j = 0; j < 2; j++) {
                int c = nt*8 + c2 + j;
                qsv[nt*2+j] = qp[c];
                qnv[nt*2+j] = qnp[c];
            }
        float resv[8], res2v[8];
#pragma unroll
        for (int i = 0; i < 8; i++) { resv[i] = 0.f; res2v[i] = 0.f; }
        float zl = 0.f;
#pragma unroll
        for (int k = 0; k < 9; k++) {
            int h2 = hh + k/3 - 1, w2 = ww + (k%3) - 1;
            bool ok = (h2 >= 0 && h2 < Hs && w2 >= 0 && w2 < Hs);
            size_t bi = ((size_t)g*Nn + (ok ? (h2*Hs + w2) : 0))*32;
            float klv[8], vlv[8];
            float lg = 0.f, wl = 0.f;
#pragma unroll
            for (int nt = 0; nt < 4; nt++)
#pragma unroll
                for (int j = 0; j < 2; j++) {
                    int c = nt*8 + c2 + j;
                    int idx = nt*2 + j;
                    klv[idx] = ok ? kl[bi + c] : 0.f;
                    vlv[idx] = ok ? vl[bi + c] : 0.f;
                    lg += qsv[idx] * klv[idx];
                    wl += qnv[idx] * lt[(h*32 + c)*9 + k];
                }
            lg += __shfl_xor_sync(0xffffffffu, lg, 1);
            lg += __shfl_xor_sync(0xffffffffu, lg, 2);
            wl += __shfl_xor_sync(0xffffffffu, wl, 1);
            wl += __shfl_xor_sync(0xffffffffu, wl, 2);
            float e = __expf(lg);
            zl += e;
            float w2l = wl + lb[h*9 + k];
#pragma unroll
            for (int i = 0; i < 8; i++) {
                resv[i]  += e   * vlv[i];
                res2v[i] += w2l * vlv[i];
            }
        }
        float Zf = Zpool + zl;
        float rZ = 1.0f / Zf;
#pragma unroll
        for (int nt = 0; nt < 4; nt++)
#pragma unroll
            for (int j = 0; j < 2; j++) {
                int c = nt*8 + c2 + j;
                int idx = nt*2 + j;
                float o = (uf[nt][half*2 + j] + resv[idx]) * rZ + res2v[idx];
                size_t oi = ((size_t)(b*Nn + n))*128 + h*32 + c;
                __half oh, ol; hsplit(o, oh, ol);
                atth[oi] = oh; attl[oi] = ol;
            }
    }
}

// ---------- depthwise 3x3 + gelu * v -> fp16 hi/lo (padded stride) ----------
__global__ void dwconv_kernel(const float* __restrict__ f1, const float* __restrict__ dww,
                              const float* __restrict__ dwb,
                              __half* __restrict__ gbh, __half* __restrict__ gbl)
{
    int t = blockIdx.x;
    int c = threadIdx.x;
    if (c >= LDF) return;
    size_t oi = (size_t)t*LDF + c;
    if (c >= HFn) { gbh[oi] = __float2half(0.f); gbl[oi] = __float2half(0.f); return; }
    int b = t / Nn, n = t - b*Nn;
    int hh = n / Hs, ww = n - hh*Hs;
    float acc = dwb[c];
#pragma unroll
    for (int k = 0; k < 9; k++) {
        int h2 = hh + k/3 - 1, w2 = ww + (k%3) - 1;
        if (h2 < 0 || h2 >= Hs || w2 < 0 || w2 >= Hs) continue;
        acc += f1[((size_t)(b*Nn + h2*Hs + w2))*682 + c] * dww[c*9 + k];
    }
    float v = f1[(size_t)t*682 + 341 + c];
    float o = gelu_exact(acc) * v;
    __half oh, ol; hsplit(o, oh, ol);
    gbh[oi] = oh; gbl[oi] = ol;
}

extern "C" void kernel_launch(void* const* d_in, const int* in_sizes, int n_in,
                              void* d_out, int out_size)
{
    const float* x      = (const float*)d_in[0];
    const float* n1w    = (const float*)d_in[1];
    const float* n1b    = (const float*)d_in[2];
    const float* q_w    = (const float*)d_in[3];
    const float* q_b    = (const float*)d_in[4];
    const float* kv_w   = (const float*)d_in[5];
    const float* kv_b   = (const float*)d_in[6];
    const float* temp   = (const float*)d_in[7];
    const float* qe     = (const float*)d_in[8];
    const float* lt     = (const float*)d_in[9];
    const float* lb     = (const float*)d_in[10];
    const float* sr_w   = (const float*)d_in[11];
    const float* sr_b   = (const float*)d_in[12];
    const float* plnw   = (const float*)d_in[13];
    const float* plnb   = (const float*)d_in[14];
    const float* proj_w = (const float*)d_in[15];
    const float* proj_b = (const float*)d_in[16];
    const float* n2w    = (const float*)d_in[17];
    const float* n2b    = (const float*)d_in[18];
    const float* fc1_w  = (const float*)d_in[19];
    const float* fc1_b  = (const float*)d_in[20];
    const float* dw_w   = (const float*)d_in[21];
    const float* dw_b   = (const float*)d_in[22];
    const float* fc2_w  = (const float*)d_in[23];
    const float* fc2_b  = (const float*)d_in[24];
    float* out = (float*)d_out;

    float *t1, *qsb, *qnb, *klb, *vlb, *x2b, *f1b, *b512;
    __half *yh, *yl, *xph, *xpl, *atth, *attl, *y2h, *y2l, *kph, *vphh, *gbh, *gbl, *wh, *wl;
    cudaGetSymbolAddress((void**)&t1,   g_tmp1);
    cudaGetSymbolAddress((void**)&qsb,  g_qs);
    cudaGetSymbolAddress((void**)&qnb,  g_qn);
    cudaGetSymbolAddress((void**)&klb,  g_kl);
    cudaGetSymbolAddress((void**)&vlb,  g_vl);
    cudaGetSymbolAddress((void**)&x2b,  g_x2);
    cudaGetSymbolAddress((void**)&f1b,  g_f1);
    cudaGetSymbolAddress((void**)&b512, g_b512);
    cudaGetSymbolAddress((void**)&yh,   g_yh);
    cudaGetSymbolAddress((void**)&yl,   g_yl);
    cudaGetSymbolAddress((void**)&xph,  g_xph);
    cudaGetSymbolAddress((void**)&xpl,  g_xpl);
    cudaGetSymbolAddress((void**)&atth, g_atth);
    cudaGetSymbolAddress((void**)&attl, g_attl);
    cudaGetSymbolAddress((void**)&y2h,  g_y2h);
    cudaGetSymbolAddress((void**)&y2l,  g_y2l);
    cudaGetSymbolAddress((void**)&kph,  g_kph);
    cudaGetSymbolAddress((void**)&vphh, g_vph);
    cudaGetSymbolAddress((void**)&gbh,  g_gbh);
    cudaGetSymbolAddress((void**)&gbl,  g_gbl);
    cudaGetSymbolAddress((void**)&wh,   g_wh);
    cudaGetSymbolAddress((void**)&wl,   g_wl);

    cvt_all<<<840, 256>>>(q_w, kv_w, sr_w, proj_w, fc1_w, fc2_w, q_b, kv_b, sr_b, wh, wl, b512);

    ln_kernel<<<TOK/8, 256>>>(x, n1w, n1b, yh, yl);
    hgemm2<<<dim3(8,98), 128>>>(yh, yl, wh+OQ, wl+OQ, 128, b512, t1, 512, 512, 0, nullptr);
    pointwise1<<<TOK/8, 256>>>(t1, temp, qe, plnw, plnb, qsb, qnb, klb, vlb, xph, xpl);
    hgemm_kv<<<dim3(4,98), 128>>>(xph, xpl, wh+OKV, wl+OKV, kv_b, kph, vphh);
    attn_pool_mma<<<dim3(49,8), 128>>>(qsb, kph, vphh, qnb, klb, vlb, lt, lb, atth, attl);
    hgemm2<<<dim3(2,98), 128>>>(atth, attl, wh+OPJ, wl+OPJ, 128, proj_b, x2b, 128, 128, 1, x);
    ln_kernel<<<TOK/8, 256>>>(x2b, n2w, n2b, y2h, y2l);
    hgemm2<<<dim3(11,98), 128>>>(y2h, y2l, wh+OF1, wl+OF1, 128, fc1_b, f1b, 682, 682, 0, nullptr);
    dwconv_kernel<<<TOK, LDF>>>(f1b, dw_w, dw_b, gbh, gbl);
    hgemm2<<<dim3(2,98), 128>>>(gbh, gbl, wh+OF2, wl+OF2, LDF, fc2_b, out, 128, 128, 2, x2b);
}

// round 10
// speedup vs baseline: 1.2809x; 1.0133x over previous
#include <cuda_runtime.h>
#include <cuda_fp16.h>
#include <math.h>

#define Bn   2
#define Cn   128
#define Hs   56
#define Nn   3136
#define NHn  4
#define HFn  341
#define TOK  (Bn*Nn)
#define LDF  352

// fp32 scratch
__device__ __align__(256) float g_tmp1[TOK*512];
__device__ __align__(256) float g_qs [8*Nn*32];
__device__ __align__(256) float g_qn [8*Nn*32];
__device__ __align__(256) float g_kl [8*Nn*32];
__device__ __align__(256) float g_vl [8*Nn*32];
__device__ __align__(256) float g_x2 [TOK*Cn];
__device__ __align__(256) float g_b512[512];
// half scratch
__device__ __align__(256) __half g_f1h[TOK*682];
__device__ __align__(256) __half g_yh [TOK*Cn], g_yl [TOK*Cn];
__device__ __align__(256) __half g_xph[TOK*Cn], g_xpl[TOK*Cn];
__device__ __align__(256) __half g_atth[TOK*Cn], g_attl[TOK*Cn];
__device__ __align__(256) __half g_y2h[TOK*Cn], g_y2l[TOK*Cn];
__device__ __align__(256) __half g_kph[TOK*Cn];
__device__ __align__(256) __half g_vph[TOK*Cn];
__device__ __align__(256) __half g_gbh[TOK*LDF], g_gbl[TOK*LDF];
// converted weights pool
#define OQ   0
#define OKV  16384
#define OSR  49152
#define OPJ  65536
#define OF1  81920
#define OF2  169216
#define WTOT 214272
__device__ __align__(256) __half g_wh[WTOT], g_wl[WTOT];

__device__ __forceinline__ float gelu_exact(float x) {
    return 0.5f * x * (1.0f + erff(x * 0.70710678118654752f));
}
__device__ __forceinline__ unsigned h2pack(float a, float b) {
    __half2 h = __floats2half2_rn(a, b);
    return *(unsigned*)&h;
}
__device__ __forceinline__ void hsplit(float v, __half& hi, __half& lo) {
    hi = __float2half_rn(v);
    lo = __float2half_rn(v - __half2float(hi));
}
__device__ __forceinline__ void mma16816(float* c, const unsigned* a, unsigned b0, unsigned b1) {
    asm volatile("mma.sync.aligned.m16n8k16.row.col.f32.f16.f16.f32 "
        "{%0,%1,%2,%3}, {%4,%5,%6,%7}, {%8,%9}, {%0,%1,%2,%3};"
        : "+f"(c[0]), "+f"(c[1]), "+f"(c[2]), "+f"(c[3])
        : "r"(a[0]), "r"(a[1]), "r"(a[2]), "r"(a[3]), "r"(b0), "r"(b1));
}

// ---------- single-launch weight conversion + fused bias ----------
__global__ void cvt_all(const float* __restrict__ q_w, const float* __restrict__ kv_w,
                        const float* __restrict__ sr_w, const float* __restrict__ proj_w,
                        const float* __restrict__ fc1_w, const float* __restrict__ fc2_w,
                        const float* __restrict__ q_b, const float* __restrict__ kv_b,
                        const float* __restrict__ sr_b,
                        __half* __restrict__ wh, __half* __restrict__ wl,
                        float* __restrict__ b512)
{
    int i = blockIdx.x * 256 + threadIdx.x;
    if (i < WTOT) {
        float v;
        if      (i < OKV) v = q_w[i];
        else if (i < OSR) v = kv_w[i - OKV];
        else if (i < OPJ) v = sr_w[i - OSR];
        else if (i < OF1) v = proj_w[i - OPJ];
        else if (i < OF2) v = fc1_w[i - OF1];
        else {
            int j = i - OF2, r = j / LDF, c = j - r * LDF;
            v = (c < HFn) ? fc2_w[r * HFn + c] : 0.f;
        }
        __half h, l; hsplit(v, h, l);
        wh[i] = h; wl[i] = l;
    } else if (i < WTOT + 512) {
        int j = i - WTOT;
        b512[j] = (j < 128) ? q_b[j] : (j < 384) ? kv_b[j - 128] : sr_b[j - 384];
    }
}

// ---------- LayerNorm (channel-major in) -> fp16 hi/lo token-major ----------
__global__ void ln_kernel(const float* __restrict__ in, const float* __restrict__ w,
                          const float* __restrict__ bvec,
                          __half* __restrict__ oh, __half* __restrict__ ol)
{
    int warp = blockIdx.x * 8 + (threadIdx.x >> 5);
    int lane = threadIdx.x & 31;
    int bb = warp / Nn, n = warp - bb * Nn;
    const float* p = in + (size_t)bb * (Cn*Nn) + n;
    float v[4], s = 0.f, s2 = 0.f;
#pragma unroll
    for (int pp = 0; pp < 2; pp++) {
        int c0 = 2*lane + 64*pp;
        v[2*pp]   = p[(size_t)c0 * Nn];
        v[2*pp+1] = p[(size_t)(c0+1) * Nn];
        s += v[2*pp] + v[2*pp+1];
        s2 += v[2*pp]*v[2*pp] + v[2*pp+1]*v[2*pp+1];
    }
#pragma unroll
    for (int d = 1; d < 32; d <<= 1) {
        s  += __shfl_xor_sync(0xffffffffu, s,  d);
        s2 += __shfl_xor_sync(0xffffffffu, s2, d);
    }
    float mu = s * (1.0f/128.0f);
    float rstd = rsqrtf(s2*(1.0f/128.0f) - mu*mu + 1e-5f);
    unsigned* ohp = (unsigned*)oh;
    unsigned* olp = (unsigned*)ol;
#pragma unroll
    for (int pp = 0; pp < 2; pp++) {
        int c0 = 2*lane + 64*pp;
        float a = (v[2*pp]  -mu)*rstd*w[c0]   + bvec[c0];
        float b = (v[2*pp+1]-mu)*rstd*w[c0+1] + bvec[c0+1];
        __half ah, al_, bh, bl; hsplit(a, ah, al_); hsplit(b, bh, bl);
        __half2 hh = __halves2half2(ah, bh), ll = __halves2half2(al_, bl);
        ohp[warp*64 + lane + 32*pp] = *(unsigned*)&hh;
        olp[warp*64 + lane + 32*pp] = *(unsigned*)&ll;
    }
}

// ---------- HMMA GEMM, gmem-direct fragments ----------
// mode 0: fp32 out; 1: fp32 +res; 2: transposed channel-major +res; 3: fp16 out
__global__ void __launch_bounds__(128) hgemm2(
    const __half* __restrict__ Ah, const __half* __restrict__ Al,
    const __half* __restrict__ Wh, const __half* __restrict__ Wl, int ld,
    const float* __restrict__ bias, float* __restrict__ out,
    int ldo, int Nout, int mode, const float* __restrict__ res)
{
    const int m0 = blockIdx.y * 64;
    const int n0 = blockIdx.x * 64;
    const int warp = threadIdx.x >> 5;
    const int lane = threadIdx.x & 31;
    const int r  = lane >> 2;
    const int c2 = (lane & 3) * 2;

    float acc[8][4];
#pragma unroll
    for (int t = 0; t < 8; t++)
#pragma unroll
        for (int i = 0; i < 4; i++) acc[t][i] = 0.f;

    const int row1 = m0 + warp*16 + r;
    const __half* a1h = Ah + (size_t)row1 * ld;
    const __half* a2h = a1h + (size_t)8 * ld;
    const __half* a1l = Al + (size_t)row1 * ld;
    const __half* a2l = a1l + (size_t)8 * ld;

    const int nr = n0 + (lane >> 2);
    const __half* wrow[8];
    const __half* wrol[8];
#pragma unroll
    for (int nt = 0; nt < 8; nt++) {
        int n = nr + nt*8;
        int nc = (n < Nout) ? n : (Nout - 1);
        wrow[nt] = Wh + (size_t)nc * ld;
        wrol[nt] = Wl + (size_t)nc * ld;
    }

    const int KC = ld / 32;
    for (int kc = 0; kc < KC; kc++) {
#pragma unroll
        for (int ks = 0; ks < 2; ks++) {
            int d0 = kc*32 + ks*16 + c2;
            unsigned ah[4], al[4];
            ah[0] = *(const unsigned*)&a1h[d0];
            ah[1] = *(const unsigned*)&a2h[d0];
            ah[2] = *(const unsigned*)&a1h[d0+8];
            ah[3] = *(const unsigned*)&a2h[d0+8];
            al[0] = *(const unsigned*)&a1l[d0];
            al[1] = *(const unsigned*)&a2l[d0];
            al[2] = *(const unsigned*)&a1l[d0+8];
            al[3] = *(const unsigned*)&a2l[d0+8];
#pragma unroll
            for (int nt = 0; nt < 8; nt++) {
                unsigned bh0 = *(const unsigned*)&wrow[nt][d0];
                unsigned bh1 = *(const unsigned*)&wrow[nt][d0+8];
                unsigned bl0 = *(const unsigned*)&wrol[nt][d0];
                unsigned bl1 = *(const unsigned*)&wrol[nt][d0+8];
                mma16816(acc[nt], ah, bh0, bh1);
                mma16816(acc[nt], al, bh0, bh1);
                mma16816(acc[nt], ah, bl0, bl1);
            }
        }
    }

    int m1 = row1, m2 = row1 + 8;
#pragma unroll
    for (int nt = 0; nt < 8; nt++) {
        int n = n0 + nt*8 + c2;
#pragma unroll
        for (int j = 0; j < 2; j++) {
            int nn = n + j;
            if (nn >= Nout) continue;
            float v1 = acc[nt][j]   + bias[nn];
            float v2 = acc[nt][2+j] + bias[nn];
            if (mode == 0) {
                out[(size_t)m1*ldo + nn] = v1;
                out[(size_t)m2*ldo + nn] = v2;
            } else if (mode == 1) {
                size_t i1 = (size_t)m1*ldo + nn, i2 = (size_t)m2*ldo + nn;
                out[i1] = v1 + res[i1];
                out[i2] = v2 + res[i2];
            } else if (mode == 2) {
                int b1 = m1 / Nn, t1i = m1 - b1*Nn;
                int b2 = m2 / Nn, t2i = m2 - b2*Nn;
                size_t i1 = ((size_t)b1*Cn + nn)*Nn + t1i;
                size_t i2 = ((size_t)b2*Cn + nn)*Nn + t2i;
                out[i1] = v1 + res[i1];
                out[i2] = v2 + res[i2];
            } else {
                __half* oh = (__half*)out;
                oh[(size_t)m1*ldo + nn] = __float2half_rn(v1);
                oh[(size_t)m2*ldo + nn] = __float2half_rn(v2);
            }
        }
    }
}

// ---------- HMMA kv GEMM with fused l2norm/split epilogue -> kph/vph fp16 ----------
__global__ void __launch_bounds__(128) hgemm_kv(
    const __half* __restrict__ Ah, const __half* __restrict__ Al,
    const __half* __restrict__ Wh, const __half* __restrict__ Wl,
    const float* __restrict__ bias,
    __half* __restrict__ kph, __half* __restrict__ vph)
{
    const int m0 = blockIdx.y * 64;
    const int n0 = blockIdx.x * 64;
    const int warp = threadIdx.x >> 5;
    const int lane = threadIdx.x & 31;
    const int r  = lane >> 2;
    const int c2 = (lane & 3) * 2;
    const int ld = 128;

    float acc[8][4];
#pragma unroll
    for (int t = 0; t < 8; t++)
#pragma unroll
        for (int i = 0; i < 4; i++) acc[t][i] = 0.f;

    const int row1 = m0 + warp*16 + r;
    const __half* a1h = Ah + (size_t)row1 * ld;
    const __half* a2h = a1h + (size_t)8 * ld;
    const __half* a1l = Al + (size_t)row1 * ld;
    const __half* a2l = a1l + (size_t)8 * ld;

    const int nr = n0 + (lane >> 2);
    const __half* wrow[8];
    const __half* wrol[8];
#pragma unroll
    for (int nt = 0; nt < 8; nt++) {
        wrow[nt] = Wh + (size_t)(nr + nt*8) * ld;
        wrol[nt] = Wl + (size_t)(nr + nt*8) * ld;
    }

#pragma unroll
    for (int kc = 0; kc < 4; kc++) {
#pragma unroll
        for (int ks = 0; ks < 2; ks++) {
            int d0 = kc*32 + ks*16 + c2;
            unsigned ah[4], al[4];
            ah[0] = *(const unsigned*)&a1h[d0];
            ah[1] = *(const unsigned*)&a2h[d0];
            ah[2] = *(const unsigned*)&a1h[d0+8];
            ah[3] = *(const unsigned*)&a2h[d0+8];
            al[0] = *(const unsigned*)&a1l[d0];
            al[1] = *(const unsigned*)&a2l[d0];
            al[2] = *(const unsigned*)&a1l[d0+8];
            al[3] = *(const unsigned*)&a2l[d0+8];
#pragma unroll
            for (int nt = 0; nt < 8; nt++) {
                unsigned bh0 = *(const unsigned*)&wrow[nt][d0];
                unsigned bh1 = *(const unsigned*)&wrow[nt][d0+8];
                unsigned bl0 = *(const unsigned*)&wrol[nt][d0];
                unsigned bl1 = *(const unsigned*)&wrol[nt][d0+8];
                mma16816(acc[nt], ah, bh0, bh1);
                mma16816(acc[nt], al, bh0, bh1);
                mma16816(acc[nt], ah, bl0, bl1);
            }
        }
    }

#pragma unroll
    for (int half = 0; half < 2; half++) {
        int m = row1 + half*8;
        int bb = m / Nn, n = m - bb*Nn;
        float vals[16];
#pragma unroll
        for (int nt = 0; nt < 8; nt++)
#pragma unroll
            for (int j = 0; j < 2; j++)
                vals[nt*2+j] = acc[nt][half*2+j] + bias[n0 + nt*8 + c2 + j];
        if (n0 < 128) {
            float se = 0.f, so = 0.f;
#pragma unroll
            for (int i = 0; i < 8; i++) { se += vals[i]*vals[i]; so += vals[8+i]*vals[8+i]; }
            se += __shfl_xor_sync(0xffffffffu, se, 1);
            se += __shfl_xor_sync(0xffffffffu, se, 2);
            so += __shfl_xor_sync(0xffffffffu, so, 1);
            so += __shfl_xor_sync(0xffffffffu, so, 2);
            float ke = 1.0f / fmaxf(sqrtf(se), 1e-12f);
            float ko = 1.0f / fmaxf(sqrtf(so), 1e-12f);
#pragma unroll
            for (int nt = 0; nt < 8; nt++) {
                int col = n0 + nt*8 + c2;
                int head = col >> 5;
                float sc = (nt < 4) ? ke : ko;
                __half2 hv = __floats2half2_rn(vals[nt*2]*sc, vals[nt*2+1]*sc);
                *(__half2*)&kph[((size_t)(bb*NHn + head)*Nn + n)*32 + (col & 31)] = hv;
            }
        } else {
#pragma unroll
            for (int nt = 0; nt < 8; nt++) {
                int col = n0 - 128 + nt*8 + c2;
                int head = col >> 5;
                __half2 hv = __floats2half2_rn(vals[nt*2], vals[nt*2+1]);
                *(__half2*)&vph[((size_t)(bb*NHn + head)*Nn + n)*32 + (col & 31)] = hv;
            }
        }
    }
}

// ---------- pointwise after fused QKVSR GEMM ----------
__global__ void pointwise1(const float* __restrict__ tmp1, const float* __restrict__ temp,
                           const float* __restrict__ qe, const float* __restrict__ plnw,
                           const float* __restrict__ plnb,
                           float* __restrict__ qs, float* __restrict__ qn,
                           float* __restrict__ kl, float* __restrict__ vl,
                           __half* __restrict__ xph, __half* __restrict__ xpl)
{
    int t = blockIdx.x * 8 + (threadIdx.x >> 5);
    int lane = threadIdx.x & 31;
    int bb = t / Nn, n = t - bb * Nn;
    int h = lane >> 3;
    int g = bb * NHn + h;
    const float4* row = (const float4*)(tmp1 + (size_t)t * 512);
    size_t ho = ((size_t)g * Nn + n) * 8 + (lane & 7);

    float4 q4 = row[lane];
    float ss = q4.x*q4.x + q4.y*q4.y + q4.z*q4.z + q4.w*q4.w;
    ss += __shfl_xor_sync(0xffffffffu, ss, 1);
    ss += __shfl_xor_sync(0xffffffffu, ss, 2);
    ss += __shfl_xor_sync(0xffffffffu, ss, 4);
    float inv = 1.0f / fmaxf(sqrtf(ss), 1e-12f);
    float4 qn4 = make_float4(q4.x*inv, q4.y*inv, q4.z*inv, q4.w*inv);
    float tv = temp[h];
    float sp = log1pf(__expf(tv));
    float4 qe4 = ((const float4*)qe)[h*8 + (lane & 7)];
    ((float4*)qn)[ho] = qn4;
    ((float4*)qs)[ho] = make_float4((qn4.x+qe4.x)*sp, (qn4.y+qe4.y)*sp,
                                    (qn4.z+qe4.z)*sp, (qn4.w+qe4.w)*sp);

    float4 k4 = row[32 + lane];
    float ks = k4.x*k4.x + k4.y*k4.y + k4.z*k4.z + k4.w*k4.w;
    ks += __shfl_xor_sync(0xffffffffu, ks, 1);
    ks += __shfl_xor_sync(0xffffffffu, ks, 2);
    ks += __shfl_xor_sync(0xffffffffu, ks, 4);
    float ki = 1.0f / fmaxf(sqrtf(ks), 1e-12f);
    ((float4*)kl)[ho] = make_float4(k4.x*ki, k4.y*ki, k4.z*ki, k4.w*ki);
    ((float4*)vl)[ho] = row[64 + lane];

    float4 s4 = row[96 + lane];
    float g0 = gelu_exact(s4.x), g1 = gelu_exact(s4.y);
    float g2 = gelu_exact(s4.z), g3 = gelu_exact(s4.w);
    float sm = g0+g1+g2+g3;
    float sq = g0*g0+g1*g1+g2*g2+g3*g3;
#pragma unroll
    for (int d = 1; d < 32; d <<= 1) {
        sm += __shfl_xor_sync(0xffffffffu, sm, d);
        sq += __shfl_xor_sync(0xffffffffu, sq, d);
    }
    float mu = sm*(1.0f/128.0f);
    float rstd = rsqrtf(sq*(1.0f/128.0f) - mu*mu + 1e-5f);
    int c = lane * 4;
    float o0 = (g0-mu)*rstd*plnw[c]   + plnb[c];
    float o1 = (g1-mu)*rstd*plnw[c+1] + plnb[c+1];
    float o2 = (g2-mu)*rstd*plnw[c+2] + plnb[c+2];
    float o3 = (g3-mu)*rstd*plnw[c+3] + plnb[c+3];
    __half h0,l0,h1,l1,h2,l2,h3,l3;
    hsplit(o0,h0,l0); hsplit(o1,h1,l1); hsplit(o2,h2,l2); hsplit(o3,h3,l3);
    unsigned* xh = (unsigned*)xph;
    unsigned* xl = (unsigned*)xpl;
    __half2 a01 = __halves2half2(h0,h1), a23 = __halves2half2(h2,h3);
    __half2 b01 = __halves2half2(l0,l1), b23 = __halves2half2(l2,l3);
    xh[(size_t)t*64 + lane*2]     = *(unsigned*)&a01;
    xh[(size_t)t*64 + lane*2 + 1] = *(unsigned*)&a23;
    xl[(size_t)t*64 + lane*2]     = *(unsigned*)&b01;
    xl[(size_t)t*64 + lane*2 + 1] = *(unsigned*)&b23;
}

// ---------- HMMA pooled attention (Q,K single fp16) + fused finalize ----------
__global__ void __launch_bounds__(128) attn_pool_mma(
    const float* __restrict__ qs, const __half* __restrict__ kph,
    const __half* __restrict__ vph,
    const float* __restrict__ qn, const float* __restrict__ kl,
    const float* __restrict__ vl, const float* __restrict__ lt,
    const float* __restrict__ lb,
    __half* __restrict__ atth, __half* __restrict__ attl)
{
    __shared__ __half Khi[128][40];
    __shared__ __half Vt[32][132];

    const int g  = blockIdx.y;
    const int q0 = blockIdx.x * 64;
    const int tid = threadIdx.x;
    const int warp = tid >> 5;
    const int lane = tid & 31;
    const int r  = lane >> 2;
    const int c2 = (lane & 3) * 2;

    unsigned qhi[2][4];
    {
        const float* q0p = qs + ((size_t)g*Nn + q0 + warp*16 + r)*32;
        const float* q8p = q0p + 8*32;
#pragma unroll
        for (int ks = 0; ks < 2; ks++) {
            int d0 = ks*16 + c2;
            qhi[ks][0] = h2pack(q0p[d0],   q0p[d0+1]);
            qhi[ks][1] = h2pack(q8p[d0],   q8p[d0+1]);
            qhi[ks][2] = h2pack(q0p[d0+8], q0p[d0+9]);
            qhi[ks][3] = h2pack(q8p[d0+8], q8p[d0+9]);
        }
    }

    float uf[4][4];
#pragma unroll
    for (int t = 0; t < 4; t++)
#pragma unroll
        for (int i = 0; i < 4; i++) uf[t][i] = 0.f;
    float z0 = 0.f, z1 = 0.f;

    const int NCH = 25;
    for (int ch = 0; ch < NCH; ch++) {
        const int m0 = ch * 128;
        {
            int kvr = m0 + tid;
            bool ok = kvr < Nn;
            size_t rb = ((size_t)g*Nn + (ok ? kvr : 0))*32;
            const uint4* krh = (const uint4*)(kph + rb);
            uint4 z4 = make_uint4(0,0,0,0);
#pragma unroll
            for (int j = 0; j < 4; j++)
                *(uint4*)&Khi[tid][j*8] = ok ? krh[j] : z4;
            const unsigned* vr = (const unsigned*)(vph + rb);
#pragma unroll
            for (int j = 0; j < 16; j++) {
                unsigned p = ok ? vr[j] : 0u;
                __half2 hh = *(__half2*)&p;
                Vt[2*j][tid]   = hh.x;
                Vt[2*j+1][tid] = hh.y;
            }
        }
        __syncthreads();

        const int kkmax = (m0 + 128 <= Nn) ? 8 : 4;
        for (int kk = 0; kk < kkmax; kk++) {
            unsigned ea[4];
#pragma unroll
            for (int tt = 0; tt < 2; tt++) {
                int t = 2*kk + tt;
                int kv = t*8 + (lane >> 2);
                float sf[4] = {0.f, 0.f, 0.f, 0.f};
#pragma unroll
                for (int ks = 0; ks < 2; ks++) {
                    int d0 = ks*16 + c2;
                    unsigned bh0 = *(const unsigned*)&Khi[kv][d0];
                    unsigned bh1 = *(const unsigned*)&Khi[kv][d0+8];
                    mma16816(sf, qhi[ks], bh0, bh1);
                }
                float e0 = __expf(sf[0]);
                float e1 = __expf(sf[1]);
                float e2 = __expf(sf[2]);
                float e3 = __expf(sf[3]);
                z0 += e0 + e1;
                z1 += e2 + e3;
                ea[2*tt]   = h2pack(e0, e1);
                ea[2*tt+1] = h2pack(e2, e3);
            }
            int kv0 = kk*16 + c2;
#pragma unroll
            for (int nt = 0; nt < 4; nt++) {
                int d = nt*8 + (lane >> 2);
                unsigned b0 = *(const unsigned*)&Vt[d][kv0];
                unsigned b1 = *(const unsigned*)&Vt[d][kv0+8];
                mma16816(uf[nt], ea, b0, b1);
            }
        }
        __syncthreads();
    }

    // ---- fused finalize ----
    z0 += __shfl_xor_sync(0xffffffffu, z0, 1);
    z0 += __shfl_xor_sync(0xffffffffu, z0, 2);
    z1 += __shfl_xor_sync(0xffffffffu, z1, 1);
    z1 += __shfl_xor_sync(0xffffffffu, z1, 2);

    const int b = g >> 2, h = g & 3;
#pragma unroll
    for (int half = 0; half < 2; half++) {
        int n = q0 + warp*16 + r + half*8;
        float Zpool = half ? z1 : z0;
        int hh = n / Hs, ww = n - hh*Hs;
        const float* qp  = qs + ((size_t)g*Nn + n)*32;
        const float* qnp = qn + ((size_t)g*Nn + n)*32;
        float qsv[8], qnv[8];
#pragma unroll
        for (int nt = 0; nt < 4; nt++)
#pragma unroll
            for (int j = 0; j < 2; j++) {
                int c = nt*8 + c2 + j;
                qsv[nt*2+j] = qp[c];
                qnv[nt*2+j] = qnp[c];
            }
        float resv[8], res2v[8];
#pragma unroll
        for (int i = 0; i < 8; i++) { resv[i] = 0.f; res2v[i] = 0.f; }
        float zl = 0.f;
#pragma unroll
        for (int k = 0; k < 9; k++) {
            int h2 = hh + k/3 - 1, w2 = ww + (k%3) - 1;
            bool ok = (h2 >= 0 && h2 < Hs && w2 >= 0 && w2 < Hs);
            size_t bi = ((size_t)g*Nn + (ok ? (h2*Hs + w2) : 0))*32;
            float klv[8], vlv[8];
            float lg = 0.f, wl = 0.f;
#pragma unroll
            for (int nt = 0; nt < 4; nt++)
#pragma unroll
                for (int j = 0; j < 2; j++) {
                    int c = nt*8 + c2 + j;
                    int idx = nt*2 + j;
                    klv[idx] = ok ? kl[bi + c] : 0.f;
                    vlv[idx] = ok ? vl[bi + c] : 0.f;
                    lg += qsv[idx] * klv[idx];
                    wl += qnv[idx] * lt[(h*32 + c)*9 + k];
                }
            lg += __shfl_xor_sync(0xffffffffu, lg, 1);
            lg += __shfl_xor_sync(0xffffffffu, lg, 2);
            wl += __shfl_xor_sync(0xffffffffu, wl, 1);
            wl += __shfl_xor_sync(0xffffffffu, wl, 2);
            float e = __expf(lg);
            zl += e;
            float w2l = wl + lb[h*9 + k];
#pragma unroll
            for (int i = 0; i < 8; i++) {
                resv[i]  += e   * vlv[i];
                res2v[i] += w2l * vlv[i];
            }
        }
        float Zf = Zpool + zl;
        float rZ = 1.0f / Zf;
#pragma unroll
        for (int nt = 0; nt < 4; nt++)
#pragma unroll
            for (int j = 0; j < 2; j++) {
                int c = nt*8 + c2 + j;
                int idx = nt*2 + j;
                float o = (uf[nt][half*2 + j] + resv[idx]) * rZ + res2v[idx];
                size_t oi = ((size_t)(b*Nn + n))*128 + h*32 + c;
                __half oh, ol; hsplit(o, oh, ol);
                atth[oi] = oh; attl[oi] = ol;
            }
    }
}

// ---------- depthwise 3x3 + gelu * v (fp16 f1) -> fp16 hi/lo ----------
__global__ void dwconv_kernel(const __half* __restrict__ f1, const float* __restrict__ dww,
                              const float* __restrict__ dwb,
                              __half* __restrict__ gbh, __half* __restrict__ gbl)
{
    int t = blockIdx.x;
    int c = threadIdx.x;
    if (c >= LDF) return;
    size_t oi = (size_t)t*LDF + c;
    if (c >= HFn) { gbh[oi] = __float2half(0.f); gbl[oi] = __float2half(0.f); return; }
    int b = t / Nn, n = t - b*Nn;
    int hh = n / Hs, ww = n - hh*Hs;
    float acc = dwb[c];
#pragma unroll
    for (int k = 0; k < 9; k++) {
        int h2 = hh + k/3 - 1, w2 = ww + (k%3) - 1;
        if (h2 < 0 || h2 >= Hs || w2 < 0 || w2 >= Hs) continue;
        acc += __half2float(f1[((size_t)(b*Nn + h2*Hs + w2))*682 + c]) * dww[c*9 + k];
    }
    float v = __half2float(f1[(size_t)t*682 + 341 + c]);
    float o = gelu_exact(acc) * v;
    __half oh, ol; hsplit(o, oh, ol);
    gbh[oi] = oh; gbl[oi] = ol;
}

extern "C" void kernel_launch(void* const* d_in, const int* in_sizes, int n_in,
                              void* d_out, int out_size)
{
    const float* x      = (const float*)d_in[0];
    const float* n1w    = (const float*)d_in[1];
    const float* n1b    = (const float*)d_in[2];
    const float* q_w    = (const float*)d_in[3];
    const float* q_b    = (const float*)d_in[4];
    const float* kv_w   = (const float*)d_in[5];
    const float* kv_b   = (const float*)d_in[6];
    const float* temp   = (const float*)d_in[7];
    const float* qe     = (const float*)d_in[8];
    const float* lt     = (const float*)d_in[9];
    const float* lb     = (const float*)d_in[10];
    const float* sr_w   = (const float*)d_in[11];
    const float* sr_b   = (const float*)d_in[12];
    const float* plnw   = (const float*)d_in[13];
    const float* plnb   = (const float*)d_in[14];
    const float* proj_w = (const float*)d_in[15];
    const float* proj_b = (const float*)d_in[16];
    const float* n2w    = (const float*)d_in[17];
    const float* n2b    = (const float*)d_in[18];
    const float* fc1_w  = (const float*)d_in[19];
    const float* fc1_b  = (const float*)d_in[20];
    const float* dw_w   = (const float*)d_in[21];
    const float* dw_b   = (const float*)d_in[22];
    const float* fc2_w  = (const float*)d_in[23];
    const float* fc2_b  = (const float*)d_in[24];
    float* out = (float*)d_out;

    float *t1, *qsb, *qnb, *klb, *vlb, *x2b, *b512;
    __half *f1hb, *yh, *yl, *xph, *xpl, *atth, *attl, *y2h, *y2l, *kph, *vphh, *gbh, *gbl, *wh, *wl;
    cudaGetSymbolAddress((void**)&t1,   g_tmp1);
    cudaGetSymbolAddress((void**)&qsb,  g_qs);
    cudaGetSymbolAddress((void**)&qnb,  g_qn);
    cudaGetSymbolAddress((void**)&klb,  g_kl);
    cudaGetSymbolAddress((void**)&vlb,  g_vl);
    cudaGetSymbolAddress((void**)&x2b,  g_x2);
    cudaGetSymbolAddress((void**)&b512, g_b512);
    cudaGetSymbolAddress((void**)&f1hb, g_f1h);
    cudaGetSymbolAddress((void**)&yh,   g_yh);
    cudaGetSymbolAddress((void**)&yl,   g_yl);
    cudaGetSymbolAddress((void**)&xph,  g_xph);
    cudaGetSymbolAddress((void**)&xpl,  g_xpl);
    cudaGetSymbolAddress((void**)&atth, g_atth);
    cudaGetSymbolAddress((void**)&attl, g_attl);
    cudaGetSymbolAddress((void**)&y2h,  g_y2h);
    cudaGetSymbolAddress((void**)&y2l,  g_y2l);
    cudaGetSymbolAddress((void**)&kph,  g_kph);
    cudaGetSymbolAddress((void**)&vphh, g_vph);
    cudaGetSymbolAddress((void**)&gbh,  g_gbh);
    cudaGetSymbolAddress((void**)&gbl,  g_gbl);
    cudaGetSymbolAddress((void**)&wh,   g_wh);
    cudaGetSymbolAddress((void**)&wl,   g_wl);

    cvt_all<<<840, 256>>>(q_w, kv_w, sr_w, proj_w, fc1_w, fc2_w, q_b, kv_b, sr_b, wh, wl, b512);

    ln_kernel<<<TOK/8, 256>>>(x, n1w, n1b, yh, yl);
    hgemm2<<<dim3(8,98), 128>>>(yh, yl, wh+OQ, wl+OQ, 128, b512, t1, 512, 512, 0, nullptr);
    pointwise1<<<TOK/8, 256>>>(t1, temp, qe, plnw, plnb, qsb, qnb, klb, vlb, xph, xpl);
    hgemm_kv<<<dim3(4,98), 128>>>(xph, xpl, wh+OKV, wl+OKV, kv_b, kph, vphh);
    attn_pool_mma<<<dim3(49,8), 128>>>(qsb, kph, vphh, qnb, klb, vlb, lt, lb, atth, attl);
    hgemm2<<<dim3(2,98), 128>>>(atth, attl, wh+OPJ, wl+OPJ, 128, proj_b, x2b, 128, 128, 1, x);
    ln_kernel<<<TOK/8, 256>>>(x2b, n2w, n2b, y2h, y2l);
    hgemm2<<<dim3(11,98), 128>>>(y2h, y2l, wh+OF1, wl+OF1, 128, fc1_b, (float*)f1hb, 682, 682, 3, nullptr);
    dwconv_kernel<<<TOK, LDF>>>(f1hb, dw_w, dw_b, gbh, gbl);
    hgemm2<<<dim3(2,98), 128>>>(gbh, gbl, wh+OF2, wl+OF2, LDF, fc2_b, out, 128, 128, 2, x2b);
}

// round 11
// speedup vs baseline: 1.3799x; 1.0773x over previous
#include <cuda_runtime.h>
#include <cuda_fp16.h>
#include <math.h>

#define Bn   2
#define Cn   128
#define Hs   56
#define Nn   3136
#define NHn  4
#define HFn  341
#define TOK  (Bn*Nn)
#define LDF  352

// fp32 scratch
__device__ __align__(256) float g_tmp1[TOK*512];
__device__ __align__(256) float g_qs [8*Nn*32];
__device__ __align__(256) float g_qn [8*Nn*32];
__device__ __align__(256) float g_kl [8*Nn*32];
__device__ __align__(256) float g_vl [8*Nn*32];
__device__ __align__(256) float g_x2 [TOK*Cn];
__device__ __align__(256) float g_b512[512];
// half scratch
__device__ __align__(256) __half g_f1h[TOK*682];
__device__ __align__(256) __half g_yh [TOK*Cn], g_yl [TOK*Cn];
__device__ __align__(256) __half g_xph[TOK*Cn], g_xpl[TOK*Cn];
__device__ __align__(256) __half g_atth[TOK*Cn], g_attl[TOK*Cn];
__device__ __align__(256) __half g_y2h[TOK*Cn], g_y2l[TOK*Cn];
__device__ __align__(256) __half g_kph[TOK*Cn];
__device__ __align__(256) __half g_vph[TOK*Cn];
__device__ __align__(256) __half g_gbh[TOK*LDF], g_gbl[TOK*LDF];
// converted weights pool (hi only)
#define OQ   0
#define OKV  16384
#define OSR  49152
#define OPJ  65536
#define OF1  81920
#define OF2  169216
#define WTOT 214272
__device__ __align__(256) __half g_wh[WTOT];

__device__ __forceinline__ float gelu_exact(float x) {
    return 0.5f * x * (1.0f + erff(x * 0.70710678118654752f));
}
__device__ __forceinline__ unsigned h2pack(float a, float b) {
    __half2 h = __floats2half2_rn(a, b);
    return *(unsigned*)&h;
}
__device__ __forceinline__ void hsplit(float v, __half& hi, __half& lo) {
    hi = __float2half_rn(v);
    lo = __float2half_rn(v - __half2float(hi));
}
__device__ __forceinline__ void mma16816(float* c, const unsigned* a, unsigned b0, unsigned b1) {
    asm volatile("mma.sync.aligned.m16n8k16.row.col.f32.f16.f16.f32 "
        "{%0,%1,%2,%3}, {%4,%5,%6,%7}, {%8,%9}, {%0,%1,%2,%3};"
        : "+f"(c[0]), "+f"(c[1]), "+f"(c[2]), "+f"(c[3])
        : "r"(a[0]), "r"(a[1]), "r"(a[2]), "r"(a[3]), "r"(b0), "r"(b1));
}

// ---------- single-launch weight conversion (hi only) + fused bias ----------
__global__ void cvt_all(const float* __restrict__ q_w, const float* __restrict__ kv_w,
                        const float* __restrict__ sr_w, const float* __restrict__ proj_w,
                        const float* __restrict__ fc1_w, const float* __restrict__ fc2_w,
                        const float* __restrict__ q_b, const float* __restrict__ kv_b,
                        const float* __restrict__ sr_b,
                        __half* __restrict__ wh, float* __restrict__ b512)
{
    int i = blockIdx.x * 256 + threadIdx.x;
    if (i < WTOT) {
        float v;
        if      (i < OKV) v = q_w[i];
        else if (i < OSR) v = kv_w[i - OKV];
        else if (i < OPJ) v = sr_w[i - OSR];
        else if (i < OF1) v = proj_w[i - OPJ];
        else if (i < OF2) v = fc1_w[i - OF1];
        else {
            int j = i - OF2, r = j / LDF, c = j - r * LDF;
            v = (c < HFn) ? fc2_w[r * HFn + c] : 0.f;
        }
        wh[i] = __float2half_rn(v);
    } else if (i < WTOT + 512) {
        int j = i - WTOT;
        b512[j] = (j < 128) ? q_b[j] : (j < 384) ? kv_b[j - 128] : sr_b[j - 384];
    }
}

// ---------- LayerNorm (channel-major in) -> fp16 hi/lo token-major ----------
__global__ void ln_kernel(const float* __restrict__ in, const float* __restrict__ w,
                          const float* __restrict__ bvec,
                          __half* __restrict__ oh, __half* __restrict__ ol)
{
    int warp = blockIdx.x * 8 + (threadIdx.x >> 5);
    int lane = threadIdx.x & 31;
    int bb = warp / Nn, n = warp - bb * Nn;
    const float* p = in + (size_t)bb * (Cn*Nn) + n;
    float v[4], s = 0.f, s2 = 0.f;
#pragma unroll
    for (int pp = 0; pp < 2; pp++) {
        int c0 = 2*lane + 64*pp;
        v[2*pp]   = p[(size_t)c0 * Nn];
        v[2*pp+1] = p[(size_t)(c0+1) * Nn];
        s += v[2*pp] + v[2*pp+1];
        s2 += v[2*pp]*v[2*pp] + v[2*pp+1]*v[2*pp+1];
    }
#pragma unroll
    for (int d = 1; d < 32; d <<= 1) {
        s  += __shfl_xor_sync(0xffffffffu, s,  d);
        s2 += __shfl_xor_sync(0xffffffffu, s2, d);
    }
    float mu = s * (1.0f/128.0f);
    float rstd = rsqrtf(s2*(1.0f/128.0f) - mu*mu + 1e-5f);
    unsigned* ohp = (unsigned*)oh;
    unsigned* olp = (unsigned*)ol;
#pragma unroll
    for (int pp = 0; pp < 2; pp++) {
        int c0 = 2*lane + 64*pp;
        float a = (v[2*pp]  -mu)*rstd*w[c0]   + bvec[c0];
        float b = (v[2*pp+1]-mu)*rstd*w[c0+1] + bvec[c0+1];
        __half ah, al_, bh, bl; hsplit(a, ah, al_); hsplit(b, bh, bl);
        __half2 hh = __halves2half2(ah, bh), ll = __halves2half2(al_, bl);
        ohp[warp*64 + lane + 32*pp] = *(unsigned*)&hh;
        olp[warp*64 + lane + 32*pp] = *(unsigned*)&ll;
    }
}

// ---------- HMMA GEMM: A hi/lo x W hi ----------
// mode 0: fp32 out; 1: fp32 +res; 2: transposed channel-major +res; 3: fp16 out
__global__ void __launch_bounds__(128) hgemm2(
    const __half* __restrict__ Ah, const __half* __restrict__ Al,
    const __half* __restrict__ Wh, int ld,
    const float* __restrict__ bias, float* __restrict__ out,
    int ldo, int Nout, int mode, const float* __restrict__ res)
{
    const int m0 = blockIdx.y * 64;
    const int n0 = blockIdx.x * 64;
    const int warp = threadIdx.x >> 5;
    const int lane = threadIdx.x & 31;
    const int r  = lane >> 2;
    const int c2 = (lane & 3) * 2;

    float acc[8][4];
#pragma unroll
    for (int t = 0; t < 8; t++)
#pragma unroll
        for (int i = 0; i < 4; i++) acc[t][i] = 0.f;

    const int row1 = m0 + warp*16 + r;
    const __half* a1h = Ah + (size_t)row1 * ld;
    const __half* a2h = a1h + (size_t)8 * ld;
    const __half* a1l = Al + (size_t)row1 * ld;
    const __half* a2l = a1l + (size_t)8 * ld;

    const int nr = n0 + (lane >> 2);
    const __half* wrow[8];
#pragma unroll
    for (int nt = 0; nt < 8; nt++) {
        int n = nr + nt*8;
        int nc = (n < Nout) ? n : (Nout - 1);
        wrow[nt] = Wh + (size_t)nc * ld;
    }

    const int KC = ld / 32;
    for (int kc = 0; kc < KC; kc++) {
#pragma unroll
        for (int ks = 0; ks < 2; ks++) {
            int d0 = kc*32 + ks*16 + c2;
            unsigned ah[4], al[4];
            ah[0] = *(const unsigned*)&a1h[d0];
            ah[1] = *(const unsigned*)&a2h[d0];
            ah[2] = *(const unsigned*)&a1h[d0+8];
            ah[3] = *(const unsigned*)&a2h[d0+8];
            al[0] = *(const unsigned*)&a1l[d0];
            al[1] = *(const unsigned*)&a2l[d0];
            al[2] = *(const unsigned*)&a1l[d0+8];
            al[3] = *(const unsigned*)&a2l[d0+8];
#pragma unroll
            for (int nt = 0; nt < 8; nt++) {
                unsigned bh0 = *(const unsigned*)&wrow[nt][d0];
                unsigned bh1 = *(const unsigned*)&wrow[nt][d0+8];
                mma16816(acc[nt], ah, bh0, bh1);
                mma16816(acc[nt], al, bh0, bh1);
            }
        }
    }

    int m1 = row1, m2 = row1 + 8;
#pragma unroll
    for (int nt = 0; nt < 8; nt++) {
        int n = n0 + nt*8 + c2;
#pragma unroll
        for (int j = 0; j < 2; j++) {
            int nn = n + j;
            if (nn >= Nout) continue;
            float v1 = acc[nt][j]   + bias[nn];
            float v2 = acc[nt][2+j] + bias[nn];
            if (mode == 0) {
                out[(size_t)m1*ldo + nn] = v1;
                out[(size_t)m2*ldo + nn] = v2;
            } else if (mode == 1) {
                size_t i1 = (size_t)m1*ldo + nn, i2 = (size_t)m2*ldo + nn;
                out[i1] = v1 + res[i1];
                out[i2] = v2 + res[i2];
            } else if (mode == 2) {
                int b1 = m1 / Nn, t1i = m1 - b1*Nn;
                int b2 = m2 / Nn, t2i = m2 - b2*Nn;
                size_t i1 = ((size_t)b1*Cn + nn)*Nn + t1i;
                size_t i2 = ((size_t)b2*Cn + nn)*Nn + t2i;
                out[i1] = v1 + res[i1];
                out[i2] = v2 + res[i2];
            } else {
                __half* oh = (__half*)out;
                oh[(size_t)m1*ldo + nn] = __float2half_rn(v1);
                oh[(size_t)m2*ldo + nn] = __float2half_rn(v2);
            }
        }
    }
}

// ---------- HMMA kv GEMM with fused l2norm/split epilogue -> kph/vph fp16 ----------
__global__ void __launch_bounds__(128) hgemm_kv(
    const __half* __restrict__ Ah, const __half* __restrict__ Al,
    const __half* __restrict__ Wh,
    const float* __restrict__ bias,
    __half* __restrict__ kph, __half* __restrict__ vph)
{
    const int m0 = blockIdx.y * 64;
    const int n0 = blockIdx.x * 64;
    const int warp = threadIdx.x >> 5;
    const int lane = threadIdx.x & 31;
    const int r  = lane >> 2;
    const int c2 = (lane & 3) * 2;
    const int ld = 128;

    float acc[8][4];
#pragma unroll
    for (int t = 0; t < 8; t++)
#pragma unroll
        for (int i = 0; i < 4; i++) acc[t][i] = 0.f;

    const int row1 = m0 + warp*16 + r;
    const __half* a1h = Ah + (size_t)row1 * ld;
    const __half* a2h = a1h + (size_t)8 * ld;
    const __half* a1l = Al + (size_t)row1 * ld;
    const __half* a2l = a1l + (size_t)8 * ld;

    const int nr = n0 + (lane >> 2);
    const __half* wrow[8];
#pragma unroll
    for (int nt = 0; nt < 8; nt++)
        wrow[nt] = Wh + (size_t)(nr + nt*8) * ld;

#pragma unroll
    for (int kc = 0; kc < 4; kc++) {
#pragma unroll
        for (int ks = 0; ks < 2; ks++) {
            int d0 = kc*32 + ks*16 + c2;
            unsigned ah[4], al[4];
            ah[0] = *(const unsigned*)&a1h[d0];
            ah[1] = *(const unsigned*)&a2h[d0];
            ah[2] = *(const unsigned*)&a1h[d0+8];
            ah[3] = *(const unsigned*)&a2h[d0+8];
            al[0] = *(const unsigned*)&a1l[d0];
            al[1] = *(const unsigned*)&a2l[d0];
            al[2] = *(const unsigned*)&a1l[d0+8];
            al[3] = *(const unsigned*)&a2l[d0+8];
#pragma unroll
            for (int nt = 0; nt < 8; nt++) {
                unsigned bh0 = *(const unsigned*)&wrow[nt][d0];
                unsigned bh1 = *(const unsigned*)&wrow[nt][d0+8];
                mma16816(acc[nt], ah, bh0, bh1);
                mma16816(acc[nt], al, bh0, bh1);
            }
        }
    }

#pragma unroll
    for (int half = 0; half < 2; half++) {
        int m = row1 + half*8;
        int bb = m / Nn, n = m - bb*Nn;
        float vals[16];
#pragma unroll
        for (int nt = 0; nt < 8; nt++)
#pragma unroll
            for (int j = 0; j < 2; j++)
                vals[nt*2+j] = acc[nt][half*2+j] + bias[n0 + nt*8 + c2 + j];
        if (n0 < 128) {
            float se = 0.f, so = 0.f;
#pragma unroll
            for (int i = 0; i < 8; i++) { se += vals[i]*vals[i]; so += vals[8+i]*vals[8+i]; }
            se += __shfl_xor_sync(0xffffffffu, se, 1);
            se += __shfl_xor_sync(0xffffffffu, se, 2);
            so += __shfl_xor_sync(0xffffffffu, so, 1);
            so += __shfl_xor_sync(0xffffffffu, so, 2);
            float ke = 1.0f / fmaxf(sqrtf(se), 1e-12f);
            float ko = 1.0f / fmaxf(sqrtf(so), 1e-12f);
#pragma unroll
            for (int nt = 0; nt < 8; nt++) {
                int col = n0 + nt*8 + c2;
                int head = col >> 5;
                float sc = (nt < 4) ? ke : ko;
                __half2 hv = __floats2half2_rn(vals[nt*2]*sc, vals[nt*2+1]*sc);
                *(__half2*)&kph[((size_t)(bb*NHn + head)*Nn + n)*32 + (col & 31)] = hv;
            }
        } else {
#pragma unroll
            for (int nt = 0; nt < 8; nt++) {
                int col = n0 - 128 + nt*8 + c2;
                int head = col >> 5;
                __half2 hv = __floats2half2_rn(vals[nt*2], vals[nt*2+1]);
                *(__half2*)&vph[((size_t)(bb*NHn + head)*Nn + n)*32 + (col & 31)] = hv;
            }
        }
    }
}

// ---------- pointwise after fused QKVSR GEMM ----------
__global__ void pointwise1(const float* __restrict__ tmp1, const float* __restrict__ temp,
                           const float* __restrict__ qe, const float* __restrict__ plnw,
                           const float* __restrict__ plnb,
                           float* __restrict__ qs, float* __restrict__ qn,
                           float* __restrict__ kl, float* __restrict__ vl,
                           __half* __restrict__ xph, __half* __restrict__ xpl)
{
    int t = blockIdx.x * 8 + (threadIdx.x >> 5);
    int lane = threadIdx.x & 31;
    int bb = t / Nn, n = t - bb * Nn;
    int h = lane >> 3;
    int g = bb * NHn + h;
    const float4* row = (const float4*)(tmp1 + (size_t)t * 512);
    size_t ho = ((size_t)g * Nn + n) * 8 + (lane & 7);

    float4 q4 = row[lane];
    float ss = q4.x*q4.x + q4.y*q4.y + q4.z*q4.z + q4.w*q4.w;
    ss += __shfl_xor_sync(0xffffffffu, ss, 1);
    ss += __shfl_xor_sync(0xffffffffu, ss, 2);
    ss += __shfl_xor_sync(0xffffffffu, ss, 4);
    float inv = 1.0f / fmaxf(sqrtf(ss), 1e-12f);
    float4 qn4 = make_float4(q4.x*inv, q4.y*inv, q4.z*inv, q4.w*inv);
    float tv = temp[h];
    float sp = log1pf(__expf(tv));
    float4 qe4 = ((const float4*)qe)[h*8 + (lane & 7)];
    ((float4*)qn)[ho] = qn4;
    ((float4*)qs)[ho] = make_float4((qn4.x+qe4.x)*sp, (qn4.y+qe4.y)*sp,
                                    (qn4.z+qe4.z)*sp, (qn4.w+qe4.w)*sp);

    float4 k4 = row[32 + lane];
    float ks = k4.x*k4.x + k4.y*k4.y + k4.z*k4.z + k4.w*k4.w;
    ks += __shfl_xor_sync(0xffffffffu, ks, 1);
    ks += __shfl_xor_sync(0xffffffffu, ks, 2);
    ks += __shfl_xor_sync(0xffffffffu, ks, 4);
    float ki = 1.0f / fmaxf(sqrtf(ks), 1e-12f);
    ((float4*)kl)[ho] = make_float4(k4.x*ki, k4.y*ki, k4.z*ki, k4.w*ki);
    ((float4*)vl)[ho] = row[64 + lane];

    float4 s4 = row[96 + lane];
    float g0 = gelu_exact(s4.x), g1 = gelu_exact(s4.y);
    float g2 = gelu_exact(s4.z), g3 = gelu_exact(s4.w);
    float sm = g0+g1+g2+g3;
    float sq = g0*g0+g1*g1+g2*g2+g3*g3;
#pragma unroll
    for (int d = 1; d < 32; d <<= 1) {
        sm += __shfl_xor_sync(0xffffffffu, sm, d);
        sq += __shfl_xor_sync(0xffffffffu, sq, d);
    }
    float mu = sm*(1.0f/128.0f);
    float rstd = rsqrtf(sq*(1.0f/128.0f) - mu*mu + 1e-5f);
    int c = lane * 4;
    float o0 = (g0-mu)*rstd*plnw[c]   + plnb[c];
    float o1 = (g1-mu)*rstd*plnw[c+1] + plnb[c+1];
    float o2 = (g2-mu)*rstd*plnw[c+2] + plnb[c+2];
    float o3 = (g3-mu)*rstd*plnw[c+3] + plnb[c+3];
    __half h0,l0,h1,l1,h2,l2,h3,l3;
    hsplit(o0,h0,l0); hsplit(o1,h1,l1); hsplit(o2,h2,l2); hsplit(o3,h3,l3);
    unsigned* xh = (unsigned*)xph;
    unsigned* xl = (unsigned*)xpl;
    __half2 a01 = __halves2half2(h0,h1), a23 = __halves2half2(h2,h3);
    __half2 b01 = __halves2half2(l0,l1), b23 = __halves2half2(l2,l3);
    xh[(size_t)t*64 + lane*2]     = *(unsigned*)&a01;
    xh[(size_t)t*64 + lane*2 + 1] = *(unsigned*)&a23;
    xl[(size_t)t*64 + lane*2]     = *(unsigned*)&b01;
    xl[(size_t)t*64 + lane*2 + 1] = *(unsigned*)&b23;
}

// ---------- HMMA pooled attention: 2 q-blocks per CTA share K/V staging ----------
__global__ void __launch_bounds__(256) attn_pool_mma(
    const float* __restrict__ qs, const __half* __restrict__ kph,
    const __half* __restrict__ vph,
    const float* __restrict__ qn, const float* __restrict__ kl,
    const float* __restrict__ vl, const float* __restrict__ lt,
    const float* __restrict__ lb,
    __half* __restrict__ atth, __half* __restrict__ attl)
{
    __shared__ __half Khi[128][40];
    __shared__ __half Vt[32][132];

    const int g  = blockIdx.y;
    const int tid = threadIdx.x;
    const int warp = tid >> 5;          // 0..7
    const int lane = tid & 31;
    const int r  = lane >> 2;
    const int c2 = (lane & 3) * 2;
    // warps 0-3 -> q-block A; warps 4-7 -> q-block B
    const int qbase = blockIdx.x * 128 + (warp >> 2) * 64 + (warp & 3) * 16 + r;
    const int qrow_l = (qbase < Nn) ? qbase : (Nn - 1);   // clamped (tail block)

    unsigned qhi[2][4];
    {
        const float* q0p = qs + ((size_t)g*Nn + qrow_l)*32;
        int q8c = (qbase + 8 < Nn) ? (qbase + 8) : (Nn - 1);
        const float* q8p = qs + ((size_t)g*Nn + q8c)*32;
#pragma unroll
        for (int ks = 0; ks < 2; ks++) {
            int d0 = ks*16 + c2;
            qhi[ks][0] = h2pack(q0p[d0],   q0p[d0+1]);
            qhi[ks][1] = h2pack(q8p[d0],   q8p[d0+1]);
            qhi[ks][2] = h2pack(q0p[d0+8], q0p[d0+9]);
            qhi[ks][3] = h2pack(q8p[d0+8], q8p[d0+9]);
        }
    }

    float uf[4][4];
#pragma unroll
    for (int t = 0; t < 4; t++)
#pragma unroll
        for (int i = 0; i < 4; i++) uf[t][i] = 0.f;
    float z0 = 0.f, z1 = 0.f;

    const int NCH = 25;
    for (int ch = 0; ch < NCH; ch++) {
        const int m0 = ch * 128;
        {
            int row = tid & 127;
            int hp  = tid >> 7;          // 0 or 1: which half of the row this thread stages
            int kvr = m0 + row;
            bool ok = kvr < Nn;
            size_t rb = ((size_t)g*Nn + (ok ? kvr : 0))*32;
            const uint4* krh = (const uint4*)(kph + rb);
            uint4 z4 = make_uint4(0,0,0,0);
#pragma unroll
            for (int j = 0; j < 2; j++)
                *(uint4*)&Khi[row][(hp*2 + j)*8] = ok ? krh[hp*2 + j] : z4;
            const unsigned* vr = (const unsigned*)(vph + rb);
#pragma unroll
            for (int j = 0; j < 8; j++) {
                int jj = hp*8 + j;
                unsigned p = ok ? vr[jj] : 0u;
                __half2 hh = *(__half2*)&p;
                Vt[2*jj][row]   = hh.x;
                Vt[2*jj+1][row] = hh.y;
            }
        }
        __syncthreads();

        const int kkmax = (m0 + 128 <= Nn) ? 8 : 4;
        for (int kk = 0; kk < kkmax; kk++) {
            unsigned ea[4];
#pragma unroll
            for (int tt = 0; tt < 2; tt++) {
                int t = 2*kk + tt;
                int kv = t*8 + (lane >> 2);
                float sf[4] = {0.f, 0.f, 0.f, 0.f};
#pragma unroll
                for (int ks = 0; ks < 2; ks++) {
                    int d0 = ks*16 + c2;
                    unsigned bh0 = *(const unsigned*)&Khi[kv][d0];
                    unsigned bh1 = *(const unsigned*)&Khi[kv][d0+8];
                    mma16816(sf, qhi[ks], bh0, bh1);
                }
                float e0 = __expf(sf[0]);
                float e1 = __expf(sf[1]);
                float e2 = __expf(sf[2]);
                float e3 = __expf(sf[3]);
                z0 += e0 + e1;
                z1 += e2 + e3;
                ea[2*tt]   = h2pack(e0, e1);
                ea[2*tt+1] = h2pack(e2, e3);
            }
            int kv0 = kk*16 + c2;
#pragma unroll
            for (int nt = 0; nt < 4; nt++) {
                int d = nt*8 + (lane >> 2);
                unsigned b0 = *(const unsigned*)&Vt[d][kv0];
                unsigned b1 = *(const unsigned*)&Vt[d][kv0+8];
                mma16816(uf[nt], ea, b0, b1);
            }
        }
        __syncthreads();
    }

    // ---- fused finalize ----
    z0 += __shfl_xor_sync(0xffffffffu, z0, 1);
    z0 += __shfl_xor_sync(0xffffffffu, z0, 2);
    z1 += __shfl_xor_sync(0xffffffffu, z1, 1);
    z1 += __shfl_xor_sync(0xffffffffu, z1, 2);

    const int b = g >> 2, h = g & 3;
#pragma unroll
    for (int half = 0; half < 2; half++) {
        int n = qbase + half*8;
        bool nok = n < Nn;
        int nc = nok ? n : (Nn - 1);
        float Zpool = half ? z1 : z0;
        int hh = nc / Hs, ww = nc - hh*Hs;
        const float* qp  = qs + ((size_t)g*Nn + nc)*32;
        const float* qnp = qn + ((size_t)g*Nn + nc)*32;
        float qsv[8], qnv[8];
#pragma unroll
        for (int nt = 0; nt < 4; nt++)
#pragma unroll
            for (int j = 0; j < 2; j++) {
                int c = nt*8 + c2 + j;
                qsv[nt*2+j] = qp[c];
                qnv[nt*2+j] = qnp[c];
            }
        float resv[8], res2v[8];
#pragma unroll
        for (int i = 0; i < 8; i++) { resv[i] = 0.f; res2v[i] = 0.f; }
        float zl = 0.f;
#pragma unroll
        for (int k = 0; k < 9; k++) {
            int h2 = hh + k/3 - 1, w2 = ww + (k%3) - 1;
            bool ok = (h2 >= 0 && h2 < Hs && w2 >= 0 && w2 < Hs);
            size_t bi = ((size_t)g*Nn + (ok ? (h2*Hs + w2) : 0))*32;
            float klv[8], vlv[8];
            float lg = 0.f, wl = 0.f;
#pragma unroll
            for (int nt = 0; nt < 4; nt++)
#pragma unroll
                for (int j = 0; j < 2; j++) {
                    int c = nt*8 + c2 + j;
                    int idx = nt*2 + j;
                    klv[idx] = ok ? kl[bi + c] : 0.f;
                    vlv[idx] = ok ? vl[bi + c] : 0.f;
                    lg += qsv[idx] * klv[idx];
                    wl += qnv[idx] * lt[(h*32 + c)*9 + k];
                }
            lg += __shfl_xor_sync(0xffffffffu, lg, 1);
            lg += __shfl_xor_sync(0xffffffffu, lg, 2);
            wl += __shfl_xor_sync(0xffffffffu, wl, 1);
            wl += __shfl_xor_sync(0xffffffffu, wl, 2);
            float e = __expf(lg);
            zl += e;
            float w2l = wl + lb[h*9 + k];
#pragma unroll
            for (int i = 0; i < 8; i++) {
                resv[i]  += e   * vlv[i];
                res2v[i] += w2l * vlv[i];
            }
        }
        float Zf = Zpool + zl;
        float rZ = 1.0f / Zf;
        if (nok) {
#pragma unroll
            for (int nt = 0; nt < 4; nt++)
#pragma unroll
                for (int j = 0; j < 2; j++) {
                    int c = nt*8 + c2 + j;
                    int idx = nt*2 + j;
                    float o = (uf[nt][half*2 + j] + resv[idx]) * rZ + res2v[idx];
                    size_t oi = ((size_t)(b*Nn + n))*128 + h*32 + c;
                    __half oh, ol; hsplit(o, oh, ol);
                    atth[oi] = oh; attl[oi] = ol;
                }
        }
    }
}

// ---------- depthwise 3x3 + gelu * v (fp16 f1) -> fp16 hi/lo ----------
__global__ void dwconv_kernel(const __half* __restrict__ f1, const float* __restrict__ dww,
                              const float* __restrict__ dwb,
                              __half* __restrict__ gbh, __half* __restrict__ gbl)
{
    int t = blockIdx.x;
    int c = threadIdx.x;
    if (c >= LDF) return;
    size_t oi = (size_t)t*LDF + c;
    if (c >= HFn) { gbh[oi] = __float2half(0.f); gbl[oi] = __float2half(0.f); return; }
    int b = t / Nn, n = t - b*Nn;
    int hh = n / Hs, ww = n - hh*Hs;
    float acc = dwb[c];
#pragma unroll
    for (int k = 0; k < 9; k++) {
        int h2 = hh + k/3 - 1, w2 = ww + (k%3) - 1;
        if (h2 < 0 || h2 >= Hs || w2 < 0 || w2 >= Hs) continue;
        acc += __half2float(f1[((size_t)(b*Nn + h2*Hs + w2))*682 + c]) * dww[c*9 + k];
    }
    float v = __half2float(f1[(size_t)t*682 + 341 + c]);
    float o = gelu_exact(acc) * v;
    __half oh, ol; hsplit(o, oh, ol);
    gbh[oi] = oh; gbl[oi] = ol;
}

extern "C" void kernel_launch(void* const* d_in, const int* in_sizes, int n_in,
                              void* d_out, int out_size)
{
    const float* x      = (const float*)d_in[0];
    const float* n1w    = (const float*)d_in[1];
    const float* n1b    = (const float*)d_in[2];
    const float* q_w    = (const float*)d_in[3];
    const float* q_b    = (const float*)d_in[4];
    const float* kv_w   = (const float*)d_in[5];
    const float* kv_b   = (const float*)d_in[6];
    const float* temp   = (const float*)d_in[7];
    const float* qe     = (const float*)d_in[8];
    const float* lt     = (const float*)d_in[9];
    const float* lb     = (const float*)d_in[10];
    const float* sr_w   = (const float*)d_in[11];
    const float* sr_b   = (const float*)d_in[12];
    const float* plnw   = (const float*)d_in[13];
    const float* plnb   = (const float*)d_in[14];
    const float* proj_w = (const float*)d_in[15];
    const float* proj_b = (const float*)d_in[16];
    const float* n2w    = (const float*)d_in[17];
    const float* n2b    = (const float*)d_in[18];
    const float* fc1_w  = (const float*)d_in[19];
    const float* fc1_b  = (const float*)d_in[20];
    const float* dw_w   = (const float*)d_in[21];
    const float* dw_b   = (const float*)d_in[22];
    const float* fc2_w  = (const float*)d_in[23];
    const float* fc2_b  = (const float*)d_in[24];
    float* out = (float*)d_out;

    float *t1, *qsb, *qnb, *klb, *vlb, *x2b, *b512;
    __half *f1hb, *yh, *yl, *xph, *xpl, *atth, *attl, *y2h, *y2l, *kph, *vphh, *gbh, *gbl, *wh;
    cudaGetSymbolAddress((void**)&t1,   g_tmp1);
    cudaGetSymbolAddress((void**)&qsb,  g_qs);
    cudaGetSymbolAddress((void**)&qnb,  g_qn);
    cudaGetSymbolAddress((void**)&klb,  g_kl);
    cudaGetSymbolAddress((void**)&vlb,  g_vl);
    cudaGetSymbolAddress((void**)&x2b,  g_x2);
    cudaGetSymbolAddress((void**)&b512, g_b512);
    cudaGetSymbolAddress((void**)&f1hb, g_f1h);
    cudaGetSymbolAddress((void**)&yh,   g_yh);
    cudaGetSymbolAddress((void**)&yl,   g_yl);
    cudaGetSymbolAddress((void**)&xph,  g_xph);
    cudaGetSymbolAddress((void**)&xpl,  g_xpl);
    cudaGetSymbolAddress((void**)&atth, g_atth);
    cudaGetSymbolAddress((void**)&attl, g_attl);
    cudaGetSymbolAddress((void**)&y2h,  g_y2h);
    cudaGetSymbolAddress((void**)&y2l,  g_y2l);
    cudaGetSymbolAddress((void**)&kph,  g_kph);
    cudaGetSymbolAddress((void**)&vphh, g_vph);
    cudaGetSymbolAddress((void**)&gbh,  g_gbh);
    cudaGetSymbolAddress((void**)&gbl,  g_gbl);
    cudaGetSymbolAddress((void**)&wh,   g_wh);

    cvt_all<<<840, 256>>>(q_w, kv_w, sr_w, proj_w, fc1_w, fc2_w, q_b, kv_b, sr_b, wh, b512);

    ln_kernel<<<TOK/8, 256>>>(x, n1w, n1b, yh, yl);
    hgemm2<<<dim3(8,98), 128>>>(yh, yl, wh+OQ, 128, b512, t1, 512, 512, 0, nullptr);
    pointwise1<<<TOK/8, 256>>>(t1, temp, qe, plnw, plnb, qsb, qnb, klb, vlb, xph, xpl);
    hgemm_kv<<<dim3(4,98), 128>>>(xph, xpl, wh+OKV, kv_b, kph, vphh);
    attn_pool_mma<<<dim3(25,8), 256>>>(qsb, kph, vphh, qnb, klb, vlb, lt, lb, atth, attl);
    hgemm2<<<dim3(2,98), 128>>>(atth, attl, wh+OPJ, 128, proj_b, x2b, 128, 128, 1, x);
    ln_kernel<<<TOK/8, 256>>>(x2b, n2w, n2b, y2h, y2l);
    hgemm2<<<dim3(11,98), 128>>>(y2h, y2l, wh+OF1, 128, fc1_b, (float*)f1hb, 682, 682, 3, nullptr);
    dwconv_kernel<<<TOK, LDF>>>(f1hb, dw_w, dw_b, gbh, gbl);
    hgemm2<<<dim3(2,98), 128>>>(gbh, gbl, wh+OF2, LDF, fc2_b, out, 128, 128, 2, x2b);
}

// round 12
// speedup vs baseline: 1.4985x; 1.0859x over previous
#include <cuda_runtime.h>
#include <cuda_fp16.h>
#include <math.h>

#define Bn   2
#define Cn   128
#define Hs   56
#define Nn   3136
#define NHn  4
#define HFn  341
#define TOK  (Bn*Nn)
#define LDF  352

// fp32 scratch
__device__ __align__(256) float g_tmp1[TOK*512];
__device__ __align__(256) float g_qs [8*Nn*32];
__device__ __align__(256) float g_qn [8*Nn*32];
__device__ __align__(256) float g_kl [8*Nn*32];
__device__ __align__(256) float g_vl [8*Nn*32];
__device__ __align__(256) float g_x2 [TOK*Cn];
__device__ __align__(256) float g_b512[512];
// half scratch
__device__ __align__(256) __half g_f1h[TOK*682];
__device__ __align__(256) __half g_yh [TOK*Cn];
__device__ __align__(256) __half g_xph[TOK*Cn];
__device__ __align__(256) __half g_atth[TOK*Cn];
__device__ __align__(256) __half g_y2h[TOK*Cn];
__device__ __align__(256) __half g_kph[TOK*Cn];
__device__ __align__(256) __half g_vph[TOK*Cn];
__device__ __align__(256) __half g_gbh[TOK*LDF];
// converted weights pool (hi only)
#define OQ   0
#define OKV  16384
#define OSR  49152
#define OPJ  65536
#define OF1  81920
#define OF2  169216
#define WTOT 214272
__device__ __align__(256) __half g_wh[WTOT];

__device__ __forceinline__ float gelu_exact(float x) {
    return 0.5f * x * (1.0f + erff(x * 0.70710678118654752f));
}
__device__ __forceinline__ unsigned h2pack(float a, float b) {
    __half2 h = __floats2half2_rn(a, b);
    return *(unsigned*)&h;
}
__device__ __forceinline__ void mma16816(float* c, const unsigned* a, unsigned b0, unsigned b1) {
    asm volatile("mma.sync.aligned.m16n8k16.row.col.f32.f16.f16.f32 "
        "{%0,%1,%2,%3}, {%4,%5,%6,%7}, {%8,%9}, {%0,%1,%2,%3};"
        : "+f"(c[0]), "+f"(c[1]), "+f"(c[2]), "+f"(c[3])
        : "r"(a[0]), "r"(a[1]), "r"(a[2]), "r"(a[3]), "r"(b0), "r"(b1));
}

// ---------- single-launch weight conversion (hi only) + fused bias ----------
__global__ void cvt_all(const float* __restrict__ q_w, const float* __restrict__ kv_w,
                        const float* __restrict__ sr_w, const float* __restrict__ proj_w,
                        const float* __restrict__ fc1_w, const float* __restrict__ fc2_w,
                        const float* __restrict__ q_b, const float* __restrict__ kv_b,
                        const float* __restrict__ sr_b,
                        __half* __restrict__ wh, float* __restrict__ b512)
{
    int i = blockIdx.x * 256 + threadIdx.x;
    if (i < WTOT) {
        float v;
        if      (i < OKV) v = q_w[i];
        else if (i < OSR) v = kv_w[i - OKV];
        else if (i < OPJ) v = sr_w[i - OSR];
        else if (i < OF1) v = proj_w[i - OPJ];
        else if (i < OF2) v = fc1_w[i - OF1];
        else {
            int j = i - OF2, r = j / LDF, c = j - r * LDF;
            v = (c < HFn) ? fc2_w[r * HFn + c] : 0.f;
        }
        wh[i] = __float2half_rn(v);
    } else if (i < WTOT + 512) {
        int j = i - WTOT;
        b512[j] = (j < 128) ? q_b[j] : (j < 384) ? kv_b[j - 128] : sr_b[j - 384];
    }
}

// ---------- LayerNorm (channel-major in) -> fp16 token-major ----------
__global__ void ln_kernel(const float* __restrict__ in, const float* __restrict__ w,
                          const float* __restrict__ bvec, __half* __restrict__ oh)
{
    int warp = blockIdx.x * 8 + (threadIdx.x >> 5);
    int lane = threadIdx.x & 31;
    int bb = warp / Nn, n = warp - bb * Nn;
    const float* p = in + (size_t)bb * (Cn*Nn) + n;
    float v[4], s = 0.f, s2 = 0.f;
#pragma unroll
    for (int pp = 0; pp < 2; pp++) {
        int c0 = 2*lane + 64*pp;
        v[2*pp]   = p[(size_t)c0 * Nn];
        v[2*pp+1] = p[(size_t)(c0+1) * Nn];
        s += v[2*pp] + v[2*pp+1];
        s2 += v[2*pp]*v[2*pp] + v[2*pp+1]*v[2*pp+1];
    }
#pragma unroll
    for (int d = 1; d < 32; d <<= 1) {
        s  += __shfl_xor_sync(0xffffffffu, s,  d);
        s2 += __shfl_xor_sync(0xffffffffu, s2, d);
    }
    float mu = s * (1.0f/128.0f);
    float rstd = rsqrtf(s2*(1.0f/128.0f) - mu*mu + 1e-5f);
    unsigned* ohp = (unsigned*)oh;
#pragma unroll
    for (int pp = 0; pp < 2; pp++) {
        int c0 = 2*lane + 64*pp;
        float a = (v[2*pp]  -mu)*rstd*w[c0]   + bvec[c0];
        float b = (v[2*pp+1]-mu)*rstd*w[c0+1] + bvec[c0+1];
        ohp[warp*64 + lane + 32*pp] = h2pack(a, b);
    }
}

// ---------- HMMA GEMM: single fp16 A x W ----------
// mode 0: fp32 out; 1: fp32 +res; 2: transposed channel-major +res; 3: fp16 out
__global__ void __launch_bounds__(128) hgemm2(
    const __half* __restrict__ Ah, const __half* __restrict__ Wh, int ld,
    const float* __restrict__ bias, float* __restrict__ out,
    int ldo, int Nout, int mode, const float* __restrict__ res)
{
    const int m0 = blockIdx.y * 64;
    const int n0 = blockIdx.x * 64;
    const int warp = threadIdx.x >> 5;
    const int lane = threadIdx.x & 31;
    const int r  = lane >> 2;
    const int c2 = (lane & 3) * 2;

    float acc[8][4];
#pragma unroll
    for (int t = 0; t < 8; t++)
#pragma unroll
        for (int i = 0; i < 4; i++) acc[t][i] = 0.f;

    const int row1 = m0 + warp*16 + r;
    const __half* a1h = Ah + (size_t)row1 * ld;
    const __half* a2h = a1h + (size_t)8 * ld;

    const int nr = n0 + (lane >> 2);
    const __half* wrow[8];
#pragma unroll
    for (int nt = 0; nt < 8; nt++) {
        int n = nr + nt*8;
        int nc = (n < Nout) ? n : (Nout - 1);
        wrow[nt] = Wh + (size_t)nc * ld;
    }

    const int KC = ld / 32;
    for (int kc = 0; kc < KC; kc++) {
#pragma unroll
        for (int ks = 0; ks < 2; ks++) {
            int d0 = kc*32 + ks*16 + c2;
            unsigned ah[4];
            ah[0] = *(const unsigned*)&a1h[d0];
            ah[1] = *(const unsigned*)&a2h[d0];
            ah[2] = *(const unsigned*)&a1h[d0+8];
            ah[3] = *(const unsigned*)&a2h[d0+8];
#pragma unroll
            for (int nt = 0; nt < 8; nt++) {
                unsigned bh0 = *(const unsigned*)&wrow[nt][d0];
                unsigned bh1 = *(const unsigned*)&wrow[nt][d0+8];
                mma16816(acc[nt], ah, bh0, bh1);
            }
        }
    }

    int m1 = row1, m2 = row1 + 8;
#pragma unroll
    for (int nt = 0; nt < 8; nt++) {
        int n = n0 + nt*8 + c2;
#pragma unroll
        for (int j = 0; j < 2; j++) {
            int nn = n + j;
            if (nn >= Nout) continue;
            float v1 = acc[nt][j]   + bias[nn];
            float v2 = acc[nt][2+j] + bias[nn];
            if (mode == 0) {
                out[(size_t)m1*ldo + nn] = v1;
                out[(size_t)m2*ldo + nn] = v2;
            } else if (mode == 1) {
                size_t i1 = (size_t)m1*ldo + nn, i2 = (size_t)m2*ldo + nn;
                out[i1] = v1 + res[i1];
                out[i2] = v2 + res[i2];
            } else if (mode == 2) {
                int b1 = m1 / Nn, t1i = m1 - b1*Nn;
                int b2 = m2 / Nn, t2i = m2 - b2*Nn;
                size_t i1 = ((size_t)b1*Cn + nn)*Nn + t1i;
                size_t i2 = ((size_t)b2*Cn + nn)*Nn + t2i;
                out[i1] = v1 + res[i1];
                out[i2] = v2 + res[i2];
            } else {
                __half* oh = (__half*)out;
                oh[(size_t)m1*ldo + nn] = __float2half_rn(v1);
                oh[(size_t)m2*ldo + nn] = __float2half_rn(v2);
            }
        }
    }
}

// ---------- HMMA kv GEMM with fused l2norm/split epilogue -> kph/vph fp16 ----------
__global__ void __launch_bounds__(128) hgemm_kv(
    const __half* __restrict__ Ah, const __half* __restrict__ Wh,
    const float* __restrict__ bias,
    __half* __restrict__ kph, __half* __restrict__ vph)
{
    const int m0 = blockIdx.y * 64;
    const int n0 = blockIdx.x * 64;
    const int warp = threadIdx.x >> 5;
    const int lane = threadIdx.x & 31;
    const int r  = lane >> 2;
    const int c2 = (lane & 3) * 2;
    const int ld = 128;

    float acc[8][4];
#pragma unroll
    for (int t = 0; t < 8; t++)
#pragma unroll
        for (int i = 0; i < 4; i++) acc[t][i] = 0.f;

    const int row1 = m0 + warp*16 + r;
    const __half* a1h = Ah + (size_t)row1 * ld;
    const __half* a2h = a1h + (size_t)8 * ld;

    const int nr = n0 + (lane >> 2);
    const __half* wrow[8];
#pragma unroll
    for (int nt = 0; nt < 8; nt++)
        wrow[nt] = Wh + (size_t)(nr + nt*8) * ld;

#pragma unroll
    for (int kc = 0; kc < 4; kc++) {
#pragma unroll
        for (int ks = 0; ks < 2; ks++) {
            int d0 = kc*32 + ks*16 + c2;
            unsigned ah[4];
            ah[0] = *(const unsigned*)&a1h[d0];
            ah[1] = *(const unsigned*)&a2h[d0];
            ah[2] = *(const unsigned*)&a1h[d0+8];
            ah[3] = *(const unsigned*)&a2h[d0+8];
#pragma unroll
            for (int nt = 0; nt < 8; nt++) {
                unsigned bh0 = *(const unsigned*)&wrow[nt][d0];
                unsigned bh1 = *(const unsigned*)&wrow[nt][d0+8];
                mma16816(acc[nt], ah, bh0, bh1);
            }
        }
    }

#pragma unroll
    for (int half = 0; half < 2; half++) {
        int m = row1 + half*8;
        int bb = m / Nn, n = m - bb*Nn;
        float vals[16];
#pragma unroll
        for (int nt = 0; nt < 8; nt++)
#pragma unroll
            for (int j = 0; j < 2; j++)
                vals[nt*2+j] = acc[nt][half*2+j] + bias[n0 + nt*8 + c2 + j];
        if (n0 < 128) {
            float se = 0.f, so = 0.f;
#pragma unroll
            for (int i = 0; i < 8; i++) { se += vals[i]*vals[i]; so += vals[8+i]*vals[8+i]; }
            se += __shfl_xor_sync(0xffffffffu, se, 1);
            se += __shfl_xor_sync(0xffffffffu, se, 2);
            so += __shfl_xor_sync(0xffffffffu, so, 1);
            so += __shfl_xor_sync(0xffffffffu, so, 2);
            float ke = 1.0f / fmaxf(sqrtf(se), 1e-12f);
            float ko = 1.0f / fmaxf(sqrtf(so), 1e-12f);
#pragma unroll
            for (int nt = 0; nt < 8; nt++) {
                int col = n0 + nt*8 + c2;
                int head = col >> 5;
                float sc = (nt < 4) ? ke : ko;
                __half2 hv = __floats2half2_rn(vals[nt*2]*sc, vals[nt*2+1]*sc);
                *(__half2*)&kph[((size_t)(bb*NHn + head)*Nn + n)*32 + (col & 31)] = hv;
            }
        } else {
#pragma unroll
            for (int nt = 0; nt < 8; nt++) {
                int col = n0 - 128 + nt*8 + c2;
                int head = col >> 5;
                __half2 hv = __floats2half2_rn(vals[nt*2], vals[nt*2+1]);
                *(__half2*)&vph[((size_t)(bb*NHn + head)*Nn + n)*32 + (col & 31)] = hv;
            }
        }
    }
}

// ---------- pointwise after fused QKVSR GEMM ----------
__global__ void pointwise1(const float* __restrict__ tmp1, const float* __restrict__ temp,
                           const float* __restrict__ qe, const float* __restrict__ plnw,
                           const float* __restrict__ plnb,
                           float* __restrict__ qs, float* __restrict__ qn,
                           float* __restrict__ kl, float* __restrict__ vl,
                           __half* __restrict__ xph)
{
    int t = blockIdx.x * 8 + (threadIdx.x >> 5);
    int lane = threadIdx.x & 31;
    int bb = t / Nn, n = t - bb * Nn;
    int h = lane >> 3;
    int g = bb * NHn + h;
    const float4* row = (const float4*)(tmp1 + (size_t)t * 512);
    size_t ho = ((size_t)g * Nn + n) * 8 + (lane & 7);

    float4 q4 = row[lane];
    float ss = q4.x*q4.x + q4.y*q4.y + q4.z*q4.z + q4.w*q4.w;
    ss += __shfl_xor_sync(0xffffffffu, ss, 1);
    ss += __shfl_xor_sync(0xffffffffu, ss, 2);
    ss += __shfl_xor_sync(0xffffffffu, ss, 4);
    float inv = 1.0f / fmaxf(sqrtf(ss), 1e-12f);
    float4 qn4 = make_float4(q4.x*inv, q4.y*inv, q4.z*inv, q4.w*inv);
    float tv = temp[h];
    float sp = log1pf(__expf(tv));
    float4 qe4 = ((const float4*)qe)[h*8 + (lane & 7)];
    ((float4*)qn)[ho] = qn4;
    ((float4*)qs)[ho] = make_float4((qn4.x+qe4.x)*sp, (qn4.y+qe4.y)*sp,
                                    (qn4.z+qe4.z)*sp, (qn4.w+qe4.w)*sp);

    float4 k4 = row[32 + lane];
    float ks = k4.x*k4.x + k4.y*k4.y + k4.z*k4.z + k4.w*k4.w;
    ks += __shfl_xor_sync(0xffffffffu, ks, 1);
    ks += __shfl_xor_sync(0xffffffffu, ks, 2);
    ks += __shfl_xor_sync(0xffffffffu, ks, 4);
    float ki = 1.0f / fmaxf(sqrtf(ks), 1e-12f);
    ((float4*)kl)[ho] = make_float4(k4.x*ki, k4.y*ki, k4.z*ki, k4.w*ki);
    ((float4*)vl)[ho] = row[64 + lane];

    float4 s4 = row[96 + lane];
    float g0 = gelu_exact(s4.x), g1 = gelu_exact(s4.y);
    float g2 = gelu_exact(s4.z), g3 = gelu_exact(s4.w);
    float sm = g0+g1+g2+g3;
    float sq = g0*g0+g1*g1+g2*g2+g3*g3;
#pragma unroll
    for (int d = 1; d < 32; d <<= 1) {
        sm += __shfl_xor_sync(0xffffffffu, sm, d);
        sq += __shfl_xor_sync(0xffffffffu, sq, d);
    }
    float mu = sm*(1.0f/128.0f);
    float rstd = rsqrtf(sq*(1.0f/128.0f) - mu*mu + 1e-5f);
    int c = lane * 4;
    float o0 = (g0-mu)*rstd*plnw[c]   + plnb[c];
    float o1 = (g1-mu)*rstd*plnw[c+1] + plnb[c+1];
    float o2 = (g2-mu)*rstd*plnw[c+2] + plnb[c+2];
    float o3 = (g3-mu)*rstd*plnw[c+3] + plnb[c+3];
    unsigned* xh = (unsigned*)xph;
    xh[(size_t)t*64 + lane*2]     = h2pack(o0, o1);
    xh[(size_t)t*64 + lane*2 + 1] = h2pack(o2, o3);
}

// ---------- HMMA pooled attention: 2 q-blocks per CTA share K/V staging ----------
__global__ void __launch_bounds__(256) attn_pool_mma(
    const float* __restrict__ qs, const __half* __restrict__ kph,
    const __half* __restrict__ vph,
    const float* __restrict__ qn, const float* __restrict__ kl,
    const float* __restrict__ vl, const float* __restrict__ lt,
    const float* __restrict__ lb,
    __half* __restrict__ atth)
{
    __shared__ __half Khi[128][40];
    __shared__ __half Vt[32][132];

    const int g  = blockIdx.y;
    const int tid = threadIdx.x;
    const int warp = tid >> 5;
    const int lane = tid & 31;
    const int r  = lane >> 2;
    const int c2 = (lane & 3) * 2;
    const int qbase = blockIdx.x * 128 + (warp >> 2) * 64 + (warp & 3) * 16 + r;
    const int qrow_l = (qbase < Nn) ? qbase : (Nn - 1);

    unsigned qhi[2][4];
    {
        const float* q0p = qs + ((size_t)g*Nn + qrow_l)*32;
        int q8c = (qbase + 8 < Nn) ? (qbase + 8) : (Nn - 1);
        const float* q8p = qs + ((size_t)g*Nn + q8c)*32;
#pragma unroll
        for (int ks = 0; ks < 2; ks++) {
            int d0 = ks*16 + c2;
            qhi[ks][0] = h2pack(q0p[d0],   q0p[d0+1]);
            qhi[ks][1] = h2pack(q8p[d0],   q8p[d0+1]);
            qhi[ks][2] = h2pack(q0p[d0+8], q0p[d0+9]);
            qhi[ks][3] = h2pack(q8p[d0+8], q8p[d0+9]);
        }
    }

    float uf[4][4];
#pragma unroll
    for (int t = 0; t < 4; t++)
#pragma unroll
        for (int i = 0; i < 4; i++) uf[t][i] = 0.f;
    float z0 = 0.f, z1 = 0.f;

    const int NCH = 25;
    for (int ch = 0; ch < NCH; ch++) {
        const int m0 = ch * 128;
        {
            int row = tid & 127;
            int hp  = tid >> 7;
            int kvr = m0 + row;
            bool ok = kvr < Nn;
            size_t rb = ((size_t)g*Nn + (ok ? kvr : 0))*32;
            const uint4* krh = (const uint4*)(kph + rb);
            uint4 z4 = make_uint4(0,0,0,0);
#pragma unroll
            for (int j = 0; j < 2; j++)
                *(uint4*)&Khi[row][(hp*2 + j)*8] = ok ? krh[hp*2 + j] : z4;
            const unsigned* vr = (const unsigned*)(vph + rb);
#pragma unroll
            for (int j = 0; j < 8; j++) {
                int jj = hp*8 + j;
                unsigned p = ok ? vr[jj] : 0u;
                __half2 hh = *(__half2*)&p;
                Vt[2*jj][row]   = hh.x;
                Vt[2*jj+1][row] = hh.y;
            }
        }
        __syncthreads();

        const int kkmax = (m0 + 128 <= Nn) ? 8 : 4;
        for (int kk = 0; kk < kkmax; kk++) {
            unsigned ea[4];
#pragma unroll
            for (int tt = 0; tt < 2; tt++) {
                int t = 2*kk + tt;
                int kv = t*8 + (lane >> 2);
                float sf[4] = {0.f, 0.f, 0.f, 0.f};
#pragma unroll
                for (int ks = 0; ks < 2; ks++) {
                    int d0 = ks*16 + c2;
                    unsigned bh0 = *(const unsigned*)&Khi[kv][d0];
                    unsigned bh1 = *(const unsigned*)&Khi[kv][d0+8];
                    mma16816(sf, qhi[ks], bh0, bh1);
                }
                float e0 = __expf(sf[0]);
                float e1 = __expf(sf[1]);
                float e2 = __expf(sf[2]);
                float e3 = __expf(sf[3]);
                z0 += e0 + e1;
                z1 += e2 + e3;
                ea[2*tt]   = h2pack(e0, e1);
                ea[2*tt+1] = h2pack(e2, e3);
            }
            int kv0 = kk*16 + c2;
#pragma unroll
            for (int nt = 0; nt < 4; nt++) {
                int d = nt*8 + (lane >> 2);
                unsigned b0 = *(const unsigned*)&Vt[d][kv0];
                unsigned b1 = *(const unsigned*)&Vt[d][kv0+8];
                mma16816(uf[nt], ea, b0, b1);
            }
        }
        __syncthreads();
    }

    // ---- fused finalize ----
    z0 += __shfl_xor_sync(0xffffffffu, z0, 1);
    z0 += __shfl_xor_sync(0xffffffffu, z0, 2);
    z1 += __shfl_xor_sync(0xffffffffu, z1, 1);
    z1 += __shfl_xor_sync(0xffffffffu, z1, 2);

    const int b = g >> 2, h = g & 3;
#pragma unroll
    for (int half = 0; half < 2; half++) {
        int n = qbase + half*8;
        bool nok = n < Nn;
        int nc = nok ? n : (Nn - 1);
        float Zpool = half ? z1 : z0;
        int hh = nc / Hs, ww = nc - hh*Hs;
        const float* qp  = qs + ((size_t)g*Nn + nc)*32;
        const float* qnp = qn + ((size_t)g*Nn + nc)*32;
        float qsv[8], qnv[8];
#pragma unroll
        for (int nt = 0; nt < 4; nt++)
#pragma unroll
            for (int j = 0; j < 2; j++) {
                int c = nt*8 + c2 + j;
                qsv[nt*2+j] = qp[c];
                qnv[nt*2+j] = qnp[c];
            }
        float resv[8], res2v[8];
#pragma unroll
        for (int i = 0; i < 8; i++) { resv[i] = 0.f; res2v[i] = 0.f; }
        float zl = 0.f;
#pragma unroll
        for (int k = 0; k < 9; k++) {
            int h2 = hh + k/3 - 1, w2 = ww + (k%3) - 1;
            bool ok = (h2 >= 0 && h2 < Hs && w2 >= 0 && w2 < Hs);
            size_t bi = ((size_t)g*Nn + (ok ? (h2*Hs + w2) : 0))*32;
            float klv[8], vlv[8];
            float lg = 0.f, wl = 0.f;
#pragma unroll
            for (int nt = 0; nt < 4; nt++)
#pragma unroll
                for (int j = 0; j < 2; j++) {
                    int c = nt*8 + c2 + j;
                    int idx = nt*2 + j;
                    klv[idx] = ok ? kl[bi + c] : 0.f;
                    vlv[idx] = ok ? vl[bi + c] : 0.f;
                    lg += qsv[idx] * klv[idx];
                    wl += qnv[idx] * lt[(h*32 + c)*9 + k];
                }
            lg += __shfl_xor_sync(0xffffffffu, lg, 1);
            lg += __shfl_xor_sync(0xffffffffu, lg, 2);
            wl += __shfl_xor_sync(0xffffffffu, wl, 1);
            wl += __shfl_xor_sync(0xffffffffu, wl, 2);
            float e = __expf(lg);
            zl += e;
            float w2l = wl + lb[h*9 + k];
#pragma unroll
            for (int i = 0; i < 8; i++) {
                resv[i]  += e   * vlv[i];
                res2v[i] += w2l * vlv[i];
            }
        }
        float Zf = Zpool + zl;
        float rZ = 1.0f / Zf;
        if (nok) {
#pragma unroll
            for (int nt = 0; nt < 4; nt++)
#pragma unroll
                for (int j = 0; j < 2; j++) {
                    int c = nt*8 + c2 + j;
                    int idx = nt*2 + j;
                    float o = (uf[nt][half*2 + j] + resv[idx]) * rZ + res2v[idx];
                    size_t oi = ((size_t)(b*Nn + n))*128 + h*32 + c;
                    atth[oi] = __float2half_rn(o);
                }
        }
    }
}

// ---------- depthwise 3x3 + gelu * v (fp16 f1) -> fp16 ----------
__global__ void dwconv_kernel(const __half* __restrict__ f1, const float* __restrict__ dww,
                              const float* __restrict__ dwb, __half* __restrict__ gbh)
{
    int t = blockIdx.x;
    int c = threadIdx.x;
    if (c >= LDF) return;
    size_t oi = (size_t)t*LDF + c;
    if (c >= HFn) { gbh[oi] = __float2half(0.f); return; }
    int b = t / Nn, n = t - b*Nn;
    int hh = n / Hs, ww = n - hh*Hs;
    float acc = dwb[c];
#pragma unroll
    for (int k = 0; k < 9; k++) {
        int h2 = hh + k/3 - 1, w2 = ww + (k%3) - 1;
        if (h2 < 0 || h2 >= Hs || w2 < 0 || w2 >= Hs) continue;
        acc += __half2float(f1[((size_t)(b*Nn + h2*Hs + w2))*682 + c]) * dww[c*9 + k];
    }
    float v = __half2float(f1[(size_t)t*682 + 341 + c]);
    gbh[oi] = __float2half_rn(gelu_exact(acc) * v);
}

extern "C" void kernel_launch(void* const* d_in, const int* in_sizes, int n_in,
                              void* d_out, int out_size)
{
    const float* x      = (const float*)d_in[0];
    const float* n1w    = (const float*)d_in[1];
    const float* n1b    = (const float*)d_in[2];
    const float* q_w    = (const float*)d_in[3];
    const float* q_b    = (const float*)d_in[4];
    const float* kv_w   = (const float*)d_in[5];
    const float* kv_b   = (const float*)d_in[6];
    const float* temp   = (const float*)d_in[7];
    const float* qe     = (const float*)d_in[8];
    const float* lt     = (const float*)d_in[9];
    const float* lb     = (const float*)d_in[10];
    const float* sr_w   = (const float*)d_in[11];
    const float* sr_b   = (const float*)d_in[12];
    const float* plnw   = (const float*)d_in[13];
    const float* plnb   = (const float*)d_in[14];
    const float* proj_w = (const float*)d_in[15];
    const float* proj_b = (const float*)d_in[16];
    const float* n2w    = (const float*)d_in[17];
    const float* n2b    = (const float*)d_in[18];
    const float* fc1_w  = (const float*)d_in[19];
    const float* fc1_b  = (const float*)d_in[20];
    const float* dw_w   = (const float*)d_in[21];
    const float* dw_b   = (const float*)d_in[22];
    const float* fc2_w  = (const float*)d_in[23];
    const float* fc2_b  = (const float*)d_in[24];
    float* out = (float*)d_out;

    float *t1, *qsb, *qnb, *klb, *vlb, *x2b, *b512;
    __half *f1hb, *yh, *xph, *atth, *y2h, *kph, *vphh, *gbh, *wh;
    cudaGetSymbolAddress((void**)&t1,   g_tmp1);
    cudaGetSymbolAddress((void**)&qsb,  g_qs);
    cudaGetSymbolAddress((void**)&qnb,  g_qn);
    cudaGetSymbolAddress((void**)&klb,  g_kl);
    cudaGetSymbolAddress((void**)&vlb,  g_vl);
    cudaGetSymbolAddress((void**)&x2b,  g_x2);
    cudaGetSymbolAddress((void**)&b512, g_b512);
    cudaGetSymbolAddress((void**)&f1hb, g_f1h);
    cudaGetSymbolAddress((void**)&yh,   g_yh);
    cudaGetSymbolAddress((void**)&xph,  g_xph);
    cudaGetSymbolAddress((void**)&atth, g_atth);
    cudaGetSymbolAddress((void**)&y2h,  g_y2h);
    cudaGetSymbolAddress((void**)&kph,  g_kph);
    cudaGetSymbolAddress((void**)&vphh, g_vph);
    cudaGetSymbolAddress((void**)&gbh,  g_gbh);
    cudaGetSymbolAddress((void**)&wh,   g_wh);

    cvt_all<<<840, 256>>>(q_w, kv_w, sr_w, proj_w, fc1_w, fc2_w, q_b, kv_b, sr_b, wh, b512);

    ln_kernel<<<TOK/8, 256>>>(x, n1w, n1b, yh);
    hgemm2<<<dim3(8,98), 128>>>(yh, wh+OQ, 128, b512, t1, 512, 512, 0, nullptr);
    pointwise1<<<TOK/8, 256>>>(t1, temp, qe, plnw, plnb, qsb, qnb, klb, vlb, xph);
    hgemm_kv<<<dim3(4,98), 128>>>(xph, wh+OKV, kv_b, kph, vphh);
    attn_pool_mma<<<dim3(25,8), 256>>>(qsb, kph, vphh, qnb, klb, vlb, lt, lb, atth);
    hgemm2<<<dim3(2,98), 128>>>(atth, wh+OPJ, 128, proj_b, x2b, 128, 128, 1, x);
    ln_kernel<<<TOK/8, 256>>>(x2b, n2w, n2b, y2h);
    hgemm2<<<dim3(11,98), 128>>>(y2h, wh+OF1, 128, fc1_b, (float*)f1hb, 682, 682, 3, nullptr);
    dwconv_kernel<<<TOK, LDF>>>(f1hb, dw_w, dw_b, gbh);
    hgemm2<<<dim3(2,98), 128>>>(gbh, wh+OF2, LDF, fc2_b, out, 128, 128, 2, x2b);
}

// round 13
// speedup vs baseline: 1.5728x; 1.0496x over previous
#include <cuda_runtime.h>
#include <cuda_fp16.h>
#include <math.h>

#define Bn   2
#define Cn   128
#define Hs   56
#define Nn   3136
#define NHn  4
#define HFn  341
#define TOK  (Bn*Nn)
#define LDF  352

// fp32 scratch
__device__ __align__(256) float g_x2 [TOK*Cn];
__device__ __align__(256) float g_b512[512];
// half scratch
__device__ __align__(256) __half g_t1h[TOK*512];
__device__ __align__(256) __half g_qsh[8*Nn*32];
__device__ __align__(256) __half g_qnh[8*Nn*32];
__device__ __align__(256) __half g_klh[8*Nn*32];
__device__ __align__(256) __half g_vlh[8*Nn*32];
__device__ __align__(256) __half g_f1h[TOK*682];
__device__ __align__(256) __half g_yh [TOK*Cn];
__device__ __align__(256) __half g_xph[TOK*Cn];
__device__ __align__(256) __half g_atth[TOK*Cn];
__device__ __align__(256) __half g_y2h[TOK*Cn];
__device__ __align__(256) __half g_kph[TOK*Cn];
__device__ __align__(256) __half g_vph[TOK*Cn];
__device__ __align__(256) __half g_gbh[TOK*LDF];
// converted weights pool (hi only)
#define OQ   0
#define OKV  16384
#define OSR  49152
#define OPJ  65536
#define OF1  81920
#define OF2  169216
#define WTOT 214272
__device__ __align__(256) __half g_wh[WTOT];

__device__ __forceinline__ float gelu_exact(float x) {
    return 0.5f * x * (1.0f + erff(x * 0.70710678118654752f));
}
__device__ __forceinline__ unsigned h2pack(float a, float b) {
    __half2 h = __floats2half2_rn(a, b);
    return *(unsigned*)&h;
}
__device__ __forceinline__ void mma16816(float* c, const unsigned* a, unsigned b0, unsigned b1) {
    asm volatile("mma.sync.aligned.m16n8k16.row.col.f32.f16.f16.f32 "
        "{%0,%1,%2,%3}, {%4,%5,%6,%7}, {%8,%9}, {%0,%1,%2,%3};"
        : "+f"(c[0]), "+f"(c[1]), "+f"(c[2]), "+f"(c[3])
        : "r"(a[0]), "r"(a[1]), "r"(a[2]), "r"(a[3]), "r"(b0), "r"(b1));
}

// ---------- single-launch weight conversion (hi only) + fused bias ----------
__global__ void cvt_all(const float* __restrict__ q_w, const float* __restrict__ kv_w,
                        const float* __restrict__ sr_w, const float* __restrict__ proj_w,
                        const float* __restrict__ fc1_w, const float* __restrict__ fc2_w,
                        const float* __restrict__ q_b, const float* __restrict__ kv_b,
                        const float* __restrict__ sr_b,
                        __half* __restrict__ wh, float* __restrict__ b512)
{
    int i = blockIdx.x * 256 + threadIdx.x;
    if (i < WTOT) {
        float v;
        if      (i < OKV) v = q_w[i];
        else if (i < OSR) v = kv_w[i - OKV];
        else if (i < OPJ) v = sr_w[i - OSR];
        else if (i < OF1) v = proj_w[i - OPJ];
        else if (i < OF2) v = fc1_w[i - OF1];
        else {
            int j = i - OF2, r = j / LDF, c = j - r * LDF;
            v = (c < HFn) ? fc2_w[r * HFn + c] : 0.f;
        }
        wh[i] = __float2half_rn(v);
    } else if (i < WTOT + 512) {
        int j = i - WTOT;
        b512[j] = (j < 128) ? q_b[j] : (j < 384) ? kv_b[j - 128] : sr_b[j - 384];
    }
}

// ---------- LayerNorm (channel-major in) -> fp16 token-major ----------
__global__ void ln_kernel(const float* __restrict__ in, const float* __restrict__ w,
                          const float* __restrict__ bvec, __half* __restrict__ oh)
{
    int warp = blockIdx.x * 8 + (threadIdx.x >> 5);
    int lane = threadIdx.x & 31;
    int bb = warp / Nn, n = warp - bb * Nn;
    const float* p = in + (size_t)bb * (Cn*Nn) + n;
    float v[4], s = 0.f, s2 = 0.f;
#pragma unroll
    for (int pp = 0; pp < 2; pp++) {
        int c0 = 2*lane + 64*pp;
        v[2*pp]   = p[(size_t)c0 * Nn];
        v[2*pp+1] = p[(size_t)(c0+1) * Nn];
        s += v[2*pp] + v[2*pp+1];
        s2 += v[2*pp]*v[2*pp] + v[2*pp+1]*v[2*pp+1];
    }
#pragma unroll
    for (int d = 1; d < 32; d <<= 1) {
        s  += __shfl_xor_sync(0xffffffffu, s,  d);
        s2 += __shfl_xor_sync(0xffffffffu, s2, d);
    }
    float mu = s * (1.0f/128.0f);
    float rstd = rsqrtf(s2*(1.0f/128.0f) - mu*mu + 1e-5f);
    unsigned* ohp = (unsigned*)oh;
#pragma unroll
    for (int pp = 0; pp < 2; pp++) {
        int c0 = 2*lane + 64*pp;
        float a = (v[2*pp]  -mu)*rstd*w[c0]   + bvec[c0];
        float b = (v[2*pp+1]-mu)*rstd*w[c0+1] + bvec[c0+1];
        ohp[warp*64 + lane + 32*pp] = h2pack(a, b);
    }
}

// ---------- HMMA GEMM: single fp16 A x W ----------
// mode 0: fp32 out; 1: fp32 +res; 2: transposed channel-major +res; 3: fp16 out
__global__ void __launch_bounds__(128) hgemm2(
    const __half* __restrict__ Ah, const __half* __restrict__ Wh, int ld,
    const float* __restrict__ bias, float* __restrict__ out,
    int ldo, int Nout, int mode, const float* __restrict__ res)
{
    const int m0 = blockIdx.y * 64;
    const int n0 = blockIdx.x * 64;
    const int warp = threadIdx.x >> 5;
    const int lane = threadIdx.x & 31;
    const int r  = lane >> 2;
    const int c2 = (lane & 3) * 2;

    float acc[8][4];
#pragma unroll
    for (int t = 0; t < 8; t++)
#pragma unroll
        for (int i = 0; i < 4; i++) acc[t][i] = 0.f;

    const int row1 = m0 + warp*16 + r;
    const __half* a1h = Ah + (size_t)row1 * ld;
    const __half* a2h = a1h + (size_t)8 * ld;

    const int nr = n0 + (lane >> 2);
    const __half* wrow[8];
#pragma unroll
    for (int nt = 0; nt < 8; nt++) {
        int n = nr + nt*8;
        int nc = (n < Nout) ? n : (Nout - 1);
        wrow[nt] = Wh + (size_t)nc * ld;
    }

    const int KC = ld / 32;
    for (int kc = 0; kc < KC; kc++) {
#pragma unroll
        for (int ks = 0; ks < 2; ks++) {
            int d0 = kc*32 + ks*16 + c2;
            unsigned ah[4];
            ah[0] = *(const unsigned*)&a1h[d0];
            ah[1] = *(const unsigned*)&a2h[d0];
            ah[2] = *(const unsigned*)&a1h[d0+8];
            ah[3] = *(const unsigned*)&a2h[d0+8];
#pragma unroll
            for (int nt = 0; nt < 8; nt++) {
                unsigned bh0 = *(const unsigned*)&wrow[nt][d0];
                unsigned bh1 = *(const unsigned*)&wrow[nt][d0+8];
                mma16816(acc[nt], ah, bh0, bh1);
            }
        }
    }

    int m1 = row1, m2 = row1 + 8;
#pragma unroll
    for (int nt = 0; nt < 8; nt++) {
        int n = n0 + nt*8 + c2;
#pragma unroll
        for (int j = 0; j < 2; j++) {
            int nn = n + j;
            if (nn >= Nout) continue;
            float v1 = acc[nt][j]   + bias[nn];
            float v2 = acc[nt][2+j] + bias[nn];
            if (mode == 0) {
                out[(size_t)m1*ldo + nn] = v1;
                out[(size_t)m2*ldo + nn] = v2;
            } else if (mode == 1) {
                size_t i1 = (size_t)m1*ldo + nn, i2 = (size_t)m2*ldo + nn;
                out[i1] = v1 + res[i1];
                out[i2] = v2 + res[i2];
            } else if (mode == 2) {
                int b1 = m1 / Nn, t1i = m1 - b1*Nn;
                int b2 = m2 / Nn, t2i = m2 - b2*Nn;
                size_t i1 = ((size_t)b1*Cn + nn)*Nn + t1i;
                size_t i2 = ((size_t)b2*Cn + nn)*Nn + t2i;
                out[i1] = v1 + res[i1];
                out[i2] = v2 + res[i2];
            } else {
                __half* oh = (__half*)out;
                oh[(size_t)m1*ldo + nn] = __float2half_rn(v1);
                oh[(size_t)m2*ldo + nn] = __float2half_rn(v2);
            }
        }
    }
}

// ---------- HMMA kv GEMM with fused l2norm/split epilogue -> kph/vph fp16 ----------
__global__ void __launch_bounds__(128) hgemm_kv(
    const __half* __restrict__ Ah, const __half* __restrict__ Wh,
    const float* __restrict__ bias,
    __half* __restrict__ kph, __half* __restrict__ vph)
{
    const int m0 = blockIdx.y * 64;
    const int n0 = blockIdx.x * 64;
    const int warp = threadIdx.x >> 5;
    const int lane = threadIdx.x & 31;
    const int r  = lane >> 2;
    const int c2 = (lane & 3) * 2;
    const int ld = 128;

    float acc[8][4];
#pragma unroll
    for (int t = 0; t < 8; t++)
#pragma unroll
        for (int i = 0; i < 4; i++) acc[t][i] = 0.f;

    const int row1 = m0 + warp*16 + r;
    const __half* a1h = Ah + (size_t)row1 * ld;
    const __half* a2h = a1h + (size_t)8 * ld;

    const int nr = n0 + (lane >> 2);
    const __half* wrow[8];
#pragma unroll
    for (int nt = 0; nt < 8; nt++)
        wrow[nt] = Wh + (size_t)(nr + nt*8) * ld;

#pragma unroll
    for (int kc = 0; kc < 4; kc++) {
#pragma unroll
        for (int ks = 0; ks < 2; ks++) {
            int d0 = kc*32 + ks*16 + c2;
            unsigned ah[4];
            ah[0] = *(const unsigned*)&a1h[d0];
            ah[1] = *(const unsigned*)&a2h[d0];
            ah[2] = *(const unsigned*)&a1h[d0+8];
            ah[3] = *(const unsigned*)&a2h[d0+8];
#pragma unroll
            for (int nt = 0; nt < 8; nt++) {
                unsigned bh0 = *(const unsigned*)&wrow[nt][d0];
                unsigned bh1 = *(const unsigned*)&wrow[nt][d0+8];
                mma16816(acc[nt], ah, bh0, bh1);
            }
        }
    }

#pragma unroll
    for (int half = 0; half < 2; half++) {
        int m = row1 + half*8;
        int bb = m / Nn, n = m - bb*Nn;
        float vals[16];
#pragma unroll
        for (int nt = 0; nt < 8; nt++)
#pragma unroll
            for (int j = 0; j < 2; j++)
                vals[nt*2+j] = acc[nt][half*2+j] + bias[n0 + nt*8 + c2 + j];
        if (n0 < 128) {
            float se = 0.f, so = 0.f;
#pragma unroll
            for (int i = 0; i < 8; i++) { se += vals[i]*vals[i]; so += vals[8+i]*vals[8+i]; }
            se += __shfl_xor_sync(0xffffffffu, se, 1);
            se += __shfl_xor_sync(0xffffffffu, se, 2);
            so += __shfl_xor_sync(0xffffffffu, so, 1);
            so += __shfl_xor_sync(0xffffffffu, so, 2);
            float ke = 1.0f / fmaxf(sqrtf(se), 1e-12f);
            float ko = 1.0f / fmaxf(sqrtf(so), 1e-12f);
#pragma unroll
            for (int nt = 0; nt < 8; nt++) {
                int col = n0 + nt*8 + c2;
                int head = col >> 5;
                float sc = (nt < 4) ? ke : ko;
                __half2 hv = __floats2half2_rn(vals[nt*2]*sc, vals[nt*2+1]*sc);
                *(__half2*)&kph[((size_t)(bb*NHn + head)*Nn + n)*32 + (col & 31)] = hv;
            }
        } else {
#pragma unroll
            for (int nt = 0; nt < 8; nt++) {
                int col = n0 - 128 + nt*8 + c2;
                int head = col >> 5;
                __half2 hv = __floats2half2_rn(vals[nt*2], vals[nt*2+1]);
                *(__half2*)&vph[((size_t)(bb*NHn + head)*Nn + n)*32 + (col & 31)] = hv;
            }
        }
    }
}

// ---------- pointwise after fused QKVSR GEMM (fp16 in, fp16 out) ----------
__global__ void pointwise1(const __half* __restrict__ t1h, const float* __restrict__ temp,
                           const float* __restrict__ qe, const float* __restrict__ plnw,
                           const float* __restrict__ plnb,
                           __half* __restrict__ qsh, __half* __restrict__ qnh,
                           __half* __restrict__ klh, __half* __restrict__ vlh,
                           __half* __restrict__ xph)
{
    int t = blockIdx.x * 8 + (threadIdx.x >> 5);
    int lane = threadIdx.x & 31;
    int bb = t / Nn, n = t - bb * Nn;
    int h = lane >> 3;
    int g = bb * NHn + h;
    const __half2* row = (const __half2*)(t1h + (size_t)t * 512);
    unsigned base = ((unsigned)g*Nn + n)*16 + (lane & 7)*2;   // unsigned(pair) units

    // ---- q ----
    __half2 qa = row[2*lane], qb = row[2*lane + 1];
    float q0 = __half2float(qa.x), q1 = __half2float(qa.y);
    float q2 = __half2float(qb.x), q3 = __half2float(qb.y);
    float ss = q0*q0 + q1*q1 + q2*q2 + q3*q3;
    ss += __shfl_xor_sync(0xffffffffu, ss, 1);
    ss += __shfl_xor_sync(0xffffffffu, ss, 2);
    ss += __shfl_xor_sync(0xffffffffu, ss, 4);
    float inv = 1.0f / fmaxf(sqrtf(ss), 1e-12f);
    float n0 = q0*inv, n1 = q1*inv, n2 = q2*inv, n3 = q3*inv;
    float tv = temp[h];
    float sp = log1pf(__expf(tv));
    float4 qe4 = ((const float4*)qe)[h*8 + (lane & 7)];
    ((unsigned*)qnh)[base]   = h2pack(n0, n1);
    ((unsigned*)qnh)[base+1] = h2pack(n2, n3);
    ((unsigned*)qsh)[base]   = h2pack((n0+qe4.x)*sp, (n1+qe4.y)*sp);
    ((unsigned*)qsh)[base+1] = h2pack((n2+qe4.z)*sp, (n3+qe4.w)*sp);

    // ---- k ----
    __half2 ka = row[64 + 2*lane], kb = row[64 + 2*lane + 1];
    float k0 = __half2float(ka.x), k1 = __half2float(ka.y);
    float k2 = __half2float(kb.x), k3 = __half2float(kb.y);
    float ks = k0*k0 + k1*k1 + k2*k2 + k3*k3;
    ks += __shfl_xor_sync(0xffffffffu, ks, 1);
    ks += __shfl_xor_sync(0xffffffffu, ks, 2);
    ks += __shfl_xor_sync(0xffffffffu, ks, 4);
    float ki = 1.0f / fmaxf(sqrtf(ks), 1e-12f);
    ((unsigned*)klh)[base]   = h2pack(k0*ki, k1*ki);
    ((unsigned*)klh)[base+1] = h2pack(k2*ki, k3*ki);

    // ---- v copy ----
    ((unsigned*)vlh)[base]   = *(const unsigned*)&row[128 + 2*lane];
    ((unsigned*)vlh)[base+1] = *(const unsigned*)&row[128 + 2*lane + 1];

    // ---- sr -> gelu -> LN ----
    __half2 sa = row[192 + 2*lane], sb = row[192 + 2*lane + 1];
    float g0 = gelu_exact(__half2float(sa.x)), g1 = gelu_exact(__half2float(sa.y));
    float g2 = gelu_exact(__half2float(sb.x)), g3 = gelu_exact(__half2float(sb.y));
    float sm = g0+g1+g2+g3;
    float sq = g0*g0+g1*g1+g2*g2+g3*g3;
#pragma unroll
    for (int d = 1; d < 32; d <<= 1) {
        sm += __shfl_xor_sync(0xffffffffu, sm, d);
        sq += __shfl_xor_sync(0xffffffffu, sq, d);
    }
    float mu = sm*(1.0f/128.0f);
    float rstd = rsqrtf(sq*(1.0f/128.0f) - mu*mu + 1e-5f);
    int c = lane * 4;
    float o0 = (g0-mu)*rstd*plnw[c]   + plnb[c];
    float o1 = (g1-mu)*rstd*plnw[c+1] + plnb[c+1];
    float o2 = (g2-mu)*rstd*plnw[c+2] + plnb[c+2];
    float o3 = (g3-mu)*rstd*plnw[c+3] + plnb[c+3];
    unsigned* xh = (unsigned*)xph;
    xh[(size_t)t*64 + lane*2]     = h2pack(o0, o1);
    xh[(size_t)t*64 + lane*2 + 1] = h2pack(o2, o3);
}

// ---------- HMMA pooled attention (all-fp16 inputs) ----------
__global__ void __launch_bounds__(256) attn_pool_mma(
    const __half* __restrict__ qsh, const __half* __restrict__ kph,
    const __half* __restrict__ vph,
    const __half* __restrict__ qnh, const __half* __restrict__ klh,
    const __half* __restrict__ vlh, const float* __restrict__ lt,
    const float* __restrict__ lb,
    __half* __restrict__ atth)
{
    __shared__ __half Khi[128][40];
    __shared__ __half Vt[32][132];

    const int g  = blockIdx.y;
    const int tid = threadIdx.x;
    const int warp = tid >> 5;
    const int lane = tid & 31;
    const int r  = lane >> 2;
    const int c2 = (lane & 3) * 2;
    const int qbase = blockIdx.x * 128 + (warp >> 2) * 64 + (warp & 3) * 16 + r;
    const int qrow_l = (qbase < Nn) ? qbase : (Nn - 1);

    unsigned qhi[2][4];
    {
        const __half* q0p = qsh + ((size_t)g*Nn + qrow_l)*32;
        int q8c = (qbase + 8 < Nn) ? (qbase + 8) : (Nn - 1);
        const __half* q8p = qsh + ((size_t)g*Nn + q8c)*32;
#pragma unroll
        for (int ks = 0; ks < 2; ks++) {
            int d0 = ks*16 + c2;
            qhi[ks][0] = *(const unsigned*)&q0p[d0];
            qhi[ks][1] = *(const unsigned*)&q8p[d0];
            qhi[ks][2] = *(const unsigned*)&q0p[d0+8];
            qhi[ks][3] = *(const unsigned*)&q8p[d0+8];
        }
    }

    float uf[4][4];
#pragma unroll
    for (int t = 0; t < 4; t++)
#pragma unroll
        for (int i = 0; i < 4; i++) uf[t][i] = 0.f;
    float z0 = 0.f, z1 = 0.f;

    const int NCH = 25;
    for (int ch = 0; ch < NCH; ch++) {
        const int m0 = ch * 128;
        {
            int row = tid & 127;
            int hp  = tid >> 7;
            int kvr = m0 + row;
            bool ok = kvr < Nn;
            size_t rb = ((size_t)g*Nn + (ok ? kvr : 0))*32;
            const uint4* krh = (const uint4*)(kph + rb);
            uint4 z4 = make_uint4(0,0,0,0);
#pragma unroll
            for (int j = 0; j < 2; j++)
                *(uint4*)&Khi[row][(hp*2 + j)*8] = ok ? krh[hp*2 + j] : z4;
            const unsigned* vr = (const unsigned*)(vph + rb);
#pragma unroll
            for (int j = 0; j < 8; j++) {
                int jj = hp*8 + j;
                unsigned p = ok ? vr[jj] : 0u;
                __half2 hh = *(__half2*)&p;
                Vt[2*jj][row]   = hh.x;
                Vt[2*jj+1][row] = hh.y;
            }
        }
        __syncthreads();

        const int kkmax = (m0 + 128 <= Nn) ? 8 : 4;
        for (int kk = 0; kk < kkmax; kk++) {
            unsigned ea[4];
#pragma unroll
            for (int tt = 0; tt < 2; tt++) {
                int t = 2*kk + tt;
                int kv = t*8 + (lane >> 2);
                float sf[4] = {0.f, 0.f, 0.f, 0.f};
#pragma unroll
                for (int ks = 0; ks < 2; ks++) {
                    int d0 = ks*16 + c2;
                    unsigned bh0 = *(const unsigned*)&Khi[kv][d0];
                    unsigned bh1 = *(const unsigned*)&Khi[kv][d0+8];
                    mma16816(sf, qhi[ks], bh0, bh1);
                }
                float e0 = __expf(sf[0]);
                float e1 = __expf(sf[1]);
                float e2 = __expf(sf[2]);
                float e3 = __expf(sf[3]);
                z0 += e0 + e1;
                z1 += e2 + e3;
                ea[2*tt]   = h2pack(e0, e1);
                ea[2*tt+1] = h2pack(e2, e3);
            }
            int kv0 = kk*16 + c2;
#pragma unroll
            for (int nt = 0; nt < 4; nt++) {
                int d = nt*8 + (lane >> 2);
                unsigned b0 = *(const unsigned*)&Vt[d][kv0];
                unsigned b1 = *(const unsigned*)&Vt[d][kv0+8];
                mma16816(uf[nt], ea, b0, b1);
            }
        }
        __syncthreads();
    }

    // ---- fused finalize ----
    z0 += __shfl_xor_sync(0xffffffffu, z0, 1);
    z0 += __shfl_xor_sync(0xffffffffu, z0, 2);
    z1 += __shfl_xor_sync(0xffffffffu, z1, 1);
    z1 += __shfl_xor_sync(0xffffffffu, z1, 2);

    const int b = g >> 2, h = g & 3;
#pragma unroll
    for (int half = 0; half < 2; half++) {
        int n = qbase + half*8;
        bool nok = n < Nn;
        int nc = nok ? n : (Nn - 1);
        float Zpool = half ? z1 : z0;
        int hh = nc / Hs, ww = nc - hh*Hs;
        const __half* qp  = qsh + ((size_t)g*Nn + nc)*32;
        const __half* qnp = qnh + ((size_t)g*Nn + nc)*32;
        float qsv[8], qnv[8];
#pragma unroll
        for (int nt = 0; nt < 4; nt++) {
            int c = nt*8 + c2;
            __half2 a = *(const __half2*)&qp[c];
            __half2 bq = *(const __half2*)&qnp[c];
            qsv[nt*2]   = __half2float(a.x);  qsv[nt*2+1] = __half2float(a.y);
            qnv[nt*2]   = __half2float(bq.x); qnv[nt*2+1] = __half2float(bq.y);
        }
        float resv[8], res2v[8];
#pragma unroll
        for (int i = 0; i < 8; i++) { resv[i] = 0.f; res2v[i] = 0.f; }
        float zl = 0.f;
#pragma unroll
        for (int k = 0; k < 9; k++) {
            int h2 = hh + k/3 - 1, w2 = ww + (k%3) - 1;
            bool ok = (h2 >= 0 && h2 < Hs && w2 >= 0 && w2 < Hs);
            size_t bi = ((size_t)g*Nn + (ok ? (h2*Hs + w2) : 0))*32;
            float klv[8], vlv[8];
            float lg = 0.f, wl = 0.f;
#pragma unroll
            for (int nt = 0; nt < 4; nt++) {
                int c = nt*8 + c2;
                __half2 kk2 = ok ? *(const __half2*)&klh[bi + c] : __half2(__float2half(0.f), __float2half(0.f));
                __half2 vv2 = ok ? *(const __half2*)&vlh[bi + c] : __half2(__float2half(0.f), __float2half(0.f));
                int idx = nt*2;
                klv[idx]   = __half2float(kk2.x); klv[idx+1] = __half2float(kk2.y);
                vlv[idx]   = __half2float(vv2.x); vlv[idx+1] = __half2float(vv2.y);
                lg += qsv[idx]*klv[idx] + qsv[idx+1]*klv[idx+1];
                wl += qnv[idx]*lt[(h*32 + c)*9 + k] + qnv[idx+1]*lt[(h*32 + c + 1)*9 + k];
            }
            lg += __shfl_xor_sync(0xffffffffu, lg, 1);
            lg += __shfl_xor_sync(0xffffffffu, lg, 2);
            wl += __shfl_xor_sync(0xffffffffu, wl, 1);
            wl += __shfl_xor_sync(0xffffffffu, wl, 2);
            float e = __expf(lg);
            zl += e;
            float w2l = wl + lb[h*9 + k];
#pragma unroll
            for (int i = 0; i < 8; i++) {
                resv[i]  += e   * vlv[i];
                res2v[i] += w2l * vlv[i];
            }
        }
        float Zf = Zpool + zl;
        float rZ = 1.0f / Zf;
        if (nok) {
#pragma unroll
            for (int nt = 0; nt < 4; nt++)
#pragma unroll
                for (int j = 0; j < 2; j++) {
                    int c = nt*8 + c2 + j;
                    int idx = nt*2 + j;
                    float o = (uf[nt][half*2 + j] + resv[idx]) * rZ + res2v[idx];
                    size_t oi = ((size_t)(b*Nn + n))*128 + h*32 + c;
                    atth[oi] = __float2half_rn(o);
                }
        }
    }
}

// ---------- depthwise 3x3 + gelu * v (fp16 f1) -> fp16 ----------
__global__ void dwconv_kernel(const __half* __restrict__ f1, const float* __restrict__ dww,
                              const float* __restrict__ dwb, __half* __restrict__ gbh)
{
    int t = blockIdx.x;
    int c = threadIdx.x;
    if (c >= LDF) return;
    size_t oi = (size_t)t*LDF + c;
    if (c >= HFn) { gbh[oi] = __float2half(0.f); return; }
    int b = t / Nn, n = t - b*Nn;
    int hh = n / Hs, ww = n - hh*Hs;
    float acc = dwb[c];
#pragma unroll
    for (int k = 0; k < 9; k++) {
        int h2 = hh + k/3 - 1, w2 = ww + (k%3) - 1;
        if (h2 < 0 || h2 >= Hs || w2 < 0 || w2 >= Hs) continue;
        acc += __half2float(f1[((size_t)(b*Nn + h2*Hs + w2))*682 + c]) * dww[c*9 + k];
    }
    float v = __half2float(f1[(size_t)t*682 + 341 + c]);
    gbh[oi] = __float2half_rn(gelu_exact(acc) * v);
}

extern "C" void kernel_launch(void* const* d_in, const int* in_sizes, int n_in,
                              void* d_out, int out_size)
{
    const float* x      = (const float*)d_in[0];
    const float* n1w    = (const float*)d_in[1];
    const float* n1b    = (const float*)d_in[2];
    const float* q_w    = (const float*)d_in[3];
    const float* q_b    = (const float*)d_in[4];
    const float* kv_w   = (const float*)d_in[5];
    const float* kv_b   = (const float*)d_in[6];
    const float* temp   = (const float*)d_in[7];
    const float* qe     = (const float*)d_in[8];
    const float* lt     = (const float*)d_in[9];
    const float* lb     = (const float*)d_in[10];
    const float* sr_w   = (const float*)d_in[11];
    const float* sr_b   = (const float*)d_in[12];
    const float* plnw   = (const float*)d_in[13];
    const float* plnb   = (const float*)d_in[14];
    const float* proj_w = (const float*)d_in[15];
    const float* proj_b = (const float*)d_in[16];
    const float* n2w    = (const float*)d_in[17];
    const float* n2b    = (const float*)d_in[18];
    const float* fc1_w  = (const float*)d_in[19];
    const float* fc1_b  = (const float*)d_in[20];
    const float* dw_w   = (const float*)d_in[21];
    const float* dw_b   = (const float*)d_in[22];
    const float* fc2_w  = (const float*)d_in[23];
    const float* fc2_b  = (const float*)d_in[24];
    float* out = (float*)d_out;

    float *x2b, *b512;
    __half *t1h, *qshb, *qnhb, *klhb, *vlhb, *f1hb, *yh, *xph, *atth, *y2h, *kph, *vphh, *gbh, *wh;
    cudaGetSymbolAddress((void**)&x2b,  g_x2);
    cudaGetSymbolAddress((void**)&b512, g_b512);
    cudaGetSymbolAddress((void**)&t1h,  g_t1h);
    cudaGetSymbolAddress((void**)&qshb, g_qsh);
    cudaGetSymbolAddress((void**)&qnhb, g_qnh);
    cudaGetSymbolAddress((void**)&klhb, g_klh);
    cudaGetSymbolAddress((void**)&vlhb, g_vlh);
    cudaGetSymbolAddress((void**)&f1hb, g_f1h);
    cudaGetSymbolAddress((void**)&yh,   g_yh);
    cudaGetSymbolAddress((void**)&xph,  g_xph);
    cudaGetSymbolAddress((void**)&atth, g_atth);
    cudaGetSymbolAddress((void**)&y2h,  g_y2h);
    cudaGetSymbolAddress((void**)&kph,  g_kph);
    cudaGetSymbolAddress((void**)&vphh, g_vph);
    cudaGetSymbolAddress((void**)&gbh,  g_gbh);
    cudaGetSymbolAddress((void**)&wh,   g_wh);

    cvt_all<<<840, 256>>>(q_w, kv_w, sr_w, proj_w, fc1_w, fc2_w, q_b, kv_b, sr_b, wh, b512);

    ln_kernel<<<TOK/8, 256>>>(x, n1w, n1b, yh);
    hgemm2<<<dim3(8,98), 128>>>(yh, wh+OQ, 128, b512, (float*)t1h, 512, 512, 3, nullptr);
    pointwise1<<<TOK/8, 256>>>(t1h, temp, qe, plnw, plnb, qshb, qnhb, klhb, vlhb, xph);
    hgemm_kv<<<dim3(4,98), 128>>>(xph, wh+OKV, kv_b, kph, vphh);
    attn_pool_mma<<<dim3(25,8), 256>>>(qshb, kph, vphh, qnhb, klhb, vlhb, lt, lb, atth);
    hgemm2<<<dim3(2,98), 128>>>(atth, wh+OPJ, 128, proj_b, x2b, 128, 128, 1, x);
    ln_kernel<<<TOK/8, 256>>>(x2b, n2w, n2b, y2h);
    hgemm2<<<dim3(11,98), 128>>>(y2h, wh+OF1, 128, fc1_b, (float*)f1hb, 682, 682, 3, nullptr);
    dwconv_kernel<<<TOK, LDF>>>(f1hb, dw_w, dw_b, gbh);
    hgemm2<<<dim3(2,98), 128>>>(gbh, wh+OF2, LDF, fc2_b, out, 128, 128, 2, x2b);
}